// round 1
// baseline (speedup 1.0000x reference)
#include <cuda_runtime.h>
#include <math.h>

#define BATCH 4
#define CH    256
#define FH    100
#define FW    152
#define HW    (FH*FW)          // 15200
#define NROIS 512
#define OH    7
#define OW    7
#define NBIN  49
#define FDIM  (CH*NBIN)        // 12544
#define DFC   1024
#define NOFF  98               // 2*49
#define SCALE 0.0625f
#define GAMMA 0.1f

// ---------------- scratch (device globals; no allocation allowed) -----------
__device__ float g_feat[(size_t)BATCH*HW*CH];   // NHWC features, 62.3 MB
__device__ float g_h1[NROIS*DFC];
__device__ float g_h2[NROIS*DFC];
__device__ float g_off[NROIS*NOFF];
__device__ float g_nrois[NROIS*5];

// ---------------- NCHW -> NHWC transpose ------------------------------------
__global__ void nchw2nhwc(const float* __restrict__ in) {
    __shared__ float tile[32][33];
    int b   = blockIdx.z;
    int hw0 = blockIdx.x * 32;
    int c0  = blockIdx.y * 32;
    #pragma unroll
    for (int r = 0; r < 4; r++) {
        int c  = c0 + threadIdx.y + r*8;
        int hw = hw0 + threadIdx.x;
        tile[threadIdx.y + r*8][threadIdx.x] = in[((size_t)b*CH + c)*HW + hw];
    }
    __syncthreads();
    #pragma unroll
    for (int r = 0; r < 4; r++) {
        int hw = hw0 + threadIdx.y + r*8;
        int c  = c0 + threadIdx.x;
        g_feat[((size_t)b*HW + hw)*CH + c] = tile[threadIdx.x][threadIdx.y + r*8];
    }
}

// ---------------- deformable RoI pool ---------------------------------------
// 1 block per ROI, 256 threads = channels. Output staged in smem for coalesced
// writes in flat [roi][c*49+bin] layout (== x_cls.reshape(n,-1)).
template<bool HAS_OFF>
__global__ void roi_pool(const float* __restrict__ rois,
                         const float* __restrict__ off,
                         float* __restrict__ out) {
    extern __shared__ float sout[];           // FDIM floats
    int roi = blockIdx.x;
    int c   = threadIdx.x;
    const float* r = rois + roi*5;
    int   b  = (int)r[0];
    float x1 = r[1]*SCALE - 0.5f;
    float y1 = r[2]*SCALE - 0.5f;
    float x2 = r[3]*SCALE - 0.5f;
    float y2 = r[4]*SCALE - 0.5f;
    float rw = x2 - x1, rh = y2 - y1;
    float bw = rw * (1.0f/OW), bh = rh * (1.0f/OH);
    const float* fb = g_feat + (size_t)b*HW*CH;

    for (int bin = 0; bin < NBIN; bin++) {
        int ph = bin / OW, pw = bin % OW;
        float sw = x1, sh = y1;
        if (HAS_OFF) {
            sw += GAMMA * rw * off[roi*NOFF + bin];
            sh += GAMMA * rh * off[roi*NOFF + NBIN + bin];
        }
        float acc = 0.0f;
        #pragma unroll
        for (int iy = 0; iy < 2; iy++) {
            float y = sh + ((float)ph + ((float)iy + 0.5f)*0.5f) * bh;
            #pragma unroll
            for (int ix = 0; ix < 2; ix++) {
                float x = sw + ((float)pw + ((float)ix + 0.5f)*0.5f) * bw;
                if (y > -1.0f && y < (float)FH && x > -1.0f && x < (float)FW) {
                    float yc = fminf(fmaxf(y, 0.0f), (float)(FH-1));
                    float xc = fminf(fmaxf(x, 0.0f), (float)(FW-1));
                    int y0 = min((int)floorf(yc), FH-2);
                    int x0 = min((int)floorf(xc), FW-2);
                    float ly = yc - (float)y0, lx = xc - (float)x0;
                    float hy = 1.0f - ly,     hx = 1.0f - lx;
                    const float* p = fb + ((size_t)y0*FW + x0)*CH + c;
                    acc += hy*hx*p[0] + hy*lx*p[CH]
                         + ly*hx*p[FW*CH] + ly*lx*p[FW*CH + CH];
                }
            }
        }
        sout[c*NBIN + bin] = acc * 0.25f;
    }
    __syncthreads();
    float* o = out + (size_t)roi * FDIM;
    for (int i = c; i < FDIM; i += CH) o[i] = sout[i];
}

// ---------------- rescale head (only 4 of 98 outputs used) + new_rois -------
__global__ void rescale_newrois(const float* __restrict__ flat,
                                const float* __restrict__ rois,
                                const float* __restrict__ w,
                                const float* __restrict__ bias) {
    int roi = blockIdx.x;
    int tid = threadIdx.x;       // 256
    const float* f = flat + (size_t)roi * FDIM;
    float s0 = 0.f, s1 = 0.f, s2 = 0.f, s3 = 0.f;
    for (int k = tid; k < FDIM; k += 256) {
        float v = f[k];
        s0 += v * w[k];
        s1 += v * w[FDIM + k];
        s2 += v * w[2*FDIM + k];
        s3 += v * w[3*FDIM + k];
    }
    #pragma unroll
    for (int o = 16; o > 0; o >>= 1) {
        s0 += __shfl_down_sync(0xffffffffu, s0, o);
        s1 += __shfl_down_sync(0xffffffffu, s1, o);
        s2 += __shfl_down_sync(0xffffffffu, s2, o);
        s3 += __shfl_down_sync(0xffffffffu, s3, o);
    }
    __shared__ float red[4][8];
    int lane = tid & 31, warp = tid >> 5;
    if (lane == 0) { red[0][warp]=s0; red[1][warp]=s1; red[2][warp]=s2; red[3][warp]=s3; }
    __syncthreads();
    if (tid == 0) {
        float d[4];
        #pragma unroll
        for (int j = 0; j < 4; j++) {
            float t = 0.f;
            #pragma unroll
            for (int ww = 0; ww < 8; ww++) t += red[j][ww];
            d[j] = 1.0f + 0.5f / (1.0f + expf(-(t + bias[j])));
        }
        const float* r = rois + roi*5;
        float cx = (r[1] + r[3]) * 0.5f + d[0];
        float cy = (r[2] + r[4]) * 0.5f + d[1];
        float nw = (r[3] - r[1]) * d[2];
        float nh = (r[4] - r[2]) * d[3];
        float* nr = g_nrois + roi*5;
        nr[0] = r[0];
        nr[1] = cx - 0.5f*nw;  nr[2] = cy - 0.5f*nh;
        nr[3] = cx + 0.5f*nw;  nr[4] = cy + 0.5f*nh;
    }
}

// ---------------- fp32 NT GEMM: C[M,N] = A[M,K] * B[N,K]^T + bias -----------
// 64x64 tile, BK=16, 256 threads, 4x4 micro-tile. M must be multiple of 64,
// K multiple of 16. N guarded (for N=98).
template<int ACT>    // 0 = none, 1 = relu
__global__ void gemm_nt(const float* __restrict__ A, const float* __restrict__ B,
                        const float* __restrict__ bias, float* __restrict__ C,
                        int N, int K) {
    const int BM = 64, BN = 64, BK = 16;
    __shared__ float As[BK][BM+4];
    __shared__ float Bs[BK][BN+4];
    int tid = threadIdx.x;
    int bm = blockIdx.y * BM, bn = blockIdx.x * BN;
    int ty = tid >> 4, tx = tid & 15;
    int lr = tid >> 2, lk = (tid & 3) << 2;

    float acc[4][4] = {};
    const float* Ap = A + (size_t)(bm + lr)*K + lk;
    bool bvalid = (bn + lr) < N;
    const float* Bp = B + (size_t)(bn + lr)*K + lk;

    for (int k0 = 0; k0 < K; k0 += BK) {
        float4 av = *(const float4*)(Ap + k0);
        float4 bv = bvalid ? *(const float4*)(Bp + k0) : make_float4(0,0,0,0);
        As[lk  ][lr] = av.x; As[lk+1][lr] = av.y; As[lk+2][lr] = av.z; As[lk+3][lr] = av.w;
        Bs[lk  ][lr] = bv.x; Bs[lk+1][lr] = bv.y; Bs[lk+2][lr] = bv.z; Bs[lk+3][lr] = bv.w;
        __syncthreads();
        #pragma unroll
        for (int k = 0; k < BK; k++) {
            float4 a4 = *(const float4*)&As[k][ty*4];
            float4 b4 = *(const float4*)&Bs[k][tx*4];
            float a[4] = {a4.x, a4.y, a4.z, a4.w};
            float bb[4] = {b4.x, b4.y, b4.z, b4.w};
            #pragma unroll
            for (int i = 0; i < 4; i++)
                #pragma unroll
                for (int j = 0; j < 4; j++)
                    acc[i][j] += a[i] * bb[j];
        }
        __syncthreads();
    }
    #pragma unroll
    for (int i = 0; i < 4; i++) {
        int m = bm + ty*4 + i;
        #pragma unroll
        for (int j = 0; j < 4; j++) {
            int n = bn + tx*4 + j;
            if (n < N) {
                float v = acc[i][j] + bias[n];
                if (ACT == 1) v = fmaxf(v, 0.0f);
                C[(size_t)m*N + n] = v;
            }
        }
    }
}

// ---------------- launch -----------------------------------------------------
extern "C" void kernel_launch(void* const* d_in, const int* in_sizes, int n_in,
                              void* d_out, int out_size) {
    const float* input     = (const float*)d_in[0];
    const float* rois      = (const float*)d_in[1];
    const float* rescale_w = (const float*)d_in[2];
    const float* rescale_b = (const float*)d_in[3];
    const float* off_w1    = (const float*)d_in[4];
    const float* off_b1    = (const float*)d_in[5];
    const float* off_w2    = (const float*)d_in[6];
    const float* off_b2    = (const float*)d_in[7];
    const float* off_w3    = (const float*)d_in[8];
    const float* off_b3    = (const float*)d_in[9];

    float* xcls = (float*)d_out;
    float* xreg = xcls + (size_t)NROIS * FDIM;

    float *h1p, *h2p, *offp, *nroisp;
    cudaGetSymbolAddress((void**)&h1p,    g_h1);
    cudaGetSymbolAddress((void**)&h2p,    g_h2);
    cudaGetSymbolAddress((void**)&offp,   g_off);
    cudaGetSymbolAddress((void**)&nroisp, g_nrois);

    const int smem_pool = FDIM * sizeof(float);   // 50176 > 48KB default
    cudaFuncSetAttribute(roi_pool<false>, cudaFuncAttributeMaxDynamicSharedMemorySize, smem_pool);
    cudaFuncSetAttribute(roi_pool<true>,  cudaFuncAttributeMaxDynamicSharedMemorySize, smem_pool);

    // 1) transpose to NHWC
    nchw2nhwc<<<dim3(HW/32, CH/32, BATCH), dim3(32, 8)>>>(input);
    // 2) x_cls pool (no offsets) -> first half of d_out (also serves as `flat`)
    roi_pool<false><<<NROIS, CH, smem_pool>>>(rois, nullptr, xcls);
    // 3) rescale head (4 dots) + new_rois
    rescale_newrois<<<NROIS, 256>>>(xcls, rois, rescale_w, rescale_b);
    // 4) offset MLP
    gemm_nt<1><<<dim3(DFC/64,  NROIS/64), 256>>>(xcls, off_w1, off_b1, h1p, DFC,  FDIM);
    gemm_nt<1><<<dim3(DFC/64,  NROIS/64), 256>>>(h1p,  off_w2, off_b2, h2p, DFC,  DFC);
    gemm_nt<0><<<dim3(2,       NROIS/64), 256>>>(h2p,  off_w3, off_b3, offp, NOFF, DFC);
    // 5) x_reg pool (new rois + offsets) -> second half of d_out
    roi_pool<true><<<NROIS, CH, smem_pool>>>(nroisp, offp, xreg);
}

// round 2
// speedup vs baseline: 1.8676x; 1.8676x over previous
#include <cuda_runtime.h>
#include <math.h>
#include <stdint.h>

#define BATCH 4
#define CH    256
#define FH    100
#define FW    152
#define HW    (FH*FW)          // 15200
#define NROIS 512
#define OH    7
#define OW    7
#define NBIN  49
#define FDIM  (CH*NBIN)        // 12544
#define DFC   1024
#define NOFF  98               // 2*49
#define SCALE 0.0625f
#define GAMMA 0.1f

// ---------------- scratch (device globals; no allocation allowed) -----------
__device__ float g_feat[(size_t)BATCH*HW*CH];   // NHWC features, 62.3 MB
__device__ float g_h1[NROIS*DFC];
__device__ float g_h2[NROIS*DFC];
__device__ float g_off[NROIS*NOFF];
__device__ float g_nrois[NROIS*5];
__device__ float g_part[2*(size_t)NROIS*DFC];   // split-K partials (4 MB)

// ---------------- NCHW -> NHWC transpose ------------------------------------
__global__ void nchw2nhwc(const float* __restrict__ in) {
    __shared__ float tile[32][33];
    int b   = blockIdx.z;
    int hw0 = blockIdx.x * 32;
    int c0  = blockIdx.y * 32;
    #pragma unroll
    for (int r = 0; r < 4; r++) {
        int c  = c0 + threadIdx.y + r*8;
        int hw = hw0 + threadIdx.x;
        tile[threadIdx.y + r*8][threadIdx.x] = in[((size_t)b*CH + c)*HW + hw];
    }
    __syncthreads();
    #pragma unroll
    for (int r = 0; r < 4; r++) {
        int hw = hw0 + threadIdx.y + r*8;
        int c  = c0 + threadIdx.x;
        g_feat[((size_t)b*HW + hw)*CH + c] = tile[threadIdx.x][threadIdx.y + r*8];
    }
}

// ---------------- deformable RoI pool ---------------------------------------
template<bool HAS_OFF>
__global__ void roi_pool(const float* __restrict__ rois,
                         const float* __restrict__ off,
                         float* __restrict__ out) {
    extern __shared__ float sout[];           // FDIM floats
    int roi = blockIdx.x;
    int c   = threadIdx.x;
    const float* r = rois + roi*5;
    int   b  = (int)r[0];
    float x1 = r[1]*SCALE - 0.5f;
    float y1 = r[2]*SCALE - 0.5f;
    float x2 = r[3]*SCALE - 0.5f;
    float y2 = r[4]*SCALE - 0.5f;
    float rw = x2 - x1, rh = y2 - y1;
    float bw = rw * (1.0f/OW), bh = rh * (1.0f/OH);
    const float* fb = g_feat + (size_t)b*HW*CH;

    for (int bin = 0; bin < NBIN; bin++) {
        int ph = bin / OW, pw = bin % OW;
        float sw = x1, sh = y1;
        if (HAS_OFF) {
            sw += GAMMA * rw * off[roi*NOFF + bin];
            sh += GAMMA * rh * off[roi*NOFF + NBIN + bin];
        }
        float acc = 0.0f;
        #pragma unroll
        for (int iy = 0; iy < 2; iy++) {
            float y = sh + ((float)ph + ((float)iy + 0.5f)*0.5f) * bh;
            #pragma unroll
            for (int ix = 0; ix < 2; ix++) {
                float x = sw + ((float)pw + ((float)ix + 0.5f)*0.5f) * bw;
                if (y > -1.0f && y < (float)FH && x > -1.0f && x < (float)FW) {
                    float yc = fminf(fmaxf(y, 0.0f), (float)(FH-1));
                    float xc = fminf(fmaxf(x, 0.0f), (float)(FW-1));
                    int y0 = min((int)floorf(yc), FH-2);
                    int x0 = min((int)floorf(xc), FW-2);
                    float ly = yc - (float)y0, lx = xc - (float)x0;
                    float hy = 1.0f - ly,     hx = 1.0f - lx;
                    const float* p = fb + ((size_t)y0*FW + x0)*CH + c;
                    acc += hy*hx*p[0] + hy*lx*p[CH]
                         + ly*hx*p[FW*CH] + ly*lx*p[FW*CH + CH];
                }
            }
        }
        sout[c*NBIN + bin] = acc * 0.25f;
    }
    __syncthreads();
    float* o = out + (size_t)roi * FDIM;
    for (int i = c; i < FDIM; i += CH) o[i] = sout[i];
}

// ---------------- rescale head (only 4 of 98 outputs used) + new_rois -------
__global__ void rescale_newrois(const float* __restrict__ flat,
                                const float* __restrict__ rois,
                                const float* __restrict__ w,
                                const float* __restrict__ bias) {
    int roi = blockIdx.x;
    int tid = threadIdx.x;       // 256
    const float* f = flat + (size_t)roi * FDIM;
    float s0 = 0.f, s1 = 0.f, s2 = 0.f, s3 = 0.f;
    for (int k = tid; k < FDIM; k += 256) {
        float v = f[k];
        s0 += v * w[k];
        s1 += v * w[FDIM + k];
        s2 += v * w[2*FDIM + k];
        s3 += v * w[3*FDIM + k];
    }
    #pragma unroll
    for (int o = 16; o > 0; o >>= 1) {
        s0 += __shfl_down_sync(0xffffffffu, s0, o);
        s1 += __shfl_down_sync(0xffffffffu, s1, o);
        s2 += __shfl_down_sync(0xffffffffu, s2, o);
        s3 += __shfl_down_sync(0xffffffffu, s3, o);
    }
    __shared__ float red[4][8];
    int lane = tid & 31, warp = tid >> 5;
    if (lane == 0) { red[0][warp]=s0; red[1][warp]=s1; red[2][warp]=s2; red[3][warp]=s3; }
    __syncthreads();
    if (tid == 0) {
        float d[4];
        #pragma unroll
        for (int j = 0; j < 4; j++) {
            float t = 0.f;
            #pragma unroll
            for (int ww = 0; ww < 8; ww++) t += red[j][ww];
            d[j] = 1.0f + 0.5f / (1.0f + expf(-(t + bias[j])));
        }
        const float* r = rois + roi*5;
        float cx = (r[1] + r[3]) * 0.5f + d[0];
        float cy = (r[2] + r[4]) * 0.5f + d[1];
        float nw = (r[3] - r[1]) * d[2];
        float nh = (r[4] - r[2]) * d[3];
        float* nr = g_nrois + roi*5;
        nr[0] = r[0];
        nr[1] = cx - 0.5f*nw;  nr[2] = cy - 0.5f*nh;
        nr[3] = cx + 0.5f*nw;  nr[4] = cy + 0.5f*nh;
    }
}

// ---------------- tf32 tensor-core NT GEMM ----------------------------------
// P[kz][M][N] partial = A[M, kz*K/2 : ...] * B[N, ...]^T  (split-K x2)
// BM=64, BN=128, BK=16, 256 threads (8 warps, 2x4 warp grid, 32x32 warp tile).
// XOR-swizzled smem: idx(k,m) = k*W + (m ^ ((((k&3)^((k>>2)&3)))<<3))
// -> conflict-free for both the float4 store pattern and the mma-fragment loads.

__device__ __forceinline__ uint32_t f2tf(float x) {
    uint32_t u;
    asm("cvt.rna.tf32.f32 %0, %1;" : "=r"(u) : "f"(x));
    return u;
}

__device__ __forceinline__ void mma_tf32(float* c, const uint32_t* a, const uint32_t* b) {
    asm volatile(
        "mma.sync.aligned.m16n8k8.row.col.f32.tf32.tf32.f32 "
        "{%0,%1,%2,%3}, {%4,%5,%6,%7}, {%8,%9}, {%0,%1,%2,%3};"
        : "+f"(c[0]), "+f"(c[1]), "+f"(c[2]), "+f"(c[3])
        : "r"(a[0]), "r"(a[1]), "r"(a[2]), "r"(a[3]), "r"(b[0]), "r"(b[1]));
}

__global__ void __launch_bounds__(256)
gemm_tf32(const float* __restrict__ A, const float* __restrict__ B,
          float* __restrict__ P, int N, int K) {
    const int BM = 64, BN = 128, BK = 16;
    __shared__ uint32_t As[2][BK*BM];
    __shared__ uint32_t Bs[2][BK*BN];

    int tid  = threadIdx.x;
    int lane = tid & 31, w = tid >> 5;
    int g = lane >> 2, tig = lane & 3;
    int wm = w >> 2, wn = w & 3;
    int bm = blockIdx.y * BM, bn = blockIdx.x * BN;
    int Kh = K >> 1;
    int kz = blockIdx.z;
    int M  = gridDim.y * BM;

    // ---- loader setup: each thread loads one float4 of A, two of B per stage
    int lm = tid >> 2, lq = tid & 3;
    const float* Ap  = A + (size_t)(bm + lm)*K + (size_t)kz*Kh + lq*4;
    int brow0 = bn + lm, brow1 = bn + lm + 64;
    bool bv0 = brow0 < N, bv1 = brow1 < N;
    const float* Bp0 = B + (size_t)min(brow0, N-1)*K + (size_t)kz*Kh + lq*4;
    const float* Bp1 = B + (size_t)min(brow1, N-1)*K + (size_t)kz*Kh + lq*4;

    int sa[4], sb[4];
    #pragma unroll
    for (int e = 0; e < 4; e++) {
        int k  = lq*4 + e;
        int sw = (((k & 3) ^ ((k >> 2) & 3)) << 3);
        sa[e] = k*BM + (lm ^ sw);
        sb[e] = k*BN + (lm ^ sw);   // row lm+64 -> sb[e]+64 (bit6 untouched by sw)
    }

    float acc[2][4][4];
    #pragma unroll
    for (int i = 0; i < 2; i++)
        #pragma unroll
        for (int j = 0; j < 4; j++)
            #pragma unroll
            for (int q = 0; q < 4; q++) acc[i][j][q] = 0.0f;

    const int nstage = Kh / BK;
    float4 fa  = *(const float4*)Ap;
    float4 fb0 = bv0 ? *(const float4*)Bp0 : make_float4(0,0,0,0);
    float4 fb1 = bv1 ? *(const float4*)Bp1 : make_float4(0,0,0,0);
    {
        uint32_t* as = As[0]; uint32_t* bs = Bs[0];
        as[sa[0]] = f2tf(fa.x);  as[sa[1]] = f2tf(fa.y);
        as[sa[2]] = f2tf(fa.z);  as[sa[3]] = f2tf(fa.w);
        bs[sb[0]] = f2tf(fb0.x); bs[sb[1]] = f2tf(fb0.y);
        bs[sb[2]] = f2tf(fb0.z); bs[sb[3]] = f2tf(fb0.w);
        bs[sb[0]+64] = f2tf(fb1.x); bs[sb[1]+64] = f2tf(fb1.y);
        bs[sb[2]+64] = f2tf(fb1.z); bs[sb[3]+64] = f2tf(fb1.w);
    }
    __syncthreads();

    for (int s = 0; s < nstage; s++) {
        int buf = s & 1;
        if (s + 1 < nstage) {
            fa  = *(const float4*)(Ap  + (size_t)(s+1)*BK);
            fb0 = bv0 ? *(const float4*)(Bp0 + (size_t)(s+1)*BK) : make_float4(0,0,0,0);
            fb1 = bv1 ? *(const float4*)(Bp1 + (size_t)(s+1)*BK) : make_float4(0,0,0,0);
        }
        const uint32_t* as = As[buf];
        const uint32_t* bs = Bs[buf];
        #pragma unroll
        for (int kb = 0; kb < 2; kb++) {
            uint32_t af[2][4], bf[4][2];
            #pragma unroll
            for (int h = 0; h < 2; h++) {
                int k  = kb*8 + tig + h*4;
                int sw = (((k & 3) ^ ((k >> 2) & 3)) << 3);
                int ka = k*BM, kb2 = k*BN;
                #pragma unroll
                for (int ii = 0; ii < 2; ii++) {
                    int m0 = wm*32 + ii*16 + g;
                    af[ii][h*2+0] = as[ka + ( m0      ^ sw)];
                    af[ii][h*2+1] = as[ka + ((m0 + 8) ^ sw)];
                }
                #pragma unroll
                for (int jj = 0; jj < 4; jj++) {
                    int n0 = wn*32 + jj*8 + g;
                    bf[jj][h] = bs[kb2 + (n0 ^ sw)];
                }
            }
            #pragma unroll
            for (int ii = 0; ii < 2; ii++)
                #pragma unroll
                for (int jj = 0; jj < 4; jj++)
                    mma_tf32(acc[ii][jj], af[ii], bf[jj]);
        }
        if (s + 1 < nstage) {
            uint32_t* asn = As[buf ^ 1]; uint32_t* bsn = Bs[buf ^ 1];
            asn[sa[0]] = f2tf(fa.x);  asn[sa[1]] = f2tf(fa.y);
            asn[sa[2]] = f2tf(fa.z);  asn[sa[3]] = f2tf(fa.w);
            bsn[sb[0]] = f2tf(fb0.x); bsn[sb[1]] = f2tf(fb0.y);
            bsn[sb[2]] = f2tf(fb0.z); bsn[sb[3]] = f2tf(fb0.w);
            bsn[sb[0]+64] = f2tf(fb1.x); bsn[sb[1]+64] = f2tf(fb1.y);
            bsn[sb[2]+64] = f2tf(fb1.z); bsn[sb[3]+64] = f2tf(fb1.w);
        }
        __syncthreads();
    }

    // ---- epilogue: write fp32 partials
    float* Pp = P + (size_t)kz * M * N;
    #pragma unroll
    for (int ii = 0; ii < 2; ii++) {
        #pragma unroll
        for (int jj = 0; jj < 4; jj++) {
            int r0 = bm + wm*32 + ii*16 + g;
            int c0 = bn + wn*32 + jj*8 + tig*2;
            if (c0 < N) {
                Pp[(size_t)r0*N + c0]       = acc[ii][jj][0];
                Pp[(size_t)r0*N + c0 + 1]   = acc[ii][jj][1];
                Pp[(size_t)(r0+8)*N + c0]   = acc[ii][jj][2];
                Pp[(size_t)(r0+8)*N + c0+1] = acc[ii][jj][3];
            }
        }
    }
}

// ---------------- split-K combine: out = act(P0 + P1 + bias) ----------------
template<bool RELU>
__global__ void combine(const float* __restrict__ P, const float* __restrict__ bias,
                        float* __restrict__ out, int M, int N) {
    int i = blockIdx.x * 256 + threadIdx.x;
    if (i >= M*N) return;
    int n = i % N;
    float v = P[i] + P[(size_t)M*N + i] + bias[n];
    if (RELU) v = fmaxf(v, 0.0f);
    out[i] = v;
}

// ---------------- launch -----------------------------------------------------
extern "C" void kernel_launch(void* const* d_in, const int* in_sizes, int n_in,
                              void* d_out, int out_size) {
    const float* input     = (const float*)d_in[0];
    const float* rois      = (const float*)d_in[1];
    const float* rescale_w = (const float*)d_in[2];
    const float* rescale_b = (const float*)d_in[3];
    const float* off_w1    = (const float*)d_in[4];
    const float* off_b1    = (const float*)d_in[5];
    const float* off_w2    = (const float*)d_in[6];
    const float* off_b2    = (const float*)d_in[7];
    const float* off_w3    = (const float*)d_in[8];
    const float* off_b3    = (const float*)d_in[9];

    float* xcls = (float*)d_out;
    float* xreg = xcls + (size_t)NROIS * FDIM;

    float *h1p, *h2p, *offp, *nroisp, *partp;
    cudaGetSymbolAddress((void**)&h1p,    g_h1);
    cudaGetSymbolAddress((void**)&h2p,    g_h2);
    cudaGetSymbolAddress((void**)&offp,   g_off);
    cudaGetSymbolAddress((void**)&nroisp, g_nrois);
    cudaGetSymbolAddress((void**)&partp,  g_part);

    const int smem_pool = FDIM * sizeof(float);
    cudaFuncSetAttribute(roi_pool<false>, cudaFuncAttributeMaxDynamicSharedMemorySize, smem_pool);
    cudaFuncSetAttribute(roi_pool<true>,  cudaFuncAttributeMaxDynamicSharedMemorySize, smem_pool);

    // 1) transpose to NHWC
    nchw2nhwc<<<dim3(HW/32, CH/32, BATCH), dim3(32, 8)>>>(input);
    // 2) x_cls pool -> first half of d_out (also serves as `flat`)
    roi_pool<false><<<NROIS, CH, smem_pool>>>(rois, nullptr, xcls);
    // 3) rescale head (exact fp32) + new_rois
    rescale_newrois<<<NROIS, 256>>>(xcls, rois, rescale_w, rescale_b);
    // 4) offset MLP on tf32 tensor cores (split-K x2 + combine)
    gemm_tf32<<<dim3(DFC/128, NROIS/64, 2), 256>>>(xcls, off_w1, partp, DFC, FDIM);
    combine<true><<<(NROIS*DFC + 255)/256, 256>>>(partp, off_b1, h1p, NROIS, DFC);
    gemm_tf32<<<dim3(DFC/128, NROIS/64, 2), 256>>>(h1p, off_w2, partp, DFC, DFC);
    combine<true><<<(NROIS*DFC + 255)/256, 256>>>(partp, off_b2, h2p, NROIS, DFC);
    gemm_tf32<<<dim3(1, NROIS/64, 2), 256>>>(h2p, off_w3, partp, NOFF, DFC);
    combine<false><<<(NROIS*NOFF + 255)/256, 256>>>(partp, off_b3, offp, NROIS, NOFF);
    // 5) x_reg pool (new rois + offsets) -> second half of d_out
    roi_pool<true><<<NROIS, CH, smem_pool>>>(nroisp, offp, xreg);
}

// round 3
// speedup vs baseline: 2.3398x; 1.2528x over previous
#include <cuda_runtime.h>
#include <math.h>
#include <stdint.h>

#define BATCH 4
#define CH    256
#define FH    100
#define FW    152
#define HW    (FH*FW)          // 15200
#define NROIS 512
#define OH    7
#define OW    7
#define NBIN  49
#define FDIM  (CH*NBIN)        // 12544
#define DFC   1024
#define NOFF  98               // 2*49
#define SCALE 0.0625f
#define GAMMA 0.1f
#define SPLITK 4

// ---------------- scratch (device globals; no allocation allowed) -----------
__device__ float g_feat[(size_t)BATCH*HW*CH];   // NHWC features, 62.3 MB
__device__ float g_h1[NROIS*DFC];
__device__ float g_h2[NROIS*DFC];
__device__ float g_off[NROIS*NOFF];
__device__ float g_nrois[NROIS*5];
__device__ float g_part[SPLITK*(size_t)NROIS*DFC];   // split-K partials (8 MB)

// ---------------- NCHW -> NHWC transpose ------------------------------------
__global__ void nchw2nhwc(const float* __restrict__ in) {
    __shared__ float tile[32][33];
    int b   = blockIdx.z;
    int hw0 = blockIdx.x * 32;
    int c0  = blockIdx.y * 32;
    #pragma unroll
    for (int r = 0; r < 4; r++) {
        int c  = c0 + threadIdx.y + r*8;
        int hw = hw0 + threadIdx.x;
        tile[threadIdx.y + r*8][threadIdx.x] = in[((size_t)b*CH + c)*HW + hw];
    }
    __syncthreads();
    #pragma unroll
    for (int r = 0; r < 4; r++) {
        int hw = hw0 + threadIdx.y + r*8;
        int c  = c0 + threadIdx.x;
        g_feat[((size_t)b*HW + hw)*CH + c] = tile[threadIdx.x][threadIdx.y + r*8];
    }
}

// ---------------- deformable RoI pool ---------------------------------------
template<bool HAS_OFF>
__global__ void roi_pool(const float* __restrict__ rois,
                         const float* __restrict__ off,
                         float* __restrict__ out) {
    extern __shared__ float sout[];           // FDIM floats
    int roi = blockIdx.x;
    int c   = threadIdx.x;
    const float* r = rois + roi*5;
    int   b  = (int)r[0];
    float x1 = r[1]*SCALE - 0.5f;
    float y1 = r[2]*SCALE - 0.5f;
    float x2 = r[3]*SCALE - 0.5f;
    float y2 = r[4]*SCALE - 0.5f;
    float rw = x2 - x1, rh = y2 - y1;
    float bw = rw * (1.0f/OW), bh = rh * (1.0f/OH);
    const float* fb = g_feat + (size_t)b*HW*CH;

    for (int bin = 0; bin < NBIN; bin++) {
        int ph = bin / OW, pw = bin % OW;
        float sw = x1, sh = y1;
        if (HAS_OFF) {
            sw += GAMMA * rw * off[roi*NOFF + bin];
            sh += GAMMA * rh * off[roi*NOFF + NBIN + bin];
        }
        float acc = 0.0f;
        #pragma unroll
        for (int iy = 0; iy < 2; iy++) {
            float y = sh + ((float)ph + ((float)iy + 0.5f)*0.5f) * bh;
            #pragma unroll
            for (int ix = 0; ix < 2; ix++) {
                float x = sw + ((float)pw + ((float)ix + 0.5f)*0.5f) * bw;
                if (y > -1.0f && y < (float)FH && x > -1.0f && x < (float)FW) {
                    float yc = fminf(fmaxf(y, 0.0f), (float)(FH-1));
                    float xc = fminf(fmaxf(x, 0.0f), (float)(FW-1));
                    int y0 = min((int)floorf(yc), FH-2);
                    int x0 = min((int)floorf(xc), FW-2);
                    float ly = yc - (float)y0, lx = xc - (float)x0;
                    float hy = 1.0f - ly,     hx = 1.0f - lx;
                    const float* p = fb + ((size_t)y0*FW + x0)*CH + c;
                    acc += hy*hx*p[0] + hy*lx*p[CH]
                         + ly*hx*p[FW*CH] + ly*lx*p[FW*CH + CH];
                }
            }
        }
        sout[c*NBIN + bin] = acc * 0.25f;
    }
    __syncthreads();
    float* o = out + (size_t)roi * FDIM;
    for (int i = c; i < FDIM; i += CH) o[i] = sout[i];
}

// ---------------- rescale head (only 4 of 98 outputs used) + new_rois -------
__global__ void rescale_newrois(const float* __restrict__ flat,
                                const float* __restrict__ rois,
                                const float* __restrict__ w,
                                const float* __restrict__ bias) {
    int roi = blockIdx.x;
    int tid = threadIdx.x;       // 256
    const float* f = flat + (size_t)roi * FDIM;
    float s0 = 0.f, s1 = 0.f, s2 = 0.f, s3 = 0.f;
    for (int k = tid; k < FDIM; k += 256) {
        float v = f[k];
        s0 += v * w[k];
        s1 += v * w[FDIM + k];
        s2 += v * w[2*FDIM + k];
        s3 += v * w[3*FDIM + k];
    }
    #pragma unroll
    for (int o = 16; o > 0; o >>= 1) {
        s0 += __shfl_down_sync(0xffffffffu, s0, o);
        s1 += __shfl_down_sync(0xffffffffu, s1, o);
        s2 += __shfl_down_sync(0xffffffffu, s2, o);
        s3 += __shfl_down_sync(0xffffffffu, s3, o);
    }
    __shared__ float red[4][8];
    int lane = tid & 31, warp = tid >> 5;
    if (lane == 0) { red[0][warp]=s0; red[1][warp]=s1; red[2][warp]=s2; red[3][warp]=s3; }
    __syncthreads();
    if (tid == 0) {
        float d[4];
        #pragma unroll
        for (int j = 0; j < 4; j++) {
            float t = 0.f;
            #pragma unroll
            for (int ww = 0; ww < 8; ww++) t += red[j][ww];
            d[j] = 1.0f + 0.5f / (1.0f + expf(-(t + bias[j])));
        }
        const float* r = rois + roi*5;
        float cx = (r[1] + r[3]) * 0.5f + d[0];
        float cy = (r[2] + r[4]) * 0.5f + d[1];
        float nw = (r[3] - r[1]) * d[2];
        float nh = (r[4] - r[2]) * d[3];
        float* nr = g_nrois + roi*5;
        nr[0] = r[0];
        nr[1] = cx - 0.5f*nw;  nr[2] = cy - 0.5f*nh;
        nr[3] = cx + 0.5f*nw;  nr[4] = cy + 0.5f*nh;
    }
}

// ---------------- tf32 tensor-core NT GEMM ----------------------------------
// P[kz][M][N] partial = A[M, kz*K/S : ...] * B[N, ...]^T  (split-K = gridDim.z)
// BM=64, BN=128, BK=16, 256 threads (8 warps, 2x4 warp grid, 32x32 warp tile).
// XOR-swizzled smem: idx(k,m) = k*W + (m ^ ((((k&3)^((k>>2)&3)))<<3))
// -> conflict-free for both the float4 store pattern and the mma-fragment loads.

__device__ __forceinline__ uint32_t f2tf(float x) {
    uint32_t u;
    asm("cvt.rna.tf32.f32 %0, %1;" : "=r"(u) : "f"(x));
    return u;
}

__device__ __forceinline__ void mma_tf32(float* c, const uint32_t* a, const uint32_t* b) {
    asm volatile(
        "mma.sync.aligned.m16n8k8.row.col.f32.tf32.tf32.f32 "
        "{%0,%1,%2,%3}, {%4,%5,%6,%7}, {%8,%9}, {%0,%1,%2,%3};"
        : "+f"(c[0]), "+f"(c[1]), "+f"(c[2]), "+f"(c[3])
        : "r"(a[0]), "r"(a[1]), "r"(a[2]), "r"(a[3]), "r"(b[0]), "r"(b[1]));
}

__global__ void __launch_bounds__(256, 2)
gemm_tf32(const float* __restrict__ A, const float* __restrict__ B,
          float* __restrict__ P, int N, int K) {
    const int BM = 64, BN = 128, BK = 16;
    __shared__ uint32_t As[2][BK*BM];
    __shared__ uint32_t Bs[2][BK*BN];

    int tid  = threadIdx.x;
    int lane = tid & 31, w = tid >> 5;
    int g = lane >> 2, tig = lane & 3;
    int wm = w >> 2, wn = w & 3;
    int bm = blockIdx.y * BM, bn = blockIdx.x * BN;
    int S  = gridDim.z;
    int Kh = K / S;
    int kz = blockIdx.z;
    int M  = gridDim.y * BM;

    // ---- loader setup: each thread loads one float4 of A, two of B per stage
    int lm = tid >> 2, lq = tid & 3;
    const float* Ap  = A + (size_t)(bm + lm)*K + (size_t)kz*Kh + lq*4;
    int brow0 = bn + lm, brow1 = bn + lm + 64;
    bool bv0 = brow0 < N, bv1 = brow1 < N;
    const float* Bp0 = B + (size_t)min(brow0, N-1)*K + (size_t)kz*Kh + lq*4;
    const float* Bp1 = B + (size_t)min(brow1, N-1)*K + (size_t)kz*Kh + lq*4;

    int sa[4], sb[4];
    #pragma unroll
    for (int e = 0; e < 4; e++) {
        int k  = lq*4 + e;
        int sw = (((k & 3) ^ ((k >> 2) & 3)) << 3);
        sa[e] = k*BM + (lm ^ sw);
        sb[e] = k*BN + (lm ^ sw);   // row lm+64 -> sb[e]+64 (bit6 untouched by sw)
    }

    float acc[2][4][4];
    #pragma unroll
    for (int i = 0; i < 2; i++)
        #pragma unroll
        for (int j = 0; j < 4; j++)
            #pragma unroll
            for (int q = 0; q < 4; q++) acc[i][j][q] = 0.0f;

    const int nstage = Kh / BK;
    float4 fa  = *(const float4*)Ap;
    float4 fb0 = bv0 ? *(const float4*)Bp0 : make_float4(0,0,0,0);
    float4 fb1 = bv1 ? *(const float4*)Bp1 : make_float4(0,0,0,0);
    {
        uint32_t* as = As[0]; uint32_t* bs = Bs[0];
        as[sa[0]] = f2tf(fa.x);  as[sa[1]] = f2tf(fa.y);
        as[sa[2]] = f2tf(fa.z);  as[sa[3]] = f2tf(fa.w);
        bs[sb[0]] = f2tf(fb0.x); bs[sb[1]] = f2tf(fb0.y);
        bs[sb[2]] = f2tf(fb0.z); bs[sb[3]] = f2tf(fb0.w);
        bs[sb[0]+64] = f2tf(fb1.x); bs[sb[1]+64] = f2tf(fb1.y);
        bs[sb[2]+64] = f2tf(fb1.z); bs[sb[3]+64] = f2tf(fb1.w);
    }
    __syncthreads();

    for (int s = 0; s < nstage; s++) {
        int buf = s & 1;
        if (s + 1 < nstage) {
            fa  = *(const float4*)(Ap  + (size_t)(s+1)*BK);
            fb0 = bv0 ? *(const float4*)(Bp0 + (size_t)(s+1)*BK) : make_float4(0,0,0,0);
            fb1 = bv1 ? *(const float4*)(Bp1 + (size_t)(s+1)*BK) : make_float4(0,0,0,0);
        }
        const uint32_t* as = As[buf];
        const uint32_t* bs = Bs[buf];
        #pragma unroll
        for (int kb = 0; kb < 2; kb++) {
            uint32_t af[2][4], bf[4][2];
            #pragma unroll
            for (int h = 0; h < 2; h++) {
                int k  = kb*8 + tig + h*4;
                int sw = (((k & 3) ^ ((k >> 2) & 3)) << 3);
                int ka = k*BM, kb2 = k*BN;
                #pragma unroll
                for (int ii = 0; ii < 2; ii++) {
                    int m0 = wm*32 + ii*16 + g;
                    af[ii][h*2+0] = as[ka + ( m0      ^ sw)];
                    af[ii][h*2+1] = as[ka + ((m0 + 8) ^ sw)];
                }
                #pragma unroll
                for (int jj = 0; jj < 4; jj++) {
                    int n0 = wn*32 + jj*8 + g;
                    bf[jj][h] = bs[kb2 + (n0 ^ sw)];
                }
            }
            #pragma unroll
            for (int ii = 0; ii < 2; ii++)
                #pragma unroll
                for (int jj = 0; jj < 4; jj++)
                    mma_tf32(acc[ii][jj], af[ii], bf[jj]);
        }
        if (s + 1 < nstage) {
            uint32_t* asn = As[buf ^ 1]; uint32_t* bsn = Bs[buf ^ 1];
            asn[sa[0]] = f2tf(fa.x);  asn[sa[1]] = f2tf(fa.y);
            asn[sa[2]] = f2tf(fa.z);  asn[sa[3]] = f2tf(fa.w);
            bsn[sb[0]] = f2tf(fb0.x); bsn[sb[1]] = f2tf(fb0.y);
            bsn[sb[2]] = f2tf(fb0.z); bsn[sb[3]] = f2tf(fb0.w);
            bsn[sb[0]+64] = f2tf(fb1.x); bsn[sb[1]+64] = f2tf(fb1.y);
            bsn[sb[2]+64] = f2tf(fb1.z); bsn[sb[3]+64] = f2tf(fb1.w);
        }
        __syncthreads();
    }

    // ---- epilogue: write fp32 partials
    float* Pp = P + (size_t)kz * M * N;
    #pragma unroll
    for (int ii = 0; ii < 2; ii++) {
        #pragma unroll
        for (int jj = 0; jj < 4; jj++) {
            int r0 = bm + wm*32 + ii*16 + g;
            int c0 = bn + wn*32 + jj*8 + tig*2;
            if (c0 < N) {
                Pp[(size_t)r0*N + c0]       = acc[ii][jj][0];
                Pp[(size_t)r0*N + c0 + 1]   = acc[ii][jj][1];
                Pp[(size_t)(r0+8)*N + c0]   = acc[ii][jj][2];
                Pp[(size_t)(r0+8)*N + c0+1] = acc[ii][jj][3];
            }
        }
    }
}

// ---------------- split-K combine: out = act(sum_s P_s + bias) --------------
template<bool RELU>
__global__ void combine(const float* __restrict__ P, const float* __restrict__ bias,
                        float* __restrict__ out, int M, int N) {
    int i = blockIdx.x * 256 + threadIdx.x;
    if (i >= M*N) return;
    int n = i % N;
    float v = bias[n];
    #pragma unroll
    for (int s = 0; s < SPLITK; s++) v += P[(size_t)s*M*N + i];
    if (RELU) v = fmaxf(v, 0.0f);
    out[i] = v;
}

// ---------------- launch -----------------------------------------------------
extern "C" void kernel_launch(void* const* d_in, const int* in_sizes, int n_in,
                              void* d_out, int out_size) {
    const float* input     = (const float*)d_in[0];
    const float* rois      = (const float*)d_in[1];
    const float* rescale_w = (const float*)d_in[2];
    const float* rescale_b = (const float*)d_in[3];
    const float* off_w1    = (const float*)d_in[4];
    const float* off_b1    = (const float*)d_in[5];
    const float* off_w2    = (const float*)d_in[6];
    const float* off_b2    = (const float*)d_in[7];
    const float* off_w3    = (const float*)d_in[8];
    const float* off_b3    = (const float*)d_in[9];

    float* xcls = (float*)d_out;
    float* xreg = xcls + (size_t)NROIS * FDIM;

    float *h1p, *h2p, *offp, *nroisp, *partp;
    cudaGetSymbolAddress((void**)&h1p,    g_h1);
    cudaGetSymbolAddress((void**)&h2p,    g_h2);
    cudaGetSymbolAddress((void**)&offp,   g_off);
    cudaGetSymbolAddress((void**)&nroisp, g_nrois);
    cudaGetSymbolAddress((void**)&partp,  g_part);

    const int smem_pool = FDIM * sizeof(float);
    cudaFuncSetAttribute(roi_pool<false>, cudaFuncAttributeMaxDynamicSharedMemorySize, smem_pool);
    cudaFuncSetAttribute(roi_pool<true>,  cudaFuncAttributeMaxDynamicSharedMemorySize, smem_pool);

    // 1) transpose to NHWC
    nchw2nhwc<<<dim3(HW/32, CH/32, BATCH), dim3(32, 8)>>>(input);
    // 2) x_cls pool -> first half of d_out (also serves as `flat`)
    roi_pool<false><<<NROIS, CH, smem_pool>>>(rois, nullptr, xcls);
    // 3) rescale head (exact fp32) + new_rois
    rescale_newrois<<<NROIS, 256>>>(xcls, rois, rescale_w, rescale_b);
    // 4) offset MLP on tf32 tensor cores (split-K x4 + combine)
    gemm_tf32<<<dim3(DFC/128, NROIS/64, SPLITK), 256>>>(xcls, off_w1, partp, DFC, FDIM);
    combine<true><<<(NROIS*DFC + 255)/256, 256>>>(partp, off_b1, h1p, NROIS, DFC);
    gemm_tf32<<<dim3(DFC/128, NROIS/64, SPLITK), 256>>>(h1p, off_w2, partp, DFC, DFC);
    combine<true><<<(NROIS*DFC + 255)/256, 256>>>(partp, off_b2, h2p, NROIS, DFC);
    gemm_tf32<<<dim3(1, NROIS/64, SPLITK), 256>>>(h2p, off_w3, partp, NOFF, DFC);
    combine<false><<<(NROIS*NOFF + 255)/256, 256>>>(partp, off_b3, offp, NROIS, NOFF);
    // 5) x_reg pool (new rois + offsets) -> second half of d_out
    roi_pool<true><<<NROIS, CH, smem_pool>>>(nroisp, offp, xreg);
}

// round 4
// speedup vs baseline: 2.7671x; 1.1826x over previous
#include <cuda_runtime.h>
#include <math.h>
#include <stdint.h>

#define BATCH 4
#define CH    256
#define FH    100
#define FW    152
#define HW    (FH*FW)          // 15200
#define NROIS 512
#define OH    7
#define OW    7
#define NBIN  49
#define FDIM  (CH*NBIN)        // 12544
#define DFC   1024
#define NOFF  98               // 2*49
#define SCALE 0.0625f
#define GAMMA 0.1f
#define SPLITK 4

// ---------------- scratch (device globals; no allocation allowed) -----------
__device__ float g_feat[(size_t)BATCH*HW*CH];   // NHWC features, 62.3 MB
__device__ float g_h1[NROIS*DFC];
__device__ float g_h2[NROIS*DFC];
__device__ float g_off[NROIS*NOFF];
__device__ float g_nrois[NROIS*5];
__device__ float g_part[SPLITK*(size_t)NROIS*DFC];   // split-K partials (8 MB)

// ---------------- NCHW -> NHWC transpose ------------------------------------
__global__ void nchw2nhwc(const float* __restrict__ in) {
    __shared__ float tile[32][33];
    int b   = blockIdx.z;
    int hw0 = blockIdx.x * 32;
    int c0  = blockIdx.y * 32;
    #pragma unroll
    for (int r = 0; r < 4; r++) {
        int c  = c0 + threadIdx.y + r*8;
        int hw = hw0 + threadIdx.x;
        tile[threadIdx.y + r*8][threadIdx.x] = in[((size_t)b*CH + c)*HW + hw];
    }
    __syncthreads();
    #pragma unroll
    for (int r = 0; r < 4; r++) {
        int hw = hw0 + threadIdx.y + r*8;
        int c  = c0 + threadIdx.x;
        g_feat[((size_t)b*HW + hw)*CH + c] = tile[threadIdx.x][threadIdx.y + r*8];
    }
}

// ---------------- deformable RoI pool ---------------------------------------
// 1 block per ROI, 256 threads = (4 bins in flight) x (64 float4 channel groups).
template<bool HAS_OFF>
__global__ void roi_pool(const float* __restrict__ rois,
                         const float* __restrict__ off,
                         float* __restrict__ out) {
    extern __shared__ float sout[];           // FDIM floats
    int roi = blockIdx.x;
    int tid = threadIdx.x;
    int bq = tid >> 6, cq = tid & 63;         // bin quadrant, channel/4 group
    const float* r = rois + roi*5;
    int   b  = (int)r[0];
    float x1 = r[1]*SCALE - 0.5f;
    float y1 = r[2]*SCALE - 0.5f;
    float x2 = r[3]*SCALE - 0.5f;
    float y2 = r[4]*SCALE - 0.5f;
    float rw = x2 - x1, rh = y2 - y1;
    float bw = rw * (1.0f/OW), bh = rh * (1.0f/OH);
    const float4* fb4 = (const float4*)(g_feat + (size_t)b*HW*CH);

    for (int b0 = 0; b0 < NBIN; b0 += 4) {
        int bin = b0 + bq;
        if (bin < NBIN) {
            int ph = bin / OW, pw = bin - ph*OW;
            float sw_ = x1, sh_ = y1;
            if (HAS_OFF) {
                sw_ += GAMMA * rw * off[roi*NOFF + bin];
                sh_ += GAMMA * rh * off[roi*NOFF + NBIN + bin];
            }
            float ax = 0.f, ay = 0.f, az = 0.f, aw = 0.f;
            #pragma unroll
            for (int iy = 0; iy < 2; iy++) {
                float y = sh_ + ((float)ph + ((float)iy + 0.5f)*0.5f) * bh;
                #pragma unroll
                for (int ix = 0; ix < 2; ix++) {
                    float x = sw_ + ((float)pw + ((float)ix + 0.5f)*0.5f) * bw;
                    if (y > -1.0f && y < (float)FH && x > -1.0f && x < (float)FW) {
                        float yc = fminf(fmaxf(y, 0.0f), (float)(FH-1));
                        float xc = fminf(fmaxf(x, 0.0f), (float)(FW-1));
                        int y0 = min((int)floorf(yc), FH-2);
                        int x0 = min((int)floorf(xc), FW-2);
                        float ly = yc - (float)y0, lx = xc - (float)x0;
                        float hy = 1.0f - ly,     hx = 1.0f - lx;
                        float w00 = hy*hx, w01 = hy*lx, w10 = ly*hx, w11 = ly*lx;
                        const float4* p = fb4 + ((size_t)y0*FW + x0)*(CH/4) + cq;
                        float4 v00 = p[0];
                        float4 v01 = p[CH/4];
                        float4 v10 = p[FW*CH/4];
                        float4 v11 = p[FW*CH/4 + CH/4];
                        ax += w00*v00.x + w01*v01.x + w10*v10.x + w11*v11.x;
                        ay += w00*v00.y + w01*v01.y + w10*v10.y + w11*v11.y;
                        az += w00*v00.z + w01*v01.z + w10*v10.z + w11*v11.z;
                        aw += w00*v00.w + w01*v01.w + w10*v10.w + w11*v11.w;
                    }
                }
            }
            int c = cq*4;
            sout[(c+0)*NBIN + bin] = ax * 0.25f;
            sout[(c+1)*NBIN + bin] = ay * 0.25f;
            sout[(c+2)*NBIN + bin] = az * 0.25f;
            sout[(c+3)*NBIN + bin] = aw * 0.25f;
        }
    }
    __syncthreads();
    float* o = out + (size_t)roi * FDIM;
    for (int i = tid; i < FDIM; i += 256) o[i] = sout[i];
}

// ---------------- rescale head (only 4 of 98 outputs used) + new_rois -------
__global__ void rescale_newrois(const float* __restrict__ flat,
                                const float* __restrict__ rois,
                                const float* __restrict__ w,
                                const float* __restrict__ bias) {
    int roi = blockIdx.x;
    int tid = threadIdx.x;       // 256
    const float* f = flat + (size_t)roi * FDIM;
    float s0 = 0.f, s1 = 0.f, s2 = 0.f, s3 = 0.f;
    for (int k = tid; k < FDIM; k += 256) {
        float v = f[k];
        s0 += v * w[k];
        s1 += v * w[FDIM + k];
        s2 += v * w[2*FDIM + k];
        s3 += v * w[3*FDIM + k];
    }
    #pragma unroll
    for (int o = 16; o > 0; o >>= 1) {
        s0 += __shfl_down_sync(0xffffffffu, s0, o);
        s1 += __shfl_down_sync(0xffffffffu, s1, o);
        s2 += __shfl_down_sync(0xffffffffu, s2, o);
        s3 += __shfl_down_sync(0xffffffffu, s3, o);
    }
    __shared__ float red[4][8];
    int lane = tid & 31, warp = tid >> 5;
    if (lane == 0) { red[0][warp]=s0; red[1][warp]=s1; red[2][warp]=s2; red[3][warp]=s3; }
    __syncthreads();
    if (tid == 0) {
        float d[4];
        #pragma unroll
        for (int j = 0; j < 4; j++) {
            float t = 0.f;
            #pragma unroll
            for (int ww = 0; ww < 8; ww++) t += red[j][ww];
            d[j] = 1.0f + 0.5f / (1.0f + expf(-(t + bias[j])));
        }
        const float* r = rois + roi*5;
        float cx = (r[1] + r[3]) * 0.5f + d[0];
        float cy = (r[2] + r[4]) * 0.5f + d[1];
        float nw = (r[3] - r[1]) * d[2];
        float nh = (r[4] - r[2]) * d[3];
        float* nr = g_nrois + roi*5;
        nr[0] = r[0];
        nr[1] = cx - 0.5f*nw;  nr[2] = cy - 0.5f*nh;
        nr[3] = cx + 0.5f*nw;  nr[4] = cy + 0.5f*nh;
    }
}

// ---------------- tf32 tensor-core NT GEMM (fragment-major smem) ------------
// P[kz][M][N] partial = A[M, kz*K/S : ...] * B[N, ...]^T  (split-K = gridDim.z)
// BM=64, BN=128, BK=16, 256 threads (8 warps, 2x4 warp grid, 32x32 warp tile).
// Producer scatters A/B into MMA-fragment order so the consumer fetches each
// fragment with a single conflict-free LDS.128.

__device__ __forceinline__ uint32_t f2tf(float x) {
    uint32_t u;
    asm("cvt.rna.tf32.f32 %0, %1;" : "=r"(u) : "f"(x));
    return u;
}
__device__ __forceinline__ float4 tf4(float a, float b, float c, float d) {
    float4 v;
    v.x = __uint_as_float(f2tf(a)); v.y = __uint_as_float(f2tf(b));
    v.z = __uint_as_float(f2tf(c)); v.w = __uint_as_float(f2tf(d));
    return v;
}

__device__ __forceinline__ void mma_tf32(float* c, const float4& a, float b0, float b1) {
    asm volatile(
        "mma.sync.aligned.m16n8k8.row.col.f32.tf32.tf32.f32 "
        "{%0,%1,%2,%3}, {%4,%5,%6,%7}, {%8,%9}, {%0,%1,%2,%3};"
        : "+f"(c[0]), "+f"(c[1]), "+f"(c[2]), "+f"(c[3])
        : "r"(__float_as_uint(a.x)), "r"(__float_as_uint(a.y)),
          "r"(__float_as_uint(a.z)), "r"(__float_as_uint(a.w)),
          "r"(__float_as_uint(b0)),  "r"(__float_as_uint(b1)));
}

__global__ void __launch_bounds__(256, 2)
gemm_tf32(const float* __restrict__ A, const float* __restrict__ B,
          float* __restrict__ P, int N, int K) {
    const int BM = 64, BN = 128, BK = 16;
    // A frags: [buf][(kb*4 + t)*32 + lane], t = 16-row group (0..3)
    // B frags: [buf][((kb*4 + wn)*2 + p)*32 + lane]
    __shared__ float4 As4[2][256];
    __shared__ float4 Bs4[2][512];

    int tid  = threadIdx.x;
    int lane = tid & 31, w = tid >> 5;
    int g = lane >> 2, tig = lane & 3;
    int wm = w >> 2, wn = w & 3;
    int bm = blockIdx.y * BM, bn = blockIdx.x * BN;
    int S  = gridDim.z;
    int Kh = K / S;
    int kz = blockIdx.z;
    int M  = gridDim.y * BM;

    // ---- producer decode: A (one float4/stage), B (two float4s/stage)
    int pa_kb = tid >> 7;                // 0..1
    int pa_t  = (tid >> 5) & 3;          // 0..3
    const float* Ap0 = A + (size_t)(bm + pa_t*16 + g)*K + (size_t)kz*Kh + pa_kb*8 + tig;
    const float* Ap1 = Ap0 + (size_t)8*K;

    int pb_wn = (tid >> 6) & 3;
    int pb_p  = (tid >> 5) & 1;
    int bn0 = bn + pb_wn*32 + pb_p*16 + g;
    int bn1 = bn0 + 8;
    bool bv0 = bn0 < N, bv1 = bn1 < N;
    const float* Bp0 = B + (size_t)min(bn0, N-1)*K + (size_t)kz*Kh + tig;
    const float* Bp1 = B + (size_t)min(bn1, N-1)*K + (size_t)kz*Kh + tig;

    int a_sidx  = (pa_kb*4 + pa_t)*32 + lane;
    int b_sidx0 = ((0*4 + pb_wn)*2 + pb_p)*32 + lane;
    int b_sidx1 = ((1*4 + pb_wn)*2 + pb_p)*32 + lane;

    float acc[2][4][4];
    #pragma unroll
    for (int i = 0; i < 2; i++)
        #pragma unroll
        for (int j = 0; j < 4; j++)
            #pragma unroll
            for (int q = 0; q < 4; q++) acc[i][j][q] = 0.0f;

    const int nstage = Kh / BK;

    // prologue: stage 0
    {
        float a0 = Ap0[0], a1 = Ap1[0], a2 = Ap0[4], a3 = Ap1[4];
        float b00 = bv0 ? Bp0[0] : 0.f, b01 = bv0 ? Bp0[4]  : 0.f;
        float b02 = bv1 ? Bp1[0] : 0.f, b03 = bv1 ? Bp1[4]  : 0.f;
        float b10 = bv0 ? Bp0[8] : 0.f, b11 = bv0 ? Bp0[12] : 0.f;
        float b12 = bv1 ? Bp1[8] : 0.f, b13 = bv1 ? Bp1[12] : 0.f;
        As4[0][a_sidx]  = tf4(a0, a1, a2, a3);
        Bs4[0][b_sidx0] = tf4(b00, b01, b02, b03);
        Bs4[0][b_sidx1] = tf4(b10, b11, b12, b13);
    }
    __syncthreads();

    for (int s = 0; s < nstage; s++) {
        int buf = s & 1;
        float a0, a1, a2, a3, b00, b01, b02, b03, b10, b11, b12, b13;
        if (s + 1 < nstage) {
            int o = (s+1)*BK;
            a0 = Ap0[o];   a1 = Ap1[o];   a2 = Ap0[o+4];  a3 = Ap1[o+4];
            b00 = bv0 ? Bp0[o]    : 0.f;  b01 = bv0 ? Bp0[o+4]  : 0.f;
            b02 = bv1 ? Bp1[o]    : 0.f;  b03 = bv1 ? Bp1[o+4]  : 0.f;
            b10 = bv0 ? Bp0[o+8]  : 0.f;  b11 = bv0 ? Bp0[o+12] : 0.f;
            b12 = bv1 ? Bp1[o+8]  : 0.f;  b13 = bv1 ? Bp1[o+12] : 0.f;
        }
        #pragma unroll
        for (int kb = 0; kb < 2; kb++) {
            float4 af0 = As4[buf][(kb*4 + wm*2 + 0)*32 + lane];
            float4 af1 = As4[buf][(kb*4 + wm*2 + 1)*32 + lane];
            float4 bf0 = Bs4[buf][((kb*4 + wn)*2 + 0)*32 + lane];
            float4 bf1 = Bs4[buf][((kb*4 + wn)*2 + 1)*32 + lane];
            mma_tf32(acc[0][0], af0, bf0.x, bf0.y);
            mma_tf32(acc[0][1], af0, bf0.z, bf0.w);
            mma_tf32(acc[0][2], af0, bf1.x, bf1.y);
            mma_tf32(acc[0][3], af0, bf1.z, bf1.w);
            mma_tf32(acc[1][0], af1, bf0.x, bf0.y);
            mma_tf32(acc[1][1], af1, bf0.z, bf0.w);
            mma_tf32(acc[1][2], af1, bf1.x, bf1.y);
            mma_tf32(acc[1][3], af1, bf1.z, bf1.w);
        }
        if (s + 1 < nstage) {
            As4[buf^1][a_sidx]  = tf4(a0, a1, a2, a3);
            Bs4[buf^1][b_sidx0] = tf4(b00, b01, b02, b03);
            Bs4[buf^1][b_sidx1] = tf4(b10, b11, b12, b13);
        }
        __syncthreads();
    }

    // ---- epilogue: write fp32 partials
    float* Pp = P + (size_t)kz * M * N;
    #pragma unroll
    for (int ii = 0; ii < 2; ii++) {
        #pragma unroll
        for (int jj = 0; jj < 4; jj++) {
            int r0 = bm + wm*32 + ii*16 + g;
            int c0 = bn + wn*32 + jj*8 + tig*2;
            if (c0 < N) {
                Pp[(size_t)r0*N + c0]       = acc[ii][jj][0];
                Pp[(size_t)r0*N + c0 + 1]   = acc[ii][jj][1];
                Pp[(size_t)(r0+8)*N + c0]   = acc[ii][jj][2];
                Pp[(size_t)(r0+8)*N + c0+1] = acc[ii][jj][3];
            }
        }
    }
}

// ---------------- split-K combine: out = act(sum_s P_s + bias) --------------
template<bool RELU>
__global__ void combine(const float* __restrict__ P, const float* __restrict__ bias,
                        float* __restrict__ out, int M, int N) {
    int i = blockIdx.x * 256 + threadIdx.x;
    if (i >= M*N) return;
    int n = i % N;
    float v = bias[n];
    #pragma unroll
    for (int s = 0; s < SPLITK; s++) v += P[(size_t)s*M*N + i];
    if (RELU) v = fmaxf(v, 0.0f);
    out[i] = v;
}

// ---------------- launch -----------------------------------------------------
extern "C" void kernel_launch(void* const* d_in, const int* in_sizes, int n_in,
                              void* d_out, int out_size) {
    const float* input     = (const float*)d_in[0];
    const float* rois      = (const float*)d_in[1];
    const float* rescale_w = (const float*)d_in[2];
    const float* rescale_b = (const float*)d_in[3];
    const float* off_w1    = (const float*)d_in[4];
    const float* off_b1    = (const float*)d_in[5];
    const float* off_w2    = (const float*)d_in[6];
    const float* off_b2    = (const float*)d_in[7];
    const float* off_w3    = (const float*)d_in[8];
    const float* off_b3    = (const float*)d_in[9];

    float* xcls = (float*)d_out;
    float* xreg = xcls + (size_t)NROIS * FDIM;

    float *h1p, *h2p, *offp, *nroisp, *partp;
    cudaGetSymbolAddress((void**)&h1p,    g_h1);
    cudaGetSymbolAddress((void**)&h2p,    g_h2);
    cudaGetSymbolAddress((void**)&offp,   g_off);
    cudaGetSymbolAddress((void**)&nroisp, g_nrois);
    cudaGetSymbolAddress((void**)&partp,  g_part);

    const int smem_pool = FDIM * sizeof(float);
    cudaFuncSetAttribute(roi_pool<false>, cudaFuncAttributeMaxDynamicSharedMemorySize, smem_pool);
    cudaFuncSetAttribute(roi_pool<true>,  cudaFuncAttributeMaxDynamicSharedMemorySize, smem_pool);

    // 1) transpose to NHWC
    nchw2nhwc<<<dim3(HW/32, CH/32, BATCH), dim3(32, 8)>>>(input);
    // 2) x_cls pool -> first half of d_out (also serves as `flat`)
    roi_pool<false><<<NROIS, 256, smem_pool>>>(rois, nullptr, xcls);
    // 3) rescale head (exact fp32) + new_rois
    rescale_newrois<<<NROIS, 256>>>(xcls, rois, rescale_w, rescale_b);
    // 4) offset MLP on tf32 tensor cores (split-K x4 + combine)
    gemm_tf32<<<dim3(DFC/128, NROIS/64, SPLITK), 256>>>(xcls, off_w1, partp, DFC, FDIM);
    combine<true><<<(NROIS*DFC + 255)/256, 256>>>(partp, off_b1, h1p, NROIS, DFC);
    gemm_tf32<<<dim3(DFC/128, NROIS/64, SPLITK), 256>>>(h1p, off_w2, partp, DFC, DFC);
    combine<true><<<(NROIS*DFC + 255)/256, 256>>>(partp, off_b2, h2p, NROIS, DFC);
    gemm_tf32<<<dim3(1, NROIS/64, SPLITK), 256>>>(h2p, off_w3, partp, NOFF, DFC);
    combine<false><<<(NROIS*NOFF + 255)/256, 256>>>(partp, off_b3, offp, NROIS, NOFF);
    // 5) x_reg pool (new rois + offsets) -> second half of d_out
    roi_pool<true><<<NROIS, 256, smem_pool>>>(nroisp, offp, xreg);
}

// round 5
// speedup vs baseline: 3.4053x; 1.2306x over previous
#include <cuda_runtime.h>
#include <math.h>
#include <stdint.h>

#define BATCH 4
#define CH    256
#define FH    100
#define FW    152
#define HW    (FH*FW)          // 15200
#define NROIS 512
#define OH    7
#define OW    7
#define NBIN  49
#define FDIM  (CH*NBIN)        // 12544
#define DFC   1024
#define NOFF  98               // 2*49
#define SCALE 0.0625f
#define GAMMA 0.1f
#define SPLITK 8

// ---------------- scratch (device globals; no allocation allowed) -----------
__device__ float g_feat[(size_t)BATCH*HW*CH];   // NHWC features, 62.3 MB
__device__ float g_h1[NROIS*DFC];
__device__ float g_h2[NROIS*DFC];
__device__ float g_off[NROIS*NOFF];
__device__ float g_nrois[NROIS*5];
__device__ float g_part[SPLITK*(size_t)NROIS*DFC];   // split-K partials (16 MB)

// ---------------- NCHW -> NHWC transpose ------------------------------------
__global__ void nchw2nhwc(const float* __restrict__ in) {
    __shared__ float tile[32][33];
    int b   = blockIdx.z;
    int hw0 = blockIdx.x * 32;
    int c0  = blockIdx.y * 32;
    #pragma unroll
    for (int r = 0; r < 4; r++) {
        int c  = c0 + threadIdx.y + r*8;
        int hw = hw0 + threadIdx.x;
        tile[threadIdx.y + r*8][threadIdx.x] = in[((size_t)b*CH + c)*HW + hw];
    }
    __syncthreads();
    #pragma unroll
    for (int r = 0; r < 4; r++) {
        int hw = hw0 + threadIdx.y + r*8;
        int c  = c0 + threadIdx.x;
        g_feat[((size_t)b*HW + hw)*CH + c] = tile[threadIdx.x][threadIdx.y + r*8];
    }
}

// ---------------- deformable RoI pool (vectorized, R4 version) --------------
template<bool HAS_OFF>
__global__ void roi_pool(const float* __restrict__ rois,
                         const float* __restrict__ off,
                         float* __restrict__ out) {
    extern __shared__ float sout[];           // FDIM floats
    int roi = blockIdx.x;
    int tid = threadIdx.x;
    int bq = tid >> 6, cq = tid & 63;         // bin quadrant, channel/4 group
    const float* r = rois + roi*5;
    int   b  = (int)r[0];
    float x1 = r[1]*SCALE - 0.5f;
    float y1 = r[2]*SCALE - 0.5f;
    float x2 = r[3]*SCALE - 0.5f;
    float y2 = r[4]*SCALE - 0.5f;
    float rw = x2 - x1, rh = y2 - y1;
    float bw = rw * (1.0f/OW), bh = rh * (1.0f/OH);
    const float4* fb4 = (const float4*)(g_feat + (size_t)b*HW*CH);

    for (int b0 = 0; b0 < NBIN; b0 += 4) {
        int bin = b0 + bq;
        if (bin < NBIN) {
            int ph = bin / OW, pw = bin - ph*OW;
            float sw_ = x1, sh_ = y1;
            if (HAS_OFF) {
                sw_ += GAMMA * rw * off[roi*NOFF + bin];
                sh_ += GAMMA * rh * off[roi*NOFF + NBIN + bin];
            }
            float ax = 0.f, ay = 0.f, az = 0.f, aw = 0.f;
            #pragma unroll
            for (int iy = 0; iy < 2; iy++) {
                float y = sh_ + ((float)ph + ((float)iy + 0.5f)*0.5f) * bh;
                #pragma unroll
                for (int ix = 0; ix < 2; ix++) {
                    float x = sw_ + ((float)pw + ((float)ix + 0.5f)*0.5f) * bw;
                    if (y > -1.0f && y < (float)FH && x > -1.0f && x < (float)FW) {
                        float yc = fminf(fmaxf(y, 0.0f), (float)(FH-1));
                        float xc = fminf(fmaxf(x, 0.0f), (float)(FW-1));
                        int y0 = min((int)floorf(yc), FH-2);
                        int x0 = min((int)floorf(xc), FW-2);
                        float ly = yc - (float)y0, lx = xc - (float)x0;
                        float hy = 1.0f - ly,     hx = 1.0f - lx;
                        float w00 = hy*hx, w01 = hy*lx, w10 = ly*hx, w11 = ly*lx;
                        const float4* p = fb4 + ((size_t)y0*FW + x0)*(CH/4) + cq;
                        float4 v00 = p[0];
                        float4 v01 = p[CH/4];
                        float4 v10 = p[FW*CH/4];
                        float4 v11 = p[FW*CH/4 + CH/4];
                        ax += w00*v00.x + w01*v01.x + w10*v10.x + w11*v11.x;
                        ay += w00*v00.y + w01*v01.y + w10*v10.y + w11*v11.y;
                        az += w00*v00.z + w01*v01.z + w10*v10.z + w11*v11.z;
                        aw += w00*v00.w + w01*v01.w + w10*v10.w + w11*v11.w;
                    }
                }
            }
            int c = cq*4;
            sout[(c+0)*NBIN + bin] = ax * 0.25f;
            sout[(c+1)*NBIN + bin] = ay * 0.25f;
            sout[(c+2)*NBIN + bin] = az * 0.25f;
            sout[(c+3)*NBIN + bin] = aw * 0.25f;
        }
    }
    __syncthreads();
    float* o = out + (size_t)roi * FDIM;
    for (int i = tid; i < FDIM; i += 256) o[i] = sout[i];
}

// ---------------- rescale head (only 4 of 98 outputs used) + new_rois -------
__global__ void rescale_newrois(const float* __restrict__ flat,
                                const float* __restrict__ rois,
                                const float* __restrict__ w,
                                const float* __restrict__ bias) {
    int roi = blockIdx.x;
    int tid = threadIdx.x;       // 256
    const float* f = flat + (size_t)roi * FDIM;
    float s0 = 0.f, s1 = 0.f, s2 = 0.f, s3 = 0.f;
    for (int k = tid; k < FDIM; k += 256) {
        float v = f[k];
        s0 += v * w[k];
        s1 += v * w[FDIM + k];
        s2 += v * w[2*FDIM + k];
        s3 += v * w[3*FDIM + k];
    }
    #pragma unroll
    for (int o = 16; o > 0; o >>= 1) {
        s0 += __shfl_down_sync(0xffffffffu, s0, o);
        s1 += __shfl_down_sync(0xffffffffu, s1, o);
        s2 += __shfl_down_sync(0xffffffffu, s2, o);
        s3 += __shfl_down_sync(0xffffffffu, s3, o);
    }
    __shared__ float red[4][8];
    int lane = tid & 31, warp = tid >> 5;
    if (lane == 0) { red[0][warp]=s0; red[1][warp]=s1; red[2][warp]=s2; red[3][warp]=s3; }
    __syncthreads();
    if (tid == 0) {
        float d[4];
        #pragma unroll
        for (int j = 0; j < 4; j++) {
            float t = 0.f;
            #pragma unroll
            for (int ww = 0; ww < 8; ww++) t += red[j][ww];
            d[j] = 1.0f + 0.5f / (1.0f + expf(-(t + bias[j])));
        }
        const float* r = rois + roi*5;
        float cx = (r[1] + r[3]) * 0.5f + d[0];
        float cy = (r[2] + r[4]) * 0.5f + d[1];
        float nw = (r[3] - r[1]) * d[2];
        float nh = (r[4] - r[2]) * d[3];
        float* nr = g_nrois + roi*5;
        nr[0] = r[0];
        nr[1] = cx - 0.5f*nw;  nr[2] = cy - 0.5f*nh;
        nr[3] = cx + 0.5f*nw;  nr[4] = cy + 0.5f*nh;
    }
}

// ---------------- tf32 tensor-core NT GEMM (R3 core: swizzled smem) ---------
// P[kz][M][N] partial = A[M, kz*K/S : ...] * B[N, ...]^T  (split-K = gridDim.z)
// BM=64, BN=128, BK=16, 256 threads (8 warps, 2x4 warp grid, 32x32 warp tile).
// XOR-swizzled smem: idx(k,m) = k*W + (m ^ ((((k&3)^((k>>2)&3)))<<3))
// -> conflict-free for both the float4 store pattern and the mma-fragment loads.

__device__ __forceinline__ uint32_t f2tf(float x) {
    uint32_t u;
    asm("cvt.rna.tf32.f32 %0, %1;" : "=r"(u) : "f"(x));
    return u;
}

__device__ __forceinline__ void mma_tf32(float* c, const uint32_t* a, const uint32_t* b) {
    asm volatile(
        "mma.sync.aligned.m16n8k8.row.col.f32.tf32.tf32.f32 "
        "{%0,%1,%2,%3}, {%4,%5,%6,%7}, {%8,%9}, {%0,%1,%2,%3};"
        : "+f"(c[0]), "+f"(c[1]), "+f"(c[2]), "+f"(c[3])
        : "r"(a[0]), "r"(a[1]), "r"(a[2]), "r"(a[3]), "r"(b[0]), "r"(b[1]));
}

__global__ void __launch_bounds__(256, 2)
gemm_tf32(const float* __restrict__ A, const float* __restrict__ B,
          float* __restrict__ P, int N, int K) {
    const int BM = 64, BN = 128, BK = 16;
    __shared__ uint32_t As[2][BK*BM];
    __shared__ uint32_t Bs[2][BK*BN];

    int tid  = threadIdx.x;
    int lane = tid & 31, w = tid >> 5;
    int g = lane >> 2, tig = lane & 3;
    int wm = w >> 2, wn = w & 3;
    int bm = blockIdx.y * BM, bn = blockIdx.x * BN;
    int S  = gridDim.z;
    int Kh = K / S;
    int kz = blockIdx.z;
    int M  = gridDim.y * BM;

    // ---- loader setup: each thread loads one float4 of A, two of B per stage
    int lm = tid >> 2, lq = tid & 3;
    const float* Ap  = A + (size_t)(bm + lm)*K + (size_t)kz*Kh + lq*4;
    int brow0 = bn + lm, brow1 = bn + lm + 64;
    bool bv0 = brow0 < N, bv1 = brow1 < N;
    const float* Bp0 = B + (size_t)min(brow0, N-1)*K + (size_t)kz*Kh + lq*4;
    const float* Bp1 = B + (size_t)min(brow1, N-1)*K + (size_t)kz*Kh + lq*4;

    int sa[4], sb[4];
    #pragma unroll
    for (int e = 0; e < 4; e++) {
        int k  = lq*4 + e;
        int sw = (((k & 3) ^ ((k >> 2) & 3)) << 3);
        sa[e] = k*BM + (lm ^ sw);
        sb[e] = k*BN + (lm ^ sw);   // row lm+64 -> sb[e]+64 (bit6 untouched by sw)
    }

    float acc[2][4][4];
    #pragma unroll
    for (int i = 0; i < 2; i++)
        #pragma unroll
        for (int j = 0; j < 4; j++)
            #pragma unroll
            for (int q = 0; q < 4; q++) acc[i][j][q] = 0.0f;

    const int nstage = Kh / BK;
    float4 fa  = *(const float4*)Ap;
    float4 fb0 = bv0 ? *(const float4*)Bp0 : make_float4(0,0,0,0);
    float4 fb1 = bv1 ? *(const float4*)Bp1 : make_float4(0,0,0,0);
    {
        uint32_t* as = As[0]; uint32_t* bs = Bs[0];
        as[sa[0]] = f2tf(fa.x);  as[sa[1]] = f2tf(fa.y);
        as[sa[2]] = f2tf(fa.z);  as[sa[3]] = f2tf(fa.w);
        bs[sb[0]] = f2tf(fb0.x); bs[sb[1]] = f2tf(fb0.y);
        bs[sb[2]] = f2tf(fb0.z); bs[sb[3]] = f2tf(fb0.w);
        bs[sb[0]+64] = f2tf(fb1.x); bs[sb[1]+64] = f2tf(fb1.y);
        bs[sb[2]+64] = f2tf(fb1.z); bs[sb[3]+64] = f2tf(fb1.w);
    }
    __syncthreads();

    for (int s = 0; s < nstage; s++) {
        int buf = s & 1;
        if (s + 1 < nstage) {
            fa  = *(const float4*)(Ap  + (size_t)(s+1)*BK);
            fb0 = bv0 ? *(const float4*)(Bp0 + (size_t)(s+1)*BK) : make_float4(0,0,0,0);
            fb1 = bv1 ? *(const float4*)(Bp1 + (size_t)(s+1)*BK) : make_float4(0,0,0,0);
        }
        const uint32_t* as = As[buf];
        const uint32_t* bs = Bs[buf];
        #pragma unroll
        for (int kb = 0; kb < 2; kb++) {
            uint32_t af[2][4], bf[4][2];
            #pragma unroll
            for (int h = 0; h < 2; h++) {
                int k  = kb*8 + tig + h*4;
                int sw = (((k & 3) ^ ((k >> 2) & 3)) << 3);
                int ka = k*BM, kb2 = k*BN;
                #pragma unroll
                for (int ii = 0; ii < 2; ii++) {
                    int m0 = wm*32 + ii*16 + g;
                    af[ii][h*2+0] = as[ka + ( m0      ^ sw)];
                    af[ii][h*2+1] = as[ka + ((m0 + 8) ^ sw)];
                }
                #pragma unroll
                for (int jj = 0; jj < 4; jj++) {
                    int n0 = wn*32 + jj*8 + g;
                    bf[jj][h] = bs[kb2 + (n0 ^ sw)];
                }
            }
            #pragma unroll
            for (int ii = 0; ii < 2; ii++)
                #pragma unroll
                for (int jj = 0; jj < 4; jj++)
                    mma_tf32(acc[ii][jj], af[ii], bf[jj]);
        }
        if (s + 1 < nstage) {
            uint32_t* asn = As[buf ^ 1]; uint32_t* bsn = Bs[buf ^ 1];
            asn[sa[0]] = f2tf(fa.x);  asn[sa[1]] = f2tf(fa.y);
            asn[sa[2]] = f2tf(fa.z);  asn[sa[3]] = f2tf(fa.w);
            bsn[sb[0]] = f2tf(fb0.x); bsn[sb[1]] = f2tf(fb0.y);
            bsn[sb[2]] = f2tf(fb0.z); bsn[sb[3]] = f2tf(fb0.w);
            bsn[sb[0]+64] = f2tf(fb1.x); bsn[sb[1]+64] = f2tf(fb1.y);
            bsn[sb[2]+64] = f2tf(fb1.z); bsn[sb[3]+64] = f2tf(fb1.w);
        }
        __syncthreads();
    }

    // ---- epilogue: write fp32 partials
    float* Pp = P + (size_t)kz * M * N;
    #pragma unroll
    for (int ii = 0; ii < 2; ii++) {
        #pragma unroll
        for (int jj = 0; jj < 4; jj++) {
            int r0 = bm + wm*32 + ii*16 + g;
            int c0 = bn + wn*32 + jj*8 + tig*2;
            if (c0 < N) {
                Pp[(size_t)r0*N + c0]       = acc[ii][jj][0];
                Pp[(size_t)r0*N + c0 + 1]   = acc[ii][jj][1];
                Pp[(size_t)(r0+8)*N + c0]   = acc[ii][jj][2];
                Pp[(size_t)(r0+8)*N + c0+1] = acc[ii][jj][3];
            }
        }
    }
}

// ---------------- split-K combine: out = act(sum_s P_s + bias) --------------
template<bool RELU>
__global__ void combine(const float* __restrict__ P, const float* __restrict__ bias,
                        float* __restrict__ out, int M, int N) {
    int i = blockIdx.x * 256 + threadIdx.x;
    if (i >= M*N) return;
    int n = i % N;
    float v = bias[n];
    #pragma unroll
    for (int s = 0; s < SPLITK; s++) v += P[(size_t)s*M*N + i];
    if (RELU) v = fmaxf(v, 0.0f);
    out[i] = v;
}

// ---------------- launch -----------------------------------------------------
extern "C" void kernel_launch(void* const* d_in, const int* in_sizes, int n_in,
                              void* d_out, int out_size) {
    const float* input     = (const float*)d_in[0];
    const float* rois      = (const float*)d_in[1];
    const float* rescale_w = (const float*)d_in[2];
    const float* rescale_b = (const float*)d_in[3];
    const float* off_w1    = (const float*)d_in[4];
    const float* off_b1    = (const float*)d_in[5];
    const float* off_w2    = (const float*)d_in[6];
    const float* off_b2    = (const float*)d_in[7];
    const float* off_w3    = (const float*)d_in[8];
    const float* off_b3    = (const float*)d_in[9];

    float* xcls = (float*)d_out;
    float* xreg = xcls + (size_t)NROIS * FDIM;

    float *h1p, *h2p, *offp, *nroisp, *partp;
    cudaGetSymbolAddress((void**)&h1p,    g_h1);
    cudaGetSymbolAddress((void**)&h2p,    g_h2);
    cudaGetSymbolAddress((void**)&offp,   g_off);
    cudaGetSymbolAddress((void**)&nroisp, g_nrois);
    cudaGetSymbolAddress((void**)&partp,  g_part);

    const int smem_pool = FDIM * sizeof(float);
    cudaFuncSetAttribute(roi_pool<false>, cudaFuncAttributeMaxDynamicSharedMemorySize, smem_pool);
    cudaFuncSetAttribute(roi_pool<true>,  cudaFuncAttributeMaxDynamicSharedMemorySize, smem_pool);

    // 1) transpose to NHWC
    nchw2nhwc<<<dim3(HW/32, CH/32, BATCH), dim3(32, 8)>>>(input);
    // 2) x_cls pool -> first half of d_out (also serves as `flat`)
    roi_pool<false><<<NROIS, 256, smem_pool>>>(rois, nullptr, xcls);
    // 3) rescale head (exact fp32) + new_rois
    rescale_newrois<<<NROIS, 256>>>(xcls, rois, rescale_w, rescale_b);
    // 4) offset MLP on tf32 tensor cores (split-K x8 + combine)
    gemm_tf32<<<dim3(DFC/128, NROIS/64, SPLITK), 256>>>(xcls, off_w1, partp, DFC, FDIM);
    combine<true><<<(NROIS*DFC + 255)/256, 256>>>(partp, off_b1, h1p, NROIS, DFC);
    gemm_tf32<<<dim3(DFC/128, NROIS/64, SPLITK), 256>>>(h1p, off_w2, partp, DFC, DFC);
    combine<true><<<(NROIS*DFC + 255)/256, 256>>>(partp, off_b2, h2p, NROIS, DFC);
    gemm_tf32<<<dim3(1, NROIS/64, SPLITK), 256>>>(h2p, off_w3, partp, NOFF, DFC);
    combine<false><<<(NROIS*NOFF + 255)/256, 256>>>(partp, off_b3, offp, NROIS, NOFF);
    // 5) x_reg pool (new rois + offsets) -> second half of d_out
    roi_pool<true><<<NROIS, 256, smem_pool>>>(nroisp, offp, xreg);
}

// round 7
// speedup vs baseline: 4.2835x; 1.2579x over previous
#include <cuda_runtime.h>
#include <cuda_fp16.h>
#include <math.h>
#include <stdint.h>

#define BATCH 4
#define CH    256
#define FH    100
#define FW    152
#define HW    (FH*FW)          // 15200
#define NROIS 512
#define OH    7
#define OW    7
#define NBIN  49
#define FDIM  (CH*NBIN)        // 12544
#define DFC   1024
#define NOFF  98               // 2*49
#define NOFFP 128              // padded for GEMM3
#define SCALE 0.0625f
#define GAMMA 0.1f
#define SKMAX 8

// ---------------- scratch (device globals; no allocation allowed) -----------
__device__ float  g_feat[(size_t)BATCH*HW*CH];   // NHWC features, 62.3 MB
__device__ __half g_a1h[(size_t)NROIS*FDIM];     // half(xcls) 12.8 MB
__device__ __half g_w1h[(size_t)DFC*FDIM];       // half(w1) 25.7 MB
__device__ __half g_w2h[(size_t)DFC*DFC];        // half(w2) 2 MB
__device__ __half g_w3h[(size_t)NOFFP*DFC];      // half(w3), zero-padded rows
__device__ __half g_h1h[NROIS*DFC];
__device__ __half g_h2h[NROIS*DFC];
__device__ float  g_off[NROIS*NOFF];
__device__ float  g_nrois[NROIS*5];
__device__ float  g_part[(size_t)SKMAX*NROIS*DFC]; // split-K partials (16 MB)

// ---------------- NCHW -> NHWC transpose ------------------------------------
__global__ void nchw2nhwc(const float* __restrict__ in) {
    __shared__ float tile[32][33];
    int b   = blockIdx.z;
    int hw0 = blockIdx.x * 32;
    int c0  = blockIdx.y * 32;
    #pragma unroll
    for (int r = 0; r < 4; r++) {
        int c  = c0 + threadIdx.y + r*8;
        int hw = hw0 + threadIdx.x;
        tile[threadIdx.y + r*8][threadIdx.x] = in[((size_t)b*CH + c)*HW + hw];
    }
    __syncthreads();
    #pragma unroll
    for (int r = 0; r < 4; r++) {
        int hw = hw0 + threadIdx.y + r*8;
        int c  = c0 + threadIdx.x;
        g_feat[((size_t)b*HW + hw)*CH + c] = tile[threadIdx.x][threadIdx.y + r*8];
    }
}

// ---------------- fp32 -> fp16 conversions ----------------------------------
__device__ __forceinline__ uint32_t h2u(__half2 h) { return *reinterpret_cast<uint32_t*>(&h); }

__global__ void cvt_f2h(const float4* __restrict__ src, uint4* __restrict__ dst, int n8) {
    int i = blockIdx.x * 256 + threadIdx.x;
    if (i >= n8) return;
    float4 a = src[2*i], b = src[2*i + 1];
    uint4 o;
    o.x = h2u(__floats2half2_rn(a.x, a.y));
    o.y = h2u(__floats2half2_rn(a.z, a.w));
    o.z = h2u(__floats2half2_rn(b.x, b.y));
    o.w = h2u(__floats2half2_rn(b.z, b.w));
    dst[i] = o;
}
__global__ void cvt_w3h(const float* __restrict__ w3) {   // NOFFP*DFC/8 threads
    int i = blockIdx.x * 256 + threadIdx.x;
    if (i >= NOFFP*DFC/8) return;
    int base = i*8, r = base >> 10;
    uint4 o;
    if (r < NOFF) {
        const float4* s = (const float4*)(w3 + base);
        float4 a = s[0], b = s[1];
        o.x = h2u(__floats2half2_rn(a.x, a.y));
        o.y = h2u(__floats2half2_rn(a.z, a.w));
        o.z = h2u(__floats2half2_rn(b.x, b.y));
        o.w = h2u(__floats2half2_rn(b.z, b.w));
    } else {
        o.x = o.y = o.z = o.w = 0u;
    }
    ((uint4*)g_w3h)[i] = o;
}

// ---------------- deformable RoI pool (vectorized) --------------------------
template<bool HAS_OFF, bool EMIT_HALF>
__global__ void roi_pool(const float* __restrict__ rois,
                         const float* __restrict__ off,
                         float* __restrict__ out,
                         __half* __restrict__ out_h) {
    extern __shared__ float sout[];           // FDIM floats
    int roi = blockIdx.x;
    int tid = threadIdx.x;
    int bq = tid >> 6, cq = tid & 63;
    const float* r = rois + roi*5;
    int   b  = (int)r[0];
    float x1 = r[1]*SCALE - 0.5f;
    float y1 = r[2]*SCALE - 0.5f;
    float x2 = r[3]*SCALE - 0.5f;
    float y2 = r[4]*SCALE - 0.5f;
    float rw = x2 - x1, rh = y2 - y1;
    float bw = rw * (1.0f/OW), bh = rh * (1.0f/OH);
    const float4* fb4 = (const float4*)(g_feat + (size_t)b*HW*CH);

    for (int b0 = 0; b0 < NBIN; b0 += 4) {
        int bin = b0 + bq;
        if (bin < NBIN) {
            int ph = bin / OW, pw = bin - ph*OW;
            float sw_ = x1, sh_ = y1;
            if (HAS_OFF) {
                sw_ += GAMMA * rw * off[roi*NOFF + bin];
                sh_ += GAMMA * rh * off[roi*NOFF + NBIN + bin];
            }
            float ax = 0.f, ay = 0.f, az = 0.f, aw = 0.f;
            #pragma unroll
            for (int iy = 0; iy < 2; iy++) {
                float y = sh_ + ((float)ph + ((float)iy + 0.5f)*0.5f) * bh;
                #pragma unroll
                for (int ix = 0; ix < 2; ix++) {
                    float x = sw_ + ((float)pw + ((float)ix + 0.5f)*0.5f) * bw;
                    if (y > -1.0f && y < (float)FH && x > -1.0f && x < (float)FW) {
                        float yc = fminf(fmaxf(y, 0.0f), (float)(FH-1));
                        float xc = fminf(fmaxf(x, 0.0f), (float)(FW-1));
                        int y0 = min((int)floorf(yc), FH-2);
                        int x0 = min((int)floorf(xc), FW-2);
                        float ly = yc - (float)y0, lx = xc - (float)x0;
                        float hy = 1.0f - ly,     hx = 1.0f - lx;
                        float w00 = hy*hx, w01 = hy*lx, w10 = ly*hx, w11 = ly*lx;
                        const float4* p = fb4 + ((size_t)y0*FW + x0)*(CH/4) + cq;
                        float4 v00 = p[0];
                        float4 v01 = p[CH/4];
                        float4 v10 = p[FW*CH/4];
                        float4 v11 = p[FW*CH/4 + CH/4];
                        ax += w00*v00.x + w01*v01.x + w10*v10.x + w11*v11.x;
                        ay += w00*v00.y + w01*v01.y + w10*v10.y + w11*v11.y;
                        az += w00*v00.z + w01*v01.z + w10*v10.z + w11*v11.z;
                        aw += w00*v00.w + w01*v01.w + w10*v10.w + w11*v11.w;
                    }
                }
            }
            int c = cq*4;
            sout[(c+0)*NBIN + bin] = ax * 0.25f;
            sout[(c+1)*NBIN + bin] = ay * 0.25f;
            sout[(c+2)*NBIN + bin] = az * 0.25f;
            sout[(c+3)*NBIN + bin] = aw * 0.25f;
        }
    }
    __syncthreads();
    float* o = out + (size_t)roi * FDIM;
    if (EMIT_HALF) {
        __half* oh = out_h + (size_t)roi * FDIM;
        for (int i = tid; i < FDIM; i += 256) {
            float v = sout[i];
            o[i] = v;
            oh[i] = __float2half_rn(v);
        }
    } else {
        for (int i = tid; i < FDIM; i += 256) o[i] = sout[i];
    }
}

// ---------------- rescale head (only 4 of 98 outputs used) + new_rois -------
__global__ void rescale_newrois(const float* __restrict__ flat,
                                const float* __restrict__ rois,
                                const float* __restrict__ w,
                                const float* __restrict__ bias) {
    int roi = blockIdx.x;
    int tid = threadIdx.x;       // 256
    const float* f = flat + (size_t)roi * FDIM;
    float s0 = 0.f, s1 = 0.f, s2 = 0.f, s3 = 0.f;
    for (int k = tid; k < FDIM; k += 256) {
        float v = f[k];
        s0 += v * w[k];
        s1 += v * w[FDIM + k];
        s2 += v * w[2*FDIM + k];
        s3 += v * w[3*FDIM + k];
    }
    #pragma unroll
    for (int o = 16; o > 0; o >>= 1) {
        s0 += __shfl_down_sync(0xffffffffu, s0, o);
        s1 += __shfl_down_sync(0xffffffffu, s1, o);
        s2 += __shfl_down_sync(0xffffffffu, s2, o);
        s3 += __shfl_down_sync(0xffffffffu, s3, o);
    }
    __shared__ float red[4][8];
    int lane = tid & 31, warp = tid >> 5;
    if (lane == 0) { red[0][warp]=s0; red[1][warp]=s1; red[2][warp]=s2; red[3][warp]=s3; }
    __syncthreads();
    if (tid == 0) {
        float d[4];
        #pragma unroll
        for (int j = 0; j < 4; j++) {
            float t = 0.f;
            #pragma unroll
            for (int ww = 0; ww < 8; ww++) t += red[j][ww];
            d[j] = 1.0f + 0.5f / (1.0f + expf(-(t + bias[j])));
        }
        const float* r = rois + roi*5;
        float cx = (r[1] + r[3]) * 0.5f + d[0];
        float cy = (r[2] + r[4]) * 0.5f + d[1];
        float nw = (r[3] - r[1]) * d[2];
        float nh = (r[4] - r[2]) * d[3];
        float* nr = g_nrois + roi*5;
        nr[0] = r[0];
        nr[1] = cx - 0.5f*nw;  nr[2] = cy - 0.5f*nh;
        nr[3] = cx + 0.5f*nw;  nr[4] = cy + 0.5f*nh;
    }
}

// ---------------- fp16 tensor-core NT GEMM ----------------------------------
// P[kz][M][N] partial = A[M,Ks] * B[N,Ks]^T (split-K = gridDim.z), N mult of 128.
// BM=64, BN=128, BK=32 halves, 256 threads (8 warps, 2x4 grid, 32x32 warp tiles).
// smem word layout: word(m, kw) at m*16 + (kw ^ (((m>>1)&3)<<2))
//  -> conflict-free for STS.128 producer stores AND all LDS.32 fragment loads.

__device__ __forceinline__ void mma_f16(float* c, uint32_t a0, uint32_t a1,
                                        uint32_t a2, uint32_t a3,
                                        uint32_t b0, uint32_t b1) {
    asm volatile(
        "mma.sync.aligned.m16n8k16.row.col.f32.f16.f16.f32 "
        "{%0,%1,%2,%3}, {%4,%5,%6,%7}, {%8,%9}, {%0,%1,%2,%3};"
        : "+f"(c[0]), "+f"(c[1]), "+f"(c[2]), "+f"(c[3])
        : "r"(a0), "r"(a1), "r"(a2), "r"(a3), "r"(b0), "r"(b1));
}

__global__ void __launch_bounds__(256, 2)
gemm_h(const __half* __restrict__ A, const __half* __restrict__ B,
       float* __restrict__ P, int N, int K) {
    const int BM = 64, BN = 128;
    __shared__ __align__(16) uint32_t As[2][BM*16];
    __shared__ __align__(16) uint32_t Bs[2][BN*16];

    int tid  = threadIdx.x;
    int lane = tid & 31, w = tid >> 5;
    int g = lane >> 2, tig = lane & 3;
    int wm = w >> 2, wn = w & 3;
    int bm = blockIdx.y * BM, bn = blockIdx.x * BN;
    int S  = gridDim.z, kz = blockIdx.z;
    int Ks = K / S;
    int M  = gridDim.y * BM;
    int nst = Ks >> 5;

    // producer: 1 uint4 of A (8 halves), 2 of B per stage
    int lm = tid >> 2, lq = tid & 3;
    const __half* Ap  = A + (size_t)(bm + lm)*K + (size_t)kz*Ks + lq*8;
    const __half* Bp0 = B + (size_t)(bn + lm)*K + (size_t)kz*Ks + lq*8;
    const __half* Bp1 = Bp0 + (size_t)64*K;
    int sc   = lq ^ ((lm >> 1) & 3);
    int sa_w  = lm*16 + sc*4;
    int sb_w0 = lm*16 + sc*4;
    int sb_w1 = (lm + 64)*16 + sc*4;

    float acc[2][4][4];
    #pragma unroll
    for (int i = 0; i < 2; i++)
        #pragma unroll
        for (int j = 0; j < 4; j++)
            #pragma unroll
            for (int q = 0; q < 4; q++) acc[i][j][q] = 0.0f;

    // consumer index prep: same XOR nibble for rows m and m+8 ((m>>1)+4 ≡ mod 4)
    int mrow[2], mj[2];
    #pragma unroll
    for (int ii = 0; ii < 2; ii++) {
        mrow[ii] = wm*32 + ii*16 + g;
        mj[ii] = ((mrow[ii] >> 1) & 3) << 2;
    }
    int nrow[4], nj[4];
    #pragma unroll
    for (int jj = 0; jj < 4; jj++) {
        nrow[jj] = wn*32 + jj*8 + g;
        nj[jj] = ((nrow[jj] >> 1) & 3) << 2;
    }

    uint4 va  = *(const uint4*)Ap;
    uint4 vb0 = *(const uint4*)Bp0;
    uint4 vb1 = *(const uint4*)Bp1;
    *(uint4*)&As[0][sa_w]  = va;
    *(uint4*)&Bs[0][sb_w0] = vb0;
    *(uint4*)&Bs[0][sb_w1] = vb1;
    __syncthreads();

    for (int s = 0; s < nst; s++) {
        int buf = s & 1;
        if (s + 1 < nst) {
            size_t o = (size_t)(s+1)*32;
            va  = *(const uint4*)(Ap  + o);
            vb0 = *(const uint4*)(Bp0 + o);
            vb1 = *(const uint4*)(Bp1 + o);
        }
        const uint32_t* as = As[buf];
        const uint32_t* bs = Bs[buf];
        #pragma unroll
        for (int kb = 0; kb < 2; kb++) {
            int kw0 = kb*8 + tig, kw1 = kw0 + 4;
            uint32_t af[2][4], bf[4][2];
            #pragma unroll
            for (int ii = 0; ii < 2; ii++) {
                int r0 = mrow[ii]*16, r1 = (mrow[ii]+8)*16, x = mj[ii];
                af[ii][0] = as[r0 + (kw0 ^ x)];
                af[ii][1] = as[r1 + (kw0 ^ x)];
                af[ii][2] = as[r0 + (kw1 ^ x)];
                af[ii][3] = as[r1 + (kw1 ^ x)];
            }
            #pragma unroll
            for (int jj = 0; jj < 4; jj++) {
                int rn = nrow[jj]*16, x = nj[jj];
                bf[jj][0] = bs[rn + (kw0 ^ x)];
                bf[jj][1] = bs[rn + (kw1 ^ x)];
            }
            #pragma unroll
            for (int ii = 0; ii < 2; ii++)
                #pragma unroll
                for (int jj = 0; jj < 4; jj++)
                    mma_f16(acc[ii][jj], af[ii][0], af[ii][1], af[ii][2], af[ii][3],
                            bf[jj][0], bf[jj][1]);
        }
        if (s + 1 < nst) {
            *(uint4*)&As[buf^1][sa_w]  = va;
            *(uint4*)&Bs[buf^1][sb_w0] = vb0;
            *(uint4*)&Bs[buf^1][sb_w1] = vb1;
        }
        __syncthreads();
    }

    float* Pp = P + (size_t)kz * M * N;
    #pragma unroll
    for (int ii = 0; ii < 2; ii++) {
        #pragma unroll
        for (int jj = 0; jj < 4; jj++) {
            int r0 = bm + wm*32 + ii*16 + g;
            int c0 = bn + wn*32 + jj*8 + tig*2;
            Pp[(size_t)r0*N + c0]       = acc[ii][jj][0];
            Pp[(size_t)r0*N + c0 + 1]   = acc[ii][jj][1];
            Pp[(size_t)(r0+8)*N + c0]   = acc[ii][jj][2];
            Pp[(size_t)(r0+8)*N + c0+1] = acc[ii][jj][3];
        }
    }
}

// -------- split-K combine: act(sum_s P_s + bias); half or float out ---------
template<bool RELU, bool TOHALF>
__global__ void combine(const float* __restrict__ P, const float* __restrict__ bias,
                        float* __restrict__ outf, __half* __restrict__ outh,
                        int M, int Ntot, int Nlog, int S) {
    int i = blockIdx.x * 256 + threadIdx.x;
    if (i >= M*Nlog) return;
    int m = i / Nlog, n = i - m*Nlog;
    float v = bias[n];
    for (int s = 0; s < S; s++)
        v += P[((size_t)s*M + m)*Ntot + n];
    if (RELU) v = fmaxf(v, 0.0f);
    if (TOHALF) outh[i] = __float2half_rn(v);
    else        outf[i] = v;
}

// ---------------- launch -----------------------------------------------------
extern "C" void kernel_launch(void* const* d_in, const int* in_sizes, int n_in,
                              void* d_out, int out_size) {
    const float* input     = (const float*)d_in[0];
    const float* rois      = (const float*)d_in[1];
    const float* rescale_w = (const float*)d_in[2];
    const float* rescale_b = (const float*)d_in[3];
    const float* off_w1    = (const float*)d_in[4];
    const float* off_b1    = (const float*)d_in[5];
    const float* off_w2    = (const float*)d_in[6];
    const float* off_b2    = (const float*)d_in[7];
    const float* off_w3    = (const float*)d_in[8];
    const float* off_b3    = (const float*)d_in[9];

    float* xcls = (float*)d_out;
    float* xreg = xcls + (size_t)NROIS * FDIM;

    __half *a1p, *w1p, *w2p, *w3p, *h1p, *h2p;
    float *offp, *nroisp, *partp;
    cudaGetSymbolAddress((void**)&a1p,    g_a1h);
    cudaGetSymbolAddress((void**)&w1p,    g_w1h);
    cudaGetSymbolAddress((void**)&w2p,    g_w2h);
    cudaGetSymbolAddress((void**)&w3p,    g_w3h);
    cudaGetSymbolAddress((void**)&h1p,    g_h1h);
    cudaGetSymbolAddress((void**)&h2p,    g_h2h);
    cudaGetSymbolAddress((void**)&offp,   g_off);
    cudaGetSymbolAddress((void**)&nroisp, g_nrois);
    cudaGetSymbolAddress((void**)&partp,  g_part);

    const int smem_pool = FDIM * sizeof(float);
    cudaFuncSetAttribute((const void*)roi_pool<false,true>,
                         cudaFuncAttributeMaxDynamicSharedMemorySize, smem_pool);
    cudaFuncSetAttribute((const void*)roi_pool<true,false>,
                         cudaFuncAttributeMaxDynamicSharedMemorySize, smem_pool);

    // 1) transpose to NHWC + weight half-conversions
    nchw2nhwc<<<dim3(HW/32, CH/32, BATCH), dim3(32, 8)>>>(input);
    cvt_f2h<<<(DFC*FDIM/8 + 255)/256, 256>>>((const float4*)off_w1, (uint4*)w1p, DFC*FDIM/8);
    cvt_f2h<<<(DFC*DFC/8 + 255)/256, 256>>>((const float4*)off_w2, (uint4*)w2p, DFC*DFC/8);
    cvt_w3h<<<(NOFFP*DFC/8 + 255)/256, 256>>>(off_w3);
    // 2) x_cls pool -> d_out (exact fp32) + g_a1h (half)
    roi_pool<false,true><<<NROIS, 256, smem_pool>>>(rois, nullptr, xcls, a1p);
    // 3) rescale head (exact fp32) + new_rois
    rescale_newrois<<<NROIS, 256>>>(xcls, rois, rescale_w, rescale_b);
    // 4) offset MLP: fp16 tensor cores, split-K + combine
    gemm_h<<<dim3(DFC/128, NROIS/64, 8), 256>>>(a1p, w1p, partp, DFC, FDIM);
    combine<true,true><<<(NROIS*DFC + 255)/256, 256>>>(partp, off_b1, nullptr, h1p,
                                                       NROIS, DFC, DFC, 8);
    gemm_h<<<dim3(DFC/128, NROIS/64, 8), 256>>>(h1p, w2p, partp, DFC, DFC);
    combine<true,true><<<(NROIS*DFC + 255)/256, 256>>>(partp, off_b2, nullptr, h2p,
                                                       NROIS, DFC, DFC, 8);
    gemm_h<<<dim3(1, NROIS/64, 8), 256>>>(h2p, w3p, partp, NOFFP, DFC);
    combine<false,false><<<(NROIS*NOFF + 255)/256, 256>>>(partp, off_b3, offp, nullptr,
                                                          NROIS, NOFFP, NOFF, 8);
    // 5) x_reg pool (new rois + offsets) -> second half of d_out
    roi_pool<true,false><<<NROIS, 256, smem_pool>>>(nroisp, offp, xreg, nullptr);
}

// round 8
// speedup vs baseline: 5.2121x; 1.2168x over previous
#include <cuda_runtime.h>
#include <cuda_fp16.h>
#include <math.h>
#include <stdint.h>

#define BATCH 4
#define CH    256
#define FH    100
#define FW    152
#define HW    (FH*FW)          // 15200
#define NROIS 512
#define OH    7
#define OW    7
#define NBIN  49
#define FDIM  (CH*NBIN)        // 12544
#define DFC   1024
#define NOFF  98               // 2*49
#define NOFFP 128              // padded for GEMM3
#define SCALE 0.0625f
#define GAMMA 0.1f
#define SKMAX 8

// ---------------- scratch (device globals; no allocation allowed) -----------
__device__ __half g_feath[(size_t)BATCH*HW*CH];  // NHWC fp16 features, 31 MB
__device__ __half g_a1h[(size_t)NROIS*FDIM];     // half(xcls) 12.8 MB
__device__ __half g_w1h[(size_t)DFC*FDIM];       // half(w1) 25.7 MB
__device__ __half g_w2h[(size_t)DFC*DFC];        // half(w2) 2 MB
__device__ __half g_w3h[(size_t)NOFFP*DFC];      // half(w3), zero-padded rows
__device__ __half g_h1h[NROIS*DFC];
__device__ __half g_h2h[NROIS*DFC];
__device__ float  g_off[NROIS*NOFF];
__device__ float  g_nrois[NROIS*5];
__device__ float  g_part[(size_t)SKMAX*NROIS*DFC]; // split-K partials (16 MB)

// ---------------- NCHW -> NHWC fp16 transpose -------------------------------
__global__ void nchw2nhwc_h(const float* __restrict__ in) {
    __shared__ float tile[64][33];
    int b   = blockIdx.z;
    int hw0 = blockIdx.x * 32;
    int c0  = blockIdx.y * 64;
    #pragma unroll
    for (int r = 0; r < 8; r++) {
        int c  = c0 + threadIdx.y + r*8;
        int hw = hw0 + threadIdx.x;
        tile[threadIdx.y + r*8][threadIdx.x] = in[((size_t)b*CH + c)*HW + hw];
    }
    __syncthreads();
    __half2* out2 = (__half2*)g_feath;
    #pragma unroll
    for (int r = 0; r < 4; r++) {
        int hwl = threadIdx.y + r*8;
        int hw  = hw0 + hwl;
        int c2  = threadIdx.x;           // half2 index within the 64-channel tile
        float lo = tile[2*c2][hwl];
        float hi = tile[2*c2+1][hwl];
        out2[((size_t)b*HW + hw)*(CH/2) + c0/2 + c2] = __floats2half2_rn(lo, hi);
    }
}

// ---------------- fp32 -> fp16 conversions ----------------------------------
__device__ __forceinline__ uint32_t h2u(__half2 h) { return *reinterpret_cast<uint32_t*>(&h); }

__global__ void cvt_f2h(const float4* __restrict__ src, uint4* __restrict__ dst, int n8) {
    int i = blockIdx.x * 256 + threadIdx.x;
    if (i >= n8) return;
    float4 a = src[2*i], b = src[2*i + 1];
    uint4 o;
    o.x = h2u(__floats2half2_rn(a.x, a.y));
    o.y = h2u(__floats2half2_rn(a.z, a.w));
    o.z = h2u(__floats2half2_rn(b.x, b.y));
    o.w = h2u(__floats2half2_rn(b.z, b.w));
    dst[i] = o;
}
__global__ void cvt_w3h(const float* __restrict__ w3) {   // NOFFP*DFC/8 threads
    int i = blockIdx.x * 256 + threadIdx.x;
    if (i >= NOFFP*DFC/8) return;
    int base = i*8, r = base >> 10;
    uint4 o;
    if (r < NOFF) {
        const float4* s = (const float4*)(w3 + base);
        float4 a = s[0], b = s[1];
        o.x = h2u(__floats2half2_rn(a.x, a.y));
        o.y = h2u(__floats2half2_rn(a.z, a.w));
        o.z = h2u(__floats2half2_rn(b.x, b.y));
        o.w = h2u(__floats2half2_rn(b.z, b.w));
    } else {
        o.x = o.y = o.z = o.w = 0u;
    }
    ((uint4*)g_w3h)[i] = o;
}

// ---------------- deformable RoI pool (fp16 features, fp32 math) ------------
// 1 block per ROI, 256 threads = (8 bins in flight) x (32 groups of 8 channels).
template<bool HAS_OFF, bool EMIT_HALF>
__global__ void roi_pool(const float* __restrict__ rois,
                         const float* __restrict__ off,
                         float* __restrict__ out,
                         __half* __restrict__ out_h) {
    extern __shared__ float sout[];           // FDIM floats
    int roi = blockIdx.x;
    int tid = threadIdx.x;
    int bq = tid >> 5, cg = tid & 31;
    const float* r = rois + roi*5;
    int   b  = (int)r[0];
    float x1 = r[1]*SCALE - 0.5f;
    float y1 = r[2]*SCALE - 0.5f;
    float x2 = r[3]*SCALE - 0.5f;
    float y2 = r[4]*SCALE - 0.5f;
    float rw = x2 - x1, rh = y2 - y1;
    float bw = rw * (1.0f/OW), bh = rh * (1.0f/OH);
    const uint4* fb = (const uint4*)(g_feath + (size_t)b*HW*CH);
    const int C8 = CH/8;

    for (int b0 = 0; b0 < NBIN; b0 += 8) {
        int bin = b0 + bq;
        if (bin < NBIN) {
            int ph = bin / OW, pw = bin - ph*OW;
            float sw_ = x1, sh_ = y1;
            if (HAS_OFF) {
                sw_ += GAMMA * rw * off[roi*NOFF + bin];
                sh_ += GAMMA * rh * off[roi*NOFF + NBIN + bin];
            }
            float acc[8] = {};
            #pragma unroll
            for (int iy = 0; iy < 2; iy++) {
                float y = sh_ + ((float)ph + ((float)iy + 0.5f)*0.5f) * bh;
                #pragma unroll
                for (int ix = 0; ix < 2; ix++) {
                    float x = sw_ + ((float)pw + ((float)ix + 0.5f)*0.5f) * bw;
                    if (y > -1.0f && y < (float)FH && x > -1.0f && x < (float)FW) {
                        float yc = fminf(fmaxf(y, 0.0f), (float)(FH-1));
                        float xc = fminf(fmaxf(x, 0.0f), (float)(FW-1));
                        int y0 = min((int)floorf(yc), FH-2);
                        int x0 = min((int)floorf(xc), FW-2);
                        float ly = yc - (float)y0, lx = xc - (float)x0;
                        float hy = 1.0f - ly,     hx = 1.0f - lx;
                        float w00 = hy*hx, w01 = hy*lx, w10 = ly*hx, w11 = ly*lx;
                        const uint4* p = fb + ((size_t)y0*FW + x0)*C8 + cg;
                        uint4 v00 = p[0];
                        uint4 v01 = p[C8];
                        uint4 v10 = p[FW*C8];
                        uint4 v11 = p[FW*C8 + C8];
                        const uint32_t* u00 = &v00.x;
                        const uint32_t* u01 = &v01.x;
                        const uint32_t* u10 = &v10.x;
                        const uint32_t* u11 = &v11.x;
                        #pragma unroll
                        for (int q = 0; q < 4; q++) {
                            float2 f00 = __half22float2(*(const __half2*)&u00[q]);
                            float2 f01 = __half22float2(*(const __half2*)&u01[q]);
                            float2 f10 = __half22float2(*(const __half2*)&u10[q]);
                            float2 f11 = __half22float2(*(const __half2*)&u11[q]);
                            acc[2*q]   += w00*f00.x + w01*f01.x + w10*f10.x + w11*f11.x;
                            acc[2*q+1] += w00*f00.y + w01*f01.y + w10*f10.y + w11*f11.y;
                        }
                    }
                }
            }
            int c = cg*8;
            #pragma unroll
            for (int j = 0; j < 8; j++)
                sout[(c+j)*NBIN + bin] = acc[j] * 0.25f;
        }
    }
    __syncthreads();
    float* o = out + (size_t)roi * FDIM;
    if (EMIT_HALF) {
        __half* oh = out_h + (size_t)roi * FDIM;
        for (int i = tid; i < FDIM; i += 256) {
            float v = sout[i];
            o[i] = v;
            oh[i] = __float2half_rn(v);
        }
    } else {
        for (int i = tid; i < FDIM; i += 256) o[i] = sout[i];
    }
}

// ---------------- rescale head (only 4 of 98 outputs used) + new_rois -------
__global__ void rescale_newrois(const float* __restrict__ flat,
                                const float* __restrict__ rois,
                                const float* __restrict__ w,
                                const float* __restrict__ bias) {
    int roi = blockIdx.x;
    int tid = threadIdx.x;       // 256
    const float* f = flat + (size_t)roi * FDIM;
    float s0 = 0.f, s1 = 0.f, s2 = 0.f, s3 = 0.f;
    for (int k = tid; k < FDIM; k += 256) {
        float v = f[k];
        s0 += v * w[k];
        s1 += v * w[FDIM + k];
        s2 += v * w[2*FDIM + k];
        s3 += v * w[3*FDIM + k];
    }
    #pragma unroll
    for (int o = 16; o > 0; o >>= 1) {
        s0 += __shfl_down_sync(0xffffffffu, s0, o);
        s1 += __shfl_down_sync(0xffffffffu, s1, o);
        s2 += __shfl_down_sync(0xffffffffu, s2, o);
        s3 += __shfl_down_sync(0xffffffffu, s3, o);
    }
    __shared__ float red[4][8];
    int lane = tid & 31, warp = tid >> 5;
    if (lane == 0) { red[0][warp]=s0; red[1][warp]=s1; red[2][warp]=s2; red[3][warp]=s3; }
    __syncthreads();
    if (tid == 0) {
        float d[4];
        #pragma unroll
        for (int j = 0; j < 4; j++) {
            float t = 0.f;
            #pragma unroll
            for (int ww = 0; ww < 8; ww++) t += red[j][ww];
            d[j] = 1.0f + 0.5f / (1.0f + expf(-(t + bias[j])));
        }
        const float* r = rois + roi*5;
        float cx = (r[1] + r[3]) * 0.5f + d[0];
        float cy = (r[2] + r[4]) * 0.5f + d[1];
        float nw = (r[3] - r[1]) * d[2];
        float nh = (r[4] - r[2]) * d[3];
        float* nr = g_nrois + roi*5;
        nr[0] = r[0];
        nr[1] = cx - 0.5f*nw;  nr[2] = cy - 0.5f*nh;
        nr[3] = cx + 0.5f*nw;  nr[4] = cy + 0.5f*nh;
    }
}

// ---------------- fp16 tensor-core NT GEMM (unchanged from R7) --------------
__device__ __forceinline__ void mma_f16(float* c, uint32_t a0, uint32_t a1,
                                        uint32_t a2, uint32_t a3,
                                        uint32_t b0, uint32_t b1) {
    asm volatile(
        "mma.sync.aligned.m16n8k16.row.col.f32.f16.f16.f32 "
        "{%0,%1,%2,%3}, {%4,%5,%6,%7}, {%8,%9}, {%0,%1,%2,%3};"
        : "+f"(c[0]), "+f"(c[1]), "+f"(c[2]), "+f"(c[3])
        : "r"(a0), "r"(a1), "r"(a2), "r"(a3), "r"(b0), "r"(b1));
}

__global__ void __launch_bounds__(256, 2)
gemm_h(const __half* __restrict__ A, const __half* __restrict__ B,
       float* __restrict__ P, int N, int K) {
    const int BM = 64, BN = 128;
    __shared__ __align__(16) uint32_t As[2][BM*16];
    __shared__ __align__(16) uint32_t Bs[2][BN*16];

    int tid  = threadIdx.x;
    int lane = tid & 31, w = tid >> 5;
    int g = lane >> 2, tig = lane & 3;
    int wm = w >> 2, wn = w & 3;
    int bm = blockIdx.y * BM, bn = blockIdx.x * BN;
    int S  = gridDim.z, kz = blockIdx.z;
    int Ks = K / S;
    int M  = gridDim.y * BM;
    int nst = Ks >> 5;

    int lm = tid >> 2, lq = tid & 3;
    const __half* Ap  = A + (size_t)(bm + lm)*K + (size_t)kz*Ks + lq*8;
    const __half* Bp0 = B + (size_t)(bn + lm)*K + (size_t)kz*Ks + lq*8;
    const __half* Bp1 = Bp0 + (size_t)64*K;
    int sc   = lq ^ ((lm >> 1) & 3);
    int sa_w  = lm*16 + sc*4;
    int sb_w0 = lm*16 + sc*4;
    int sb_w1 = (lm + 64)*16 + sc*4;

    float acc[2][4][4];
    #pragma unroll
    for (int i = 0; i < 2; i++)
        #pragma unroll
        for (int j = 0; j < 4; j++)
            #pragma unroll
            for (int q = 0; q < 4; q++) acc[i][j][q] = 0.0f;

    int mrow[2], mj[2];
    #pragma unroll
    for (int ii = 0; ii < 2; ii++) {
        mrow[ii] = wm*32 + ii*16 + g;
        mj[ii] = ((mrow[ii] >> 1) & 3) << 2;
    }
    int nrow[4], nj[4];
    #pragma unroll
    for (int jj = 0; jj < 4; jj++) {
        nrow[jj] = wn*32 + jj*8 + g;
        nj[jj] = ((nrow[jj] >> 1) & 3) << 2;
    }

    uint4 va  = *(const uint4*)Ap;
    uint4 vb0 = *(const uint4*)Bp0;
    uint4 vb1 = *(const uint4*)Bp1;
    *(uint4*)&As[0][sa_w]  = va;
    *(uint4*)&Bs[0][sb_w0] = vb0;
    *(uint4*)&Bs[0][sb_w1] = vb1;
    __syncthreads();

    for (int s = 0; s < nst; s++) {
        int buf = s & 1;
        if (s + 1 < nst) {
            size_t o = (size_t)(s+1)*32;
            va  = *(const uint4*)(Ap  + o);
            vb0 = *(const uint4*)(Bp0 + o);
            vb1 = *(const uint4*)(Bp1 + o);
        }
        const uint32_t* as = As[buf];
        const uint32_t* bs = Bs[buf];
        #pragma unroll
        for (int kb = 0; kb < 2; kb++) {
            int kw0 = kb*8 + tig, kw1 = kw0 + 4;
            uint32_t af[2][4], bf[4][2];
            #pragma unroll
            for (int ii = 0; ii < 2; ii++) {
                int r0 = mrow[ii]*16, r1 = (mrow[ii]+8)*16, x = mj[ii];
                af[ii][0] = as[r0 + (kw0 ^ x)];
                af[ii][1] = as[r1 + (kw0 ^ x)];
                af[ii][2] = as[r0 + (kw1 ^ x)];
                af[ii][3] = as[r1 + (kw1 ^ x)];
            }
            #pragma unroll
            for (int jj = 0; jj < 4; jj++) {
                int rn = nrow[jj]*16, x = nj[jj];
                bf[jj][0] = bs[rn + (kw0 ^ x)];
                bf[jj][1] = bs[rn + (kw1 ^ x)];
            }
            #pragma unroll
            for (int ii = 0; ii < 2; ii++)
                #pragma unroll
                for (int jj = 0; jj < 4; jj++)
                    mma_f16(acc[ii][jj], af[ii][0], af[ii][1], af[ii][2], af[ii][3],
                            bf[jj][0], bf[jj][1]);
        }
        if (s + 1 < nst) {
            *(uint4*)&As[buf^1][sa_w]  = va;
            *(uint4*)&Bs[buf^1][sb_w0] = vb0;
            *(uint4*)&Bs[buf^1][sb_w1] = vb1;
        }
        __syncthreads();
    }

    float* Pp = P + (size_t)kz * M * N;
    #pragma unroll
    for (int ii = 0; ii < 2; ii++) {
        #pragma unroll
        for (int jj = 0; jj < 4; jj++) {
            int r0 = bm + wm*32 + ii*16 + g;
            int c0 = bn + wn*32 + jj*8 + tig*2;
            Pp[(size_t)r0*N + c0]       = acc[ii][jj][0];
            Pp[(size_t)r0*N + c0 + 1]   = acc[ii][jj][1];
            Pp[(size_t)(r0+8)*N + c0]   = acc[ii][jj][2];
            Pp[(size_t)(r0+8)*N + c0+1] = acc[ii][jj][3];
        }
    }
}

// -------- split-K combine: act(sum_s P_s + bias); half or float out ---------
template<bool RELU, bool TOHALF>
__global__ void combine(const float* __restrict__ P, const float* __restrict__ bias,
                        float* __restrict__ outf, __half* __restrict__ outh,
                        int M, int Ntot, int Nlog, int S) {
    int i = blockIdx.x * 256 + threadIdx.x;
    if (i >= M*Nlog) return;
    int m = i / Nlog, n = i - m*Nlog;
    float v = bias[n];
    for (int s = 0; s < S; s++)
        v += P[((size_t)s*M + m)*Ntot + n];
    if (RELU) v = fmaxf(v, 0.0f);
    if (TOHALF) outh[i] = __float2half_rn(v);
    else        outf[i] = v;
}

// ---------------- launch -----------------------------------------------------
extern "C" void kernel_launch(void* const* d_in, const int* in_sizes, int n_in,
                              void* d_out, int out_size) {
    const float* input     = (const float*)d_in[0];
    const float* rois      = (const float*)d_in[1];
    const float* rescale_w = (const float*)d_in[2];
    const float* rescale_b = (const float*)d_in[3];
    const float* off_w1    = (const float*)d_in[4];
    const float* off_b1    = (const float*)d_in[5];
    const float* off_w2    = (const float*)d_in[6];
    const float* off_b2    = (const float*)d_in[7];
    const float* off_w3    = (const float*)d_in[8];
    const float* off_b3    = (const float*)d_in[9];

    float* xcls = (float*)d_out;
    float* xreg = xcls + (size_t)NROIS * FDIM;

    __half *a1p, *w1p, *w2p, *w3p, *h1p, *h2p;
    float *offp, *nroisp, *partp;
    cudaGetSymbolAddress((void**)&a1p,    g_a1h);
    cudaGetSymbolAddress((void**)&w1p,    g_w1h);
    cudaGetSymbolAddress((void**)&w2p,    g_w2h);
    cudaGetSymbolAddress((void**)&w3p,    g_w3h);
    cudaGetSymbolAddress((void**)&h1p,    g_h1h);
    cudaGetSymbolAddress((void**)&h2p,    g_h2h);
    cudaGetSymbolAddress((void**)&offp,   g_off);
    cudaGetSymbolAddress((void**)&nroisp, g_nrois);
    cudaGetSymbolAddress((void**)&partp,  g_part);

    const int smem_pool = FDIM * sizeof(float);
    cudaFuncSetAttribute((const void*)roi_pool<false,true>,
                         cudaFuncAttributeMaxDynamicSharedMemorySize, smem_pool);
    cudaFuncSetAttribute((const void*)roi_pool<true,false>,
                         cudaFuncAttributeMaxDynamicSharedMemorySize, smem_pool);

    // 1) transpose to NHWC fp16 + weight half-conversions
    nchw2nhwc_h<<<dim3(HW/32, CH/64, BATCH), dim3(32, 8)>>>(input);
    cvt_f2h<<<(DFC*FDIM/8 + 255)/256, 256>>>((const float4*)off_w1, (uint4*)w1p, DFC*FDIM/8);
    cvt_f2h<<<(DFC*DFC/8 + 255)/256, 256>>>((const float4*)off_w2, (uint4*)w2p, DFC*DFC/8);
    cvt_w3h<<<(NOFFP*DFC/8 + 255)/256, 256>>>(off_w3);
    // 2) x_cls pool -> d_out (fp32 accum) + g_a1h (half)
    roi_pool<false,true><<<NROIS, 256, smem_pool>>>(rois, nullptr, xcls, a1p);
    // 3) rescale head (fp32) + new_rois
    rescale_newrois<<<NROIS, 256>>>(xcls, rois, rescale_w, rescale_b);
    // 4) offset MLP: fp16 tensor cores, split-K + combine
    gemm_h<<<dim3(DFC/128, NROIS/64, 8), 256>>>(a1p, w1p, partp, DFC, FDIM);
    combine<true,true><<<(NROIS*DFC + 255)/256, 256>>>(partp, off_b1, nullptr, h1p,
                                                       NROIS, DFC, DFC, 8);
    gemm_h<<<dim3(DFC/128, NROIS/64, 8), 256>>>(h1p, w2p, partp, DFC, DFC);
    combine<true,true><<<(NROIS*DFC + 255)/256, 256>>>(partp, off_b2, nullptr, h2p,
                                                       NROIS, DFC, DFC, 8);
    gemm_h<<<dim3(1, NROIS/64, 8), 256>>>(h2p, w3p, partp, NOFFP, DFC);
    combine<false,false><<<(NROIS*NOFF + 255)/256, 256>>>(partp, off_b3, offp, nullptr,
                                                          NROIS, NOFFP, NOFF, 8);
    // 5) x_reg pool (new rois + offsets) -> second half of d_out
    roi_pool<true,false><<<NROIS, 256, smem_pool>>>(nroisp, offp, xreg, nullptr);
}

// round 9
// speedup vs baseline: 5.6331x; 1.0808x over previous
#include <cuda_runtime.h>
#include <cuda_fp16.h>
#include <math.h>
#include <stdint.h>

#define BATCH 4
#define CH    256
#define FH    100
#define FW    152
#define HW    (FH*FW)          // 15200
#define NROIS 512
#define OH    7
#define OW    7
#define NBIN  49
#define FDIM  (CH*NBIN)        // 12544
#define DFC   1024
#define NOFF  98               // 2*49
#define NOFFP 128              // padded for GEMM3
#define SCALE 0.0625f
#define GAMMA 0.1f
#define SKMAX 8

// ---------------- scratch (device globals; no allocation allowed) -----------
__device__ __half g_feath[(size_t)BATCH*HW*CH];  // NHWC fp16 features, 31 MB
__device__ __half g_a1h[(size_t)NROIS*FDIM];     // half(xcls) 12.8 MB
__device__ __half g_w1h[(size_t)DFC*FDIM];       // half(w1) 25.7 MB
__device__ __half g_w2h[(size_t)DFC*DFC];        // half(w2) 2 MB
__device__ __half g_w3h[(size_t)NOFFP*DFC];      // half(w3), zero-padded rows
__device__ __half g_h1h[NROIS*DFC];
__device__ __half g_h2h[NROIS*DFC];
__device__ float  g_off[NROIS*NOFF];
__device__ float  g_nrois[NROIS*5];
__device__ float  g_part[(size_t)SKMAX*NROIS*DFC]; // split-K partials (16 MB)

// ---------------- NCHW -> NHWC fp16 transpose -------------------------------
__global__ void nchw2nhwc_h(const float* __restrict__ in) {
    __shared__ float tile[64][33];
    int b   = blockIdx.z;
    int hw0 = blockIdx.x * 32;
    int c0  = blockIdx.y * 64;
    #pragma unroll
    for (int r = 0; r < 8; r++) {
        int c  = c0 + threadIdx.y + r*8;
        int hw = hw0 + threadIdx.x;
        tile[threadIdx.y + r*8][threadIdx.x] = in[((size_t)b*CH + c)*HW + hw];
    }
    __syncthreads();
    __half2* out2 = (__half2*)g_feath;
    #pragma unroll
    for (int r = 0; r < 4; r++) {
        int hwl = threadIdx.y + r*8;
        int hw  = hw0 + hwl;
        int c2  = threadIdx.x;
        float lo = tile[2*c2][hwl];
        float hi = tile[2*c2+1][hwl];
        out2[((size_t)b*HW + hw)*(CH/2) + c0/2 + c2] = __floats2half2_rn(lo, hi);
    }
}

// ---------------- fused fp32 -> fp16 weight conversion ----------------------
__device__ __forceinline__ uint32_t h2u(__half2 h) { return *reinterpret_cast<uint32_t*>(&h); }
__device__ __forceinline__ uint4 f8toh8(const float4* s) {
    float4 a = s[0], b = s[1];
    uint4 o;
    o.x = h2u(__floats2half2_rn(a.x, a.y));
    o.y = h2u(__floats2half2_rn(a.z, a.w));
    o.z = h2u(__floats2half2_rn(b.x, b.y));
    o.w = h2u(__floats2half2_rn(b.z, b.w));
    return o;
}

#define W1_8 (DFC*FDIM/8)
#define W2_8 (DFC*DFC/8)
#define W3_8 (NOFFP*DFC/8)

__global__ void cvt_weights(const float* __restrict__ w1,
                            const float* __restrict__ w2,
                            const float* __restrict__ w3) {
    int i = blockIdx.x * 256 + threadIdx.x;
    if (i < W1_8) {
        ((uint4*)g_w1h)[i] = f8toh8((const float4*)(w1 + (size_t)i*8));
    } else if (i < W1_8 + W2_8) {
        int j = i - W1_8;
        ((uint4*)g_w2h)[j] = f8toh8((const float4*)(w2 + (size_t)j*8));
    } else if (i < W1_8 + W2_8 + W3_8) {
        int j = i - W1_8 - W2_8;
        int r = (j*8) >> 10;
        uint4 o;
        if (r < NOFF) o = f8toh8((const float4*)(w3 + (size_t)j*8));
        else          o.x = o.y = o.z = o.w = 0u;
        ((uint4*)g_w3h)[j] = o;
    }
}

// ---------------- deformable RoI pool (fp16 features, fp32 math) ------------
template<bool HAS_OFF, bool EMIT_HALF>
__global__ void roi_pool(const float* __restrict__ rois,
                         const float* __restrict__ off,
                         float* __restrict__ out,
                         __half* __restrict__ out_h) {
    extern __shared__ float sout[];           // FDIM floats
    int roi = blockIdx.x;
    int tid = threadIdx.x;
    int bq = tid >> 5, cg = tid & 31;
    const float* r = rois + roi*5;
    int   b  = (int)r[0];
    float x1 = r[1]*SCALE - 0.5f;
    float y1 = r[2]*SCALE - 0.5f;
    float x2 = r[3]*SCALE - 0.5f;
    float y2 = r[4]*SCALE - 0.5f;
    float rw = x2 - x1, rh = y2 - y1;
    float bw = rw * (1.0f/OW), bh = rh * (1.0f/OH);
    const uint4* fb = (const uint4*)(g_feath + (size_t)b*HW*CH);
    const int C8 = CH/8;

    for (int b0 = 0; b0 < NBIN; b0 += 8) {
        int bin = b0 + bq;
        if (bin < NBIN) {
            int ph = bin / OW, pw = bin - ph*OW;
            float sw_ = x1, sh_ = y1;
            if (HAS_OFF) {
                sw_ += GAMMA * rw * off[roi*NOFF + bin];
                sh_ += GAMMA * rh * off[roi*NOFF + NBIN + bin];
            }
            float acc[8] = {};
            #pragma unroll
            for (int iy = 0; iy < 2; iy++) {
                float y = sh_ + ((float)ph + ((float)iy + 0.5f)*0.5f) * bh;
                #pragma unroll
                for (int ix = 0; ix < 2; ix++) {
                    float x = sw_ + ((float)pw + ((float)ix + 0.5f)*0.5f) * bw;
                    if (y > -1.0f && y < (float)FH && x > -1.0f && x < (float)FW) {
                        float yc = fminf(fmaxf(y, 0.0f), (float)(FH-1));
                        float xc = fminf(fmaxf(x, 0.0f), (float)(FW-1));
                        int y0 = min((int)floorf(yc), FH-2);
                        int x0 = min((int)floorf(xc), FW-2);
                        float ly = yc - (float)y0, lx = xc - (float)x0;
                        float hy = 1.0f - ly,     hx = 1.0f - lx;
                        float w00 = hy*hx, w01 = hy*lx, w10 = ly*hx, w11 = ly*lx;
                        const uint4* p = fb + ((size_t)y0*FW + x0)*C8 + cg;
                        uint4 v00 = p[0];
                        uint4 v01 = p[C8];
                        uint4 v10 = p[FW*C8];
                        uint4 v11 = p[FW*C8 + C8];
                        const uint32_t* u00 = &v00.x;
                        const uint32_t* u01 = &v01.x;
                        const uint32_t* u10 = &v10.x;
                        const uint32_t* u11 = &v11.x;
                        #pragma unroll
                        for (int q = 0; q < 4; q++) {
                            float2 f00 = __half22float2(*(const __half2*)&u00[q]);
                            float2 f01 = __half22float2(*(const __half2*)&u01[q]);
                            float2 f10 = __half22float2(*(const __half2*)&u10[q]);
                            float2 f11 = __half22float2(*(const __half2*)&u11[q]);
                            acc[2*q]   += w00*f00.x + w01*f01.x + w10*f10.x + w11*f11.x;
                            acc[2*q+1] += w00*f00.y + w01*f01.y + w10*f10.y + w11*f11.y;
                        }
                    }
                }
            }
            int c = cg*8;
            #pragma unroll
            for (int j = 0; j < 8; j++)
                sout[(c+j)*NBIN + bin] = acc[j] * 0.25f;
        }
    }
    __syncthreads();
    float* o = out + (size_t)roi * FDIM;
    if (EMIT_HALF) {
        __half* oh = out_h + (size_t)roi * FDIM;
        for (int i = tid; i < FDIM; i += 256) {
            float v = sout[i];
            o[i] = v;
            oh[i] = __float2half_rn(v);
        }
    } else {
        for (int i = tid; i < FDIM; i += 256) o[i] = sout[i];
    }
}

// ---------------- rescale head + new_rois ------------------------------------
__global__ void rescale_newrois(const float* __restrict__ flat,
                                const float* __restrict__ rois,
                                const float* __restrict__ w,
                                const float* __restrict__ bias) {
    int roi = blockIdx.x;
    int tid = threadIdx.x;       // 256
    const float* f = flat + (size_t)roi * FDIM;
    float s0 = 0.f, s1 = 0.f, s2 = 0.f, s3 = 0.f;
    for (int k = tid; k < FDIM; k += 256) {
        float v = f[k];
        s0 += v * w[k];
        s1 += v * w[FDIM + k];
        s2 += v * w[2*FDIM + k];
        s3 += v * w[3*FDIM + k];
    }
    #pragma unroll
    for (int o = 16; o > 0; o >>= 1) {
        s0 += __shfl_down_sync(0xffffffffu, s0, o);
        s1 += __shfl_down_sync(0xffffffffu, s1, o);
        s2 += __shfl_down_sync(0xffffffffu, s2, o);
        s3 += __shfl_down_sync(0xffffffffu, s3, o);
    }
    __shared__ float red[4][8];
    int lane = tid & 31, warp = tid >> 5;
    if (lane == 0) { red[0][warp]=s0; red[1][warp]=s1; red[2][warp]=s2; red[3][warp]=s3; }
    __syncthreads();
    if (tid == 0) {
        float d[4];
        #pragma unroll
        for (int j = 0; j < 4; j++) {
            float t = 0.f;
            #pragma unroll
            for (int ww = 0; ww < 8; ww++) t += red[j][ww];
            d[j] = 1.0f + 0.5f / (1.0f + expf(-(t + bias[j])));
        }
        const float* r = rois + roi*5;
        float cx = (r[1] + r[3]) * 0.5f + d[0];
        float cy = (r[2] + r[4]) * 0.5f + d[1];
        float nw = (r[3] - r[1]) * d[2];
        float nh = (r[4] - r[2]) * d[3];
        float* nr = g_nrois + roi*5;
        nr[0] = r[0];
        nr[1] = cx - 0.5f*nw;  nr[2] = cy - 0.5f*nh;
        nr[3] = cx + 0.5f*nw;  nr[4] = cy + 0.5f*nh;
    }
}

// ---------------- fp16 tensor-core NT GEMM, 128x128x32 tiles ----------------
// P[kz][M][N] partial = A[M,Ks] * B[N,Ks]^T. M mult of 128, N mult of 128.
// 256 threads, 8 warps (2x4), warp tile 64x32.
// smem word layout: word(m, kw) at m*16 + (kw ^ (((m>>1)&3)<<2)) — conflict-free
// for STS.128 producer stores and all LDS.32 fragment loads.

__device__ __forceinline__ void mma_f16(float* c, uint32_t a0, uint32_t a1,
                                        uint32_t a2, uint32_t a3,
                                        uint32_t b0, uint32_t b1) {
    asm volatile(
        "mma.sync.aligned.m16n8k16.row.col.f32.f16.f16.f32 "
        "{%0,%1,%2,%3}, {%4,%5,%6,%7}, {%8,%9}, {%0,%1,%2,%3};"
        : "+f"(c[0]), "+f"(c[1]), "+f"(c[2]), "+f"(c[3])
        : "r"(a0), "r"(a1), "r"(a2), "r"(a3), "r"(b0), "r"(b1));
}

__global__ void __launch_bounds__(256, 2)
gemm_h(const __half* __restrict__ A, const __half* __restrict__ B,
       float* __restrict__ P, int N, int K) {
    const int BM = 128, BN = 128;
    __shared__ __align__(16) uint32_t As[2][BM*16];
    __shared__ __align__(16) uint32_t Bs[2][BN*16];

    int tid  = threadIdx.x;
    int lane = tid & 31, w = tid >> 5;
    int g = lane >> 2, tig = lane & 3;
    int wm = w >> 2, wn = w & 3;               // 2 x 4 warp grid
    int bm = blockIdx.y * BM, bn = blockIdx.x * BN;
    int S  = gridDim.z, kz = blockIdx.z;
    int Ks = K / S;
    int M  = gridDim.y * BM;
    int nst = Ks >> 5;

    // producer: rows lm and lm+64 for A and B (1 uint4 = 8 halves each)
    int lm = tid >> 2, lq = tid & 3;
    const __half* Ap0 = A + (size_t)(bm + lm)*K + (size_t)kz*Ks + lq*8;
    const __half* Ap1 = Ap0 + (size_t)64*K;
    const __half* Bp0 = B + (size_t)(bn + lm)*K + (size_t)kz*Ks + lq*8;
    const __half* Bp1 = Bp0 + (size_t)64*K;
    int sc = lq ^ ((lm >> 1) & 3);             // same XOR for lm and lm+64
    int sw0 = lm*16 + sc*4;
    int sw1 = (lm + 64)*16 + sc*4;

    float acc[4][4][4];
    #pragma unroll
    for (int i = 0; i < 4; i++)
        #pragma unroll
        for (int j = 0; j < 4; j++)
            #pragma unroll
            for (int q = 0; q < 4; q++) acc[i][j][q] = 0.0f;

    int mrow[4], mj[4];
    #pragma unroll
    for (int ii = 0; ii < 4; ii++) {
        mrow[ii] = wm*64 + ii*16 + g;
        mj[ii] = ((mrow[ii] >> 1) & 3) << 2;
    }
    int nrow[4], nj[4];
    #pragma unroll
    for (int jj = 0; jj < 4; jj++) {
        nrow[jj] = wn*32 + jj*8 + g;
        nj[jj] = ((nrow[jj] >> 1) & 3) << 2;
    }

    uint4 va0 = *(const uint4*)Ap0, va1 = *(const uint4*)Ap1;
    uint4 vb0 = *(const uint4*)Bp0, vb1 = *(const uint4*)Bp1;
    *(uint4*)&As[0][sw0] = va0;  *(uint4*)&As[0][sw1] = va1;
    *(uint4*)&Bs[0][sw0] = vb0;  *(uint4*)&Bs[0][sw1] = vb1;
    __syncthreads();

    for (int s = 0; s < nst; s++) {
        int buf = s & 1;
        if (s + 1 < nst) {
            size_t o = (size_t)(s+1)*32;
            va0 = *(const uint4*)(Ap0 + o);  va1 = *(const uint4*)(Ap1 + o);
            vb0 = *(const uint4*)(Bp0 + o);  vb1 = *(const uint4*)(Bp1 + o);
        }
        const uint32_t* as = As[buf];
        const uint32_t* bs = Bs[buf];
        #pragma unroll
        for (int kb = 0; kb < 2; kb++) {
            int kw0 = kb*8 + tig, kw1 = kw0 + 4;
            uint32_t af[4][4], bf[4][2];
            #pragma unroll
            for (int jj = 0; jj < 4; jj++) {
                int rn = nrow[jj]*16, x = nj[jj];
                bf[jj][0] = bs[rn + (kw0 ^ x)];
                bf[jj][1] = bs[rn + (kw1 ^ x)];
            }
            #pragma unroll
            for (int ii = 0; ii < 4; ii++) {
                int r0 = mrow[ii]*16, r1 = (mrow[ii]+8)*16, x = mj[ii];
                af[ii][0] = as[r0 + (kw0 ^ x)];
                af[ii][1] = as[r1 + (kw0 ^ x)];
                af[ii][2] = as[r0 + (kw1 ^ x)];
                af[ii][3] = as[r1 + (kw1 ^ x)];
            }
            #pragma unroll
            for (int ii = 0; ii < 4; ii++)
                #pragma unroll
                for (int jj = 0; jj < 4; jj++)
                    mma_f16(acc[ii][jj], af[ii][0], af[ii][1], af[ii][2], af[ii][3],
                            bf[jj][0], bf[jj][1]);
        }
        if (s + 1 < nst) {
            *(uint4*)&As[buf^1][sw0] = va0;  *(uint4*)&As[buf^1][sw1] = va1;
            *(uint4*)&Bs[buf^1][sw0] = vb0;  *(uint4*)&Bs[buf^1][sw1] = vb1;
        }
        __syncthreads();
    }

    float* Pp = P + (size_t)kz * M * N;
    #pragma unroll
    for (int ii = 0; ii < 4; ii++) {
        #pragma unroll
        for (int jj = 0; jj < 4; jj++) {
            int r0 = bm + wm*64 + ii*16 + g;
            int c0 = bn + wn*32 + jj*8 + tig*2;
            Pp[(size_t)r0*N + c0]       = acc[ii][jj][0];
            Pp[(size_t)r0*N + c0 + 1]   = acc[ii][jj][1];
            Pp[(size_t)(r0+8)*N + c0]   = acc[ii][jj][2];
            Pp[(size_t)(r0+8)*N + c0+1] = acc[ii][jj][3];
        }
    }
}

// -------- split-K combine: act(sum_s P_s + bias); half or float out ---------
template<bool RELU, bool TOHALF>
__global__ void combine(const float* __restrict__ P, const float* __restrict__ bias,
                        float* __restrict__ outf, __half* __restrict__ outh,
                        int M, int Ntot, int Nlog, int S) {
    int i = blockIdx.x * 256 + threadIdx.x;
    if (i >= M*Nlog) return;
    int m = i / Nlog, n = i - m*Nlog;
    float v = bias[n];
    for (int s = 0; s < S; s++)
        v += P[((size_t)s*M + m)*Ntot + n];
    if (RELU) v = fmaxf(v, 0.0f);
    if (TOHALF) outh[i] = __float2half_rn(v);
    else        outf[i] = v;
}

// ---------------- launch -----------------------------------------------------
extern "C" void kernel_launch(void* const* d_in, const int* in_sizes, int n_in,
                              void* d_out, int out_size) {
    const float* input     = (const float*)d_in[0];
    const float* rois      = (const float*)d_in[1];
    const float* rescale_w = (const float*)d_in[2];
    const float* rescale_b = (const float*)d_in[3];
    const float* off_w1    = (const float*)d_in[4];
    const float* off_b1    = (const float*)d_in[5];
    const float* off_w2    = (const float*)d_in[6];
    const float* off_b2    = (const float*)d_in[7];
    const float* off_w3    = (const float*)d_in[8];
    const float* off_b3    = (const float*)d_in[9];

    float* xcls = (float*)d_out;
    float* xreg = xcls + (size_t)NROIS * FDIM;

    __half *a1p, *w1p, *w2p, *w3p, *h1p, *h2p;
    float *offp, *nroisp, *partp;
    cudaGetSymbolAddress((void**)&a1p,    g_a1h);
    cudaGetSymbolAddress((void**)&w1p,    g_w1h);
    cudaGetSymbolAddress((void**)&w2p,    g_w2h);
    cudaGetSymbolAddress((void**)&w3p,    g_w3h);
    cudaGetSymbolAddress((void**)&h1p,    g_h1h);
    cudaGetSymbolAddress((void**)&h2p,    g_h2h);
    cudaGetSymbolAddress((void**)&offp,   g_off);
    cudaGetSymbolAddress((void**)&nroisp, g_nrois);
    cudaGetSymbolAddress((void**)&partp,  g_part);

    const int smem_pool = FDIM * sizeof(float);
    cudaFuncSetAttribute((const void*)roi_pool<false,true>,
                         cudaFuncAttributeMaxDynamicSharedMemorySize, smem_pool);
    cudaFuncSetAttribute((const void*)roi_pool<true,false>,
                         cudaFuncAttributeMaxDynamicSharedMemorySize, smem_pool);

    // 1) transpose to NHWC fp16 + fused weight half-conversion
    nchw2nhwc_h<<<dim3(HW/32, CH/64, BATCH), dim3(32, 8)>>>(input);
    cvt_weights<<<(W1_8 + W2_8 + W3_8 + 255)/256, 256>>>(off_w1, off_w2, off_w3);
    // 2) x_cls pool -> d_out (fp32) + g_a1h (half)
    roi_pool<false,true><<<NROIS, 256, smem_pool>>>(rois, nullptr, xcls, a1p);
    // 3) rescale head (fp32) + new_rois
    rescale_newrois<<<NROIS, 256>>>(xcls, rois, rescale_w, rescale_b);
    // 4) offset MLP: fp16 tensor cores (128x128 tiles), split-K + combine
    gemm_h<<<dim3(DFC/128, NROIS/128, 8), 256>>>(a1p, w1p, partp, DFC, FDIM);
    combine<true,true><<<(NROIS*DFC + 255)/256, 256>>>(partp, off_b1, nullptr, h1p,
                                                       NROIS, DFC, DFC, 8);
    gemm_h<<<dim3(DFC/128, NROIS/128, 8), 256>>>(h1p, w2p, partp, DFC, DFC);
    combine<true,true><<<(NROIS*DFC + 255)/256, 256>>>(partp, off_b2, nullptr, h2p,
                                                       NROIS, DFC, DFC, 8);
    gemm_h<<<dim3(1, NROIS/128, 8), 256>>>(h2p, w3p, partp, NOFFP, DFC);
    combine<false,false><<<(NROIS*NOFF + 255)/256, 256>>>(partp, off_b3, offp, nullptr,
                                                          NROIS, NOFFP, NOFF, 8);
    // 5) x_reg pool (new rois + offsets) -> second half of d_out
    roi_pool<true,false><<<NROIS, 256, smem_pool>>>(nroisp, offp, xreg, nullptr);
}

// round 10
// speedup vs baseline: 6.2068x; 1.1018x over previous
#include <cuda_runtime.h>
#include <cuda_fp16.h>
#include <math.h>
#include <stdint.h>

#define BATCH 4
#define CH    256
#define FH    100
#define FW    152
#define HW    (FH*FW)          // 15200
#define NROIS 512
#define OH    7
#define OW    7
#define NBIN  49
#define FDIM  (CH*NBIN)        // 12544
#define DFC   1024
#define NOFF  98               // 2*49
#define NOFFP 128              // padded for GEMM3
#define SCALE 0.0625f
#define GAMMA 0.1f
#define SKMAX 8

// ---------------- scratch (device globals; no allocation allowed) -----------
__device__ __half g_feath[(size_t)BATCH*HW*CH];  // NHWC fp16 features, 31 MB
__device__ __half g_a1h[(size_t)NROIS*FDIM];     // half(xcls) 12.8 MB
__device__ __half g_w1h[(size_t)DFC*FDIM];       // half(w1) 25.7 MB
__device__ __half g_w2h[(size_t)DFC*DFC];        // half(w2) 2 MB
__device__ __half g_w3h[(size_t)NOFFP*DFC];      // half(w3), zero-padded rows
__device__ __half g_h1h[NROIS*DFC];
__device__ __half g_h2h[NROIS*DFC];
__device__ float  g_off[NROIS*NOFF];
__device__ float  g_nrois[NROIS*5];
__device__ float  g_part[(size_t)SKMAX*NROIS*DFC]; // split-K partials (16 MB)

// ---------------- NCHW -> NHWC fp16 transpose -------------------------------
__global__ void nchw2nhwc_h(const float* __restrict__ in) {
    __shared__ float tile[64][33];
    int b   = blockIdx.z;
    int hw0 = blockIdx.x * 32;
    int c0  = blockIdx.y * 64;
    #pragma unroll
    for (int r = 0; r < 8; r++) {
        int c  = c0 + threadIdx.y + r*8;
        int hw = hw0 + threadIdx.x;
        tile[threadIdx.y + r*8][threadIdx.x] = in[((size_t)b*CH + c)*HW + hw];
    }
    __syncthreads();
    __half2* out2 = (__half2*)g_feath;
    #pragma unroll
    for (int r = 0; r < 4; r++) {
        int hwl = threadIdx.y + r*8;
        int hw  = hw0 + hwl;
        int c2  = threadIdx.x;
        float lo = tile[2*c2][hwl];
        float hi = tile[2*c2+1][hwl];
        out2[((size_t)b*HW + hw)*(CH/2) + c0/2 + c2] = __floats2half2_rn(lo, hi);
    }
}

// ---------------- fused fp32 -> fp16 weight conversion ----------------------
__device__ __forceinline__ uint32_t h2u(__half2 h) { return *reinterpret_cast<uint32_t*>(&h); }
__device__ __forceinline__ uint4 f8toh8(const float4* s) {
    float4 a = s[0], b = s[1];
    uint4 o;
    o.x = h2u(__floats2half2_rn(a.x, a.y));
    o.y = h2u(__floats2half2_rn(a.z, a.w));
    o.z = h2u(__floats2half2_rn(b.x, b.y));
    o.w = h2u(__floats2half2_rn(b.z, b.w));
    return o;
}

#define W1_8 (DFC*FDIM/8)
#define W2_8 (DFC*DFC/8)
#define W3_8 (NOFFP*DFC/8)

__global__ void cvt_weights(const float* __restrict__ w1,
                            const float* __restrict__ w2,
                            const float* __restrict__ w3) {
    int i = blockIdx.x * 256 + threadIdx.x;
    if (i < W1_8) {
        ((uint4*)g_w1h)[i] = f8toh8((const float4*)(w1 + (size_t)i*8));
    } else if (i < W1_8 + W2_8) {
        int j = i - W1_8;
        ((uint4*)g_w2h)[j] = f8toh8((const float4*)(w2 + (size_t)j*8));
    } else if (i < W1_8 + W2_8 + W3_8) {
        int j = i - W1_8 - W2_8;
        int r = (j*8) >> 10;
        uint4 o;
        if (r < NOFF) o = f8toh8((const float4*)(w3 + (size_t)j*8));
        else          o.x = o.y = o.z = o.w = 0u;
        ((uint4*)g_w3h)[j] = o;
    }
}

// ---------------- deformable RoI pool (fp16 features, fp32 math) ------------
template<bool HAS_OFF, bool EMIT_HALF>
__global__ void roi_pool(const float* __restrict__ rois,
                         const float* __restrict__ off,
                         float* __restrict__ out,
                         __half* __restrict__ out_h) {
    extern __shared__ float sout[];           // FDIM floats
    int roi = blockIdx.x;
    int tid = threadIdx.x;
    int bq = tid >> 5, cg = tid & 31;
    const float* r = rois + roi*5;
    int   b  = (int)r[0];
    float x1 = r[1]*SCALE - 0.5f;
    float y1 = r[2]*SCALE - 0.5f;
    float x2 = r[3]*SCALE - 0.5f;
    float y2 = r[4]*SCALE - 0.5f;
    float rw = x2 - x1, rh = y2 - y1;
    float bw = rw * (1.0f/OW), bh = rh * (1.0f/OH);
    const uint4* fb = (const uint4*)(g_feath + (size_t)b*HW*CH);
    const int C8 = CH/8;

    for (int b0 = 0; b0 < NBIN; b0 += 8) {
        int bin = b0 + bq;
        if (bin < NBIN) {
            int ph = bin / OW, pw = bin - ph*OW;
            float sw_ = x1, sh_ = y1;
            if (HAS_OFF) {
                sw_ += GAMMA * rw * off[roi*NOFF + bin];
                sh_ += GAMMA * rh * off[roi*NOFF + NBIN + bin];
            }
            float acc[8] = {};
            #pragma unroll
            for (int iy = 0; iy < 2; iy++) {
                float y = sh_ + ((float)ph + ((float)iy + 0.5f)*0.5f) * bh;
                #pragma unroll
                for (int ix = 0; ix < 2; ix++) {
                    float x = sw_ + ((float)pw + ((float)ix + 0.5f)*0.5f) * bw;
                    if (y > -1.0f && y < (float)FH && x > -1.0f && x < (float)FW) {
                        float yc = fminf(fmaxf(y, 0.0f), (float)(FH-1));
                        float xc = fminf(fmaxf(x, 0.0f), (float)(FW-1));
                        int y0 = min((int)floorf(yc), FH-2);
                        int x0 = min((int)floorf(xc), FW-2);
                        float ly = yc - (float)y0, lx = xc - (float)x0;
                        float hy = 1.0f - ly,     hx = 1.0f - lx;
                        float w00 = hy*hx, w01 = hy*lx, w10 = ly*hx, w11 = ly*lx;
                        const uint4* p = fb + ((size_t)y0*FW + x0)*C8 + cg;
                        uint4 v00 = p[0];
                        uint4 v01 = p[C8];
                        uint4 v10 = p[FW*C8];
                        uint4 v11 = p[FW*C8 + C8];
                        const uint32_t* u00 = &v00.x;
                        const uint32_t* u01 = &v01.x;
                        const uint32_t* u10 = &v10.x;
                        const uint32_t* u11 = &v11.x;
                        #pragma unroll
                        for (int q = 0; q < 4; q++) {
                            float2 f00 = __half22float2(*(const __half2*)&u00[q]);
                            float2 f01 = __half22float2(*(const __half2*)&u01[q]);
                            float2 f10 = __half22float2(*(const __half2*)&u10[q]);
                            float2 f11 = __half22float2(*(const __half2*)&u11[q]);
                            acc[2*q]   += w00*f00.x + w01*f01.x + w10*f10.x + w11*f11.x;
                            acc[2*q+1] += w00*f00.y + w01*f01.y + w10*f10.y + w11*f11.y;
                        }
                    }
                }
            }
            int c = cg*8;
            #pragma unroll
            for (int j = 0; j < 8; j++)
                sout[(c+j)*NBIN + bin] = acc[j] * 0.25f;
        }
    }
    __syncthreads();
    float* o = out + (size_t)roi * FDIM;
    if (EMIT_HALF) {
        __half* oh = out_h + (size_t)roi * FDIM;
        for (int i = tid; i < FDIM; i += 256) {
            float v = sout[i];
            o[i] = v;
            oh[i] = __float2half_rn(v);
        }
    } else {
        for (int i = tid; i < FDIM; i += 256) o[i] = sout[i];
    }
}

// ---------------- rescale head (float4-vectorized) + new_rois ---------------
#define FDIM4 (FDIM/4)   // 3136
__global__ void rescale_newrois(const float* __restrict__ flat,
                                const float* __restrict__ rois,
                                const float* __restrict__ w,
                                const float* __restrict__ bias) {
    int roi = blockIdx.x;
    int tid = threadIdx.x;       // 256
    const float4* f  = (const float4*)(flat + (size_t)roi * FDIM);
    const float4* w0 = (const float4*)w;
    const float4* w1 = w0 + FDIM4;
    const float4* w2 = w1 + FDIM4;
    const float4* w3 = w2 + FDIM4;
    float s0 = 0.f, s1 = 0.f, s2 = 0.f, s3 = 0.f;
    for (int k = tid; k < FDIM4; k += 256) {
        float4 v = f[k];
        float4 a = w0[k], b = w1[k], c = w2[k], d = w3[k];
        s0 += v.x*a.x + v.y*a.y + v.z*a.z + v.w*a.w;
        s1 += v.x*b.x + v.y*b.y + v.z*b.z + v.w*b.w;
        s2 += v.x*c.x + v.y*c.y + v.z*c.z + v.w*c.w;
        s3 += v.x*d.x + v.y*d.y + v.z*d.z + v.w*d.w;
    }
    #pragma unroll
    for (int o = 16; o > 0; o >>= 1) {
        s0 += __shfl_down_sync(0xffffffffu, s0, o);
        s1 += __shfl_down_sync(0xffffffffu, s1, o);
        s2 += __shfl_down_sync(0xffffffffu, s2, o);
        s3 += __shfl_down_sync(0xffffffffu, s3, o);
    }
    __shared__ float red[4][8];
    int lane = tid & 31, warp = tid >> 5;
    if (lane == 0) { red[0][warp]=s0; red[1][warp]=s1; red[2][warp]=s2; red[3][warp]=s3; }
    __syncthreads();
    if (tid == 0) {
        float d[4];
        #pragma unroll
        for (int j = 0; j < 4; j++) {
            float t = 0.f;
            #pragma unroll
            for (int ww = 0; ww < 8; ww++) t += red[j][ww];
            d[j] = 1.0f + 0.5f / (1.0f + expf(-(t + bias[j])));
        }
        const float* r = rois + roi*5;
        float cx = (r[1] + r[3]) * 0.5f + d[0];
        float cy = (r[2] + r[4]) * 0.5f + d[1];
        float nw = (r[3] - r[1]) * d[2];
        float nh = (r[4] - r[2]) * d[3];
        float* nr = g_nrois + roi*5;
        nr[0] = r[0];
        nr[1] = cx - 0.5f*nw;  nr[2] = cy - 0.5f*nh;
        nr[3] = cx + 0.5f*nw;  nr[4] = cy + 0.5f*nh;
    }
}

// ---------------- fp16 tensor-core NT GEMM, 128x128x32, cp.async ------------
// P[kz][M][N] partial = A[M,Ks] * B[N,Ks]^T. M, N multiples of 128.
// 256 threads, 8 warps (2x4), warp tile 64x32.
// smem word layout: word(m, kw) at m*16 + (kw ^ (((m>>1)&3)<<2)).

__device__ __forceinline__ void mma_f16(float* c, uint32_t a0, uint32_t a1,
                                        uint32_t a2, uint32_t a3,
                                        uint32_t b0, uint32_t b1) {
    asm volatile(
        "mma.sync.aligned.m16n8k16.row.col.f32.f16.f16.f32 "
        "{%0,%1,%2,%3}, {%4,%5,%6,%7}, {%8,%9}, {%0,%1,%2,%3};"
        : "+f"(c[0]), "+f"(c[1]), "+f"(c[2]), "+f"(c[3])
        : "r"(a0), "r"(a1), "r"(a2), "r"(a3), "r"(b0), "r"(b1));
}
__device__ __forceinline__ uint32_t s2u(const void* p) {
    return (uint32_t)__cvta_generic_to_shared(p);
}
__device__ __forceinline__ void cp16(uint32_t dst, const void* src) {
    asm volatile("cp.async.cg.shared.global [%0], [%1], 16;" :: "r"(dst), "l"(src));
}

__global__ void __launch_bounds__(256, 2)
gemm_h(const __half* __restrict__ A, const __half* __restrict__ B,
       float* __restrict__ P, int N, int K) {
    const int BM = 128, BN = 128;
    __shared__ __align__(16) uint32_t As[2][BM*16];
    __shared__ __align__(16) uint32_t Bs[2][BN*16];

    int tid  = threadIdx.x;
    int lane = tid & 31, w = tid >> 5;
    int g = lane >> 2, tig = lane & 3;
    int wm = w >> 2, wn = w & 3;               // 2 x 4 warp grid
    int bm = blockIdx.y * BM, bn = blockIdx.x * BN;
    int S  = gridDim.z, kz = blockIdx.z;
    int Ks = K / S;
    int M  = gridDim.y * BM;
    int nst = Ks >> 5;

    // producer: rows lm and lm+64 of A and B, 16B each per stage via cp.async
    int lm = tid >> 2, lq = tid & 3;
    const __half* Ap0 = A + (size_t)(bm + lm)*K + (size_t)kz*Ks + lq*8;
    const __half* Ap1 = Ap0 + (size_t)64*K;
    const __half* Bp0 = B + (size_t)(bn + lm)*K + (size_t)kz*Ks + lq*8;
    const __half* Bp1 = Bp0 + (size_t)64*K;
    int sc = lq ^ ((lm >> 1) & 3);
    int sw0 = lm*16 + sc*4;
    int sw1 = (lm + 64)*16 + sc*4;
    uint32_t sa0[2], sa1[2], sb0[2], sb1[2];
    #pragma unroll
    for (int b2 = 0; b2 < 2; b2++) {
        sa0[b2] = s2u(&As[b2][sw0]);  sa1[b2] = s2u(&As[b2][sw1]);
        sb0[b2] = s2u(&Bs[b2][sw0]);  sb1[b2] = s2u(&Bs[b2][sw1]);
    }

    float acc[4][4][4];
    #pragma unroll
    for (int i = 0; i < 4; i++)
        #pragma unroll
        for (int j = 0; j < 4; j++)
            #pragma unroll
            for (int q = 0; q < 4; q++) acc[i][j][q] = 0.0f;

    int mrow[4], mj[4];
    #pragma unroll
    for (int ii = 0; ii < 4; ii++) {
        mrow[ii] = wm*64 + ii*16 + g;
        mj[ii] = ((mrow[ii] >> 1) & 3) << 2;
    }
    int nrow[4], nj[4];
    #pragma unroll
    for (int jj = 0; jj < 4; jj++) {
        nrow[jj] = wn*32 + jj*8 + g;
        nj[jj] = ((nrow[jj] >> 1) & 3) << 2;
    }

    // prologue: stage 0 -> buf 0
    cp16(sa0[0], Ap0);  cp16(sa1[0], Ap1);
    cp16(sb0[0], Bp0);  cp16(sb1[0], Bp1);
    asm volatile("cp.async.commit_group;");

    for (int s = 0; s < nst; s++) {
        int buf = s & 1;
        if (s + 1 < nst) {
            int nb = buf ^ 1;
            size_t o = (size_t)(s+1)*32;
            cp16(sa0[nb], Ap0 + o);  cp16(sa1[nb], Ap1 + o);
            cp16(sb0[nb], Bp0 + o);  cp16(sb1[nb], Bp1 + o);
            asm volatile("cp.async.commit_group;");
            asm volatile("cp.async.wait_group 1;");
        } else {
            asm volatile("cp.async.wait_group 0;");
        }
        __syncthreads();                       // stage s visible block-wide
        const uint32_t* as = As[buf];
        const uint32_t* bs = Bs[buf];
        #pragma unroll
        for (int kb = 0; kb < 2; kb++) {
            int kw0 = kb*8 + tig, kw1 = kw0 + 4;
            uint32_t af[4][4], bf[4][2];
            #pragma unroll
            for (int jj = 0; jj < 4; jj++) {
                int rn = nrow[jj]*16, x = nj[jj];
                bf[jj][0] = bs[rn + (kw0 ^ x)];
                bf[jj][1] = bs[rn + (kw1 ^ x)];
            }
            #pragma unroll
            for (int ii = 0; ii < 4; ii++) {
                int r0 = mrow[ii]*16, r1 = (mrow[ii]+8)*16, x = mj[ii];
                af[ii][0] = as[r0 + (kw0 ^ x)];
                af[ii][1] = as[r1 + (kw0 ^ x)];
                af[ii][2] = as[r0 + (kw1 ^ x)];
                af[ii][3] = as[r1 + (kw1 ^ x)];
            }
            #pragma unroll
            for (int ii = 0; ii < 4; ii++)
                #pragma unroll
                for (int jj = 0; jj < 4; jj++)
                    mma_f16(acc[ii][jj], af[ii][0], af[ii][1], af[ii][2], af[ii][3],
                            bf[jj][0], bf[jj][1]);
        }
        __syncthreads();                       // all reads of buf done before reuse
    }

    float* Pp = P + (size_t)kz * M * N;
    #pragma unroll
    for (int ii = 0; ii < 4; ii++) {
        #pragma unroll
        for (int jj = 0; jj < 4; jj++) {
            int r0 = bm + wm*64 + ii*16 + g;
            int c0 = bn + wn*32 + jj*8 + tig*2;
            Pp[(size_t)r0*N + c0]       = acc[ii][jj][0];
            Pp[(size_t)r0*N + c0 + 1]   = acc[ii][jj][1];
            Pp[(size_t)(r0+8)*N + c0]   = acc[ii][jj][2];
            Pp[(size_t)(r0+8)*N + c0+1] = acc[ii][jj][3];
        }
    }
}

// -------- split-K combine: act(sum_s P_s + bias); half or float out ---------
template<bool RELU, bool TOHALF>
__global__ void combine(const float* __restrict__ P, const float* __restrict__ bias,
                        float* __restrict__ outf, __half* __restrict__ outh,
                        int M, int Ntot, int Nlog, int S) {
    int i = blockIdx.x * 256 + threadIdx.x;
    if (i >= M*Nlog) return;
    int m = i / Nlog, n = i - m*Nlog;
    float v = bias[n];
    for (int s = 0; s < S; s++)
        v += P[((size_t)s*M + m)*Ntot + n];
    if (RELU) v = fmaxf(v, 0.0f);
    if (TOHALF) outh[i] = __float2half_rn(v);
    else        outf[i] = v;
}

// ---------------- launch -----------------------------------------------------
extern "C" void kernel_launch(void* const* d_in, const int* in_sizes, int n_in,
                              void* d_out, int out_size) {
    const float* input     = (const float*)d_in[0];
    const float* rois      = (const float*)d_in[1];
    const float* rescale_w = (const float*)d_in[2];
    const float* rescale_b = (const float*)d_in[3];
    const float* off_w1    = (const float*)d_in[4];
    const float* off_b1    = (const float*)d_in[5];
    const float* off_w2    = (const float*)d_in[6];
    const float* off_b2    = (const float*)d_in[7];
    const float* off_w3    = (const float*)d_in[8];
    const float* off_b3    = (const float*)d_in[9];

    float* xcls = (float*)d_out;
    float* xreg = xcls + (size_t)NROIS * FDIM;

    __half *a1p, *w1p, *w2p, *w3p, *h1p, *h2p;
    float *offp, *nroisp, *partp;
    cudaGetSymbolAddress((void**)&a1p,    g_a1h);
    cudaGetSymbolAddress((void**)&w1p,    g_w1h);
    cudaGetSymbolAddress((void**)&w2p,    g_w2h);
    cudaGetSymbolAddress((void**)&w3p,    g_w3h);
    cudaGetSymbolAddress((void**)&h1p,    g_h1h);
    cudaGetSymbolAddress((void**)&h2p,    g_h2h);
    cudaGetSymbolAddress((void**)&offp,   g_off);
    cudaGetSymbolAddress((void**)&nroisp, g_nrois);
    cudaGetSymbolAddress((void**)&partp,  g_part);

    const int smem_pool = FDIM * sizeof(float);
    cudaFuncSetAttribute((const void*)roi_pool<false,true>,
                         cudaFuncAttributeMaxDynamicSharedMemorySize, smem_pool);
    cudaFuncSetAttribute((const void*)roi_pool<true,false>,
                         cudaFuncAttributeMaxDynamicSharedMemorySize, smem_pool);

    // 1) transpose to NHWC fp16 + fused weight half-conversion
    nchw2nhwc_h<<<dim3(HW/32, CH/64, BATCH), dim3(32, 8)>>>(input);
    cvt_weights<<<(W1_8 + W2_8 + W3_8 + 255)/256, 256>>>(off_w1, off_w2, off_w3);
    // 2) x_cls pool -> d_out (fp32) + g_a1h (half)
    roi_pool<false,true><<<NROIS, 256, smem_pool>>>(rois, nullptr, xcls, a1p);
    // 3) rescale head (fp32, float4) + new_rois
    rescale_newrois<<<NROIS, 256>>>(xcls, rois, rescale_w, rescale_b);
    // 4) offset MLP: fp16 tensor cores (128x128 tiles, cp.async), split-K + combine
    gemm_h<<<dim3(DFC/128, NROIS/128, 8), 256>>>(a1p, w1p, partp, DFC, FDIM);
    combine<true,true><<<(NROIS*DFC + 255)/256, 256>>>(partp, off_b1, nullptr, h1p,
                                                       NROIS, DFC, DFC, 8);
    gemm_h<<<dim3(DFC/128, NROIS/128, 8), 256>>>(h1p, w2p, partp, DFC, DFC);
    combine<true,true><<<(NROIS*DFC + 255)/256, 256>>>(partp, off_b2, nullptr, h2p,
                                                       NROIS, DFC, DFC, 8);
    gemm_h<<<dim3(1, NROIS/128, 8), 256>>>(h2p, w3p, partp, NOFFP, DFC);
    combine<false,false><<<(NROIS*NOFF + 255)/256, 256>>>(partp, off_b3, offp, nullptr,
                                                          NROIS, NOFFP, NOFF, 8);
    // 5) x_reg pool (new rois + offsets) -> second half of d_out
    roi_pool<true,false><<<NROIS, 256, smem_pool>>>(nroisp, offp, xreg, nullptr);
}

// round 11
// speedup vs baseline: 6.4218x; 1.0346x over previous
#include <cuda_runtime.h>
#include <cuda_fp16.h>
#include <math.h>
#include <stdint.h>

#define BATCH 4
#define CH    256
#define FH    100
#define FW    152
#define HW    (FH*FW)          // 15200
#define NROIS 512
#define OH    7
#define OW    7
#define NBIN  49
#define FDIM  (CH*NBIN)        // 12544
#define DFC   1024
#define NOFF  98               // 2*49
#define NOFFP 128              // padded for GEMM3
#define SCALE 0.0625f
#define GAMMA 0.1f
#define SKMAX 8

// ---------------- scratch (device globals; no allocation allowed) -----------
__device__ __half g_feath[(size_t)BATCH*HW*CH];  // NHWC fp16 features, 31 MB
__device__ __half g_a1h[(size_t)NROIS*FDIM];     // half(xcls) 12.8 MB
__device__ __half g_w1h[(size_t)DFC*FDIM];       // half(w1) 25.7 MB
__device__ __half g_w2h[(size_t)DFC*DFC];        // half(w2) 2 MB
__device__ __half g_w3h[(size_t)NOFFP*DFC];      // half(w3), zero-padded rows
__device__ __half g_h1h[NROIS*DFC];
__device__ __half g_h2h[NROIS*DFC];
__device__ float  g_off[NROIS*NOFF];
__device__ float  g_nrois[NROIS*5];
__device__ float  g_part[(size_t)SKMAX*NROIS*DFC]; // split-K partials (16 MB)

// ---------------- NCHW -> NHWC fp16 transpose -------------------------------
__global__ void nchw2nhwc_h(const float* __restrict__ in) {
    __shared__ float tile[64][33];
    int b   = blockIdx.z;
    int hw0 = blockIdx.x * 32;
    int c0  = blockIdx.y * 64;
    #pragma unroll
    for (int r = 0; r < 8; r++) {
        int c  = c0 + threadIdx.y + r*8;
        int hw = hw0 + threadIdx.x;
        tile[threadIdx.y + r*8][threadIdx.x] = in[((size_t)b*CH + c)*HW + hw];
    }
    __syncthreads();
    __half2* out2 = (__half2*)g_feath;
    #pragma unroll
    for (int r = 0; r < 4; r++) {
        int hwl = threadIdx.y + r*8;
        int hw  = hw0 + hwl;
        int c2  = threadIdx.x;
        float lo = tile[2*c2][hwl];
        float hi = tile[2*c2+1][hwl];
        out2[((size_t)b*HW + hw)*(CH/2) + c0/2 + c2] = __floats2half2_rn(lo, hi);
    }
}

// ---------------- fused fp32 -> fp16 weight conversion ----------------------
__device__ __forceinline__ uint32_t h2u(__half2 h) { return *reinterpret_cast<uint32_t*>(&h); }
__device__ __forceinline__ uint4 f8toh8(const float4* s) {
    float4 a = s[0], b = s[1];
    uint4 o;
    o.x = h2u(__floats2half2_rn(a.x, a.y));
    o.y = h2u(__floats2half2_rn(a.z, a.w));
    o.z = h2u(__floats2half2_rn(b.x, b.y));
    o.w = h2u(__floats2half2_rn(b.z, b.w));
    return o;
}

#define W1_8 (DFC*FDIM/8)
#define W2_8 (DFC*DFC/8)
#define W3_8 (NOFFP*DFC/8)

__global__ void cvt_weights(const float* __restrict__ w1,
                            const float* __restrict__ w2,
                            const float* __restrict__ w3) {
    int i = blockIdx.x * 256 + threadIdx.x;
    if (i < W1_8) {
        ((uint4*)g_w1h)[i] = f8toh8((const float4*)(w1 + (size_t)i*8));
    } else if (i < W1_8 + W2_8) {
        int j = i - W1_8;
        ((uint4*)g_w2h)[j] = f8toh8((const float4*)(w2 + (size_t)j*8));
    } else if (i < W1_8 + W2_8 + W3_8) {
        int j = i - W1_8 - W2_8;
        int r = (j*8) >> 10;
        uint4 o;
        if (r < NOFF) o = f8toh8((const float4*)(w3 + (size_t)j*8));
        else          o.x = o.y = o.z = o.w = 0u;
        ((uint4*)g_w3h)[j] = o;
    }
}

// ---------------- deformable RoI pool (fp16 features, fp32 math) ------------
template<bool HAS_OFF, bool EMIT_HALF>
__global__ void roi_pool(const float* __restrict__ rois,
                         const float* __restrict__ off,
                         float* __restrict__ out,
                         __half* __restrict__ out_h) {
    extern __shared__ float sout[];           // FDIM floats
    int roi = blockIdx.x;
    int tid = threadIdx.x;
    int bq = tid >> 5, cg = tid & 31;
    const float* r = rois + roi*5;
    int   b  = (int)r[0];
    float x1 = r[1]*SCALE - 0.5f;
    float y1 = r[2]*SCALE - 0.5f;
    float x2 = r[3]*SCALE - 0.5f;
    float y2 = r[4]*SCALE - 0.5f;
    float rw = x2 - x1, rh = y2 - y1;
    float bw = rw * (1.0f/OW), bh = rh * (1.0f/OH);
    const uint4* fb = (const uint4*)(g_feath + (size_t)b*HW*CH);
    const int C8 = CH/8;

    for (int b0 = 0; b0 < NBIN; b0 += 8) {
        int bin = b0 + bq;
        if (bin < NBIN) {
            int ph = bin / OW, pw = bin - ph*OW;
            float sw_ = x1, sh_ = y1;
            if (HAS_OFF) {
                sw_ += GAMMA * rw * off[roi*NOFF + bin];
                sh_ += GAMMA * rh * off[roi*NOFF + NBIN + bin];
            }
            float acc[8] = {};
            #pragma unroll
            for (int iy = 0; iy < 2; iy++) {
                float y = sh_ + ((float)ph + ((float)iy + 0.5f)*0.5f) * bh;
                #pragma unroll
                for (int ix = 0; ix < 2; ix++) {
                    float x = sw_ + ((float)pw + ((float)ix + 0.5f)*0.5f) * bw;
                    if (y > -1.0f && y < (float)FH && x > -1.0f && x < (float)FW) {
                        float yc = fminf(fmaxf(y, 0.0f), (float)(FH-1));
                        float xc = fminf(fmaxf(x, 0.0f), (float)(FW-1));
                        int y0 = min((int)floorf(yc), FH-2);
                        int x0 = min((int)floorf(xc), FW-2);
                        float ly = yc - (float)y0, lx = xc - (float)x0;
                        float hy = 1.0f - ly,     hx = 1.0f - lx;
                        float w00 = hy*hx, w01 = hy*lx, w10 = ly*hx, w11 = ly*lx;
                        const uint4* p = fb + ((size_t)y0*FW + x0)*C8 + cg;
                        uint4 v00 = p[0];
                        uint4 v01 = p[C8];
                        uint4 v10 = p[FW*C8];
                        uint4 v11 = p[FW*C8 + C8];
                        const uint32_t* u00 = &v00.x;
                        const uint32_t* u01 = &v01.x;
                        const uint32_t* u10 = &v10.x;
                        const uint32_t* u11 = &v11.x;
                        #pragma unroll
                        for (int q = 0; q < 4; q++) {
                            float2 f00 = __half22float2(*(const __half2*)&u00[q]);
                            float2 f01 = __half22float2(*(const __half2*)&u01[q]);
                            float2 f10 = __half22float2(*(const __half2*)&u10[q]);
                            float2 f11 = __half22float2(*(const __half2*)&u11[q]);
                            acc[2*q]   += w00*f00.x + w01*f01.x + w10*f10.x + w11*f11.x;
                            acc[2*q+1] += w00*f00.y + w01*f01.y + w10*f10.y + w11*f11.y;
                        }
                    }
                }
            }
            int c = cg*8;
            #pragma unroll
            for (int j = 0; j < 8; j++)
                sout[(c+j)*NBIN + bin] = acc[j] * 0.25f;
        }
    }
    __syncthreads();
    float* o = out + (size_t)roi * FDIM;
    if (EMIT_HALF) {
        __half* oh = out_h + (size_t)roi * FDIM;
        for (int i = tid; i < FDIM; i += 256) {
            float v = sout[i];
            o[i] = v;
            oh[i] = __float2half_rn(v);
        }
    } else {
        for (int i = tid; i < FDIM; i += 256) o[i] = sout[i];
    }
}

// ------ rescale head (reads fp16 flat, fp32 weights) + new_rois -------------
#define FDIM8 (FDIM/8)   // 1568
__global__ void rescale_newrois(const __half* __restrict__ flath,
                                const float* __restrict__ rois,
                                const float* __restrict__ w,
                                const float* __restrict__ bias) {
    int roi = blockIdx.x;
    int tid = threadIdx.x;       // 256
    const uint4* f = (const uint4*)(flath + (size_t)roi * FDIM);
    float s[4] = {0.f, 0.f, 0.f, 0.f};
    for (int k = tid; k < FDIM8; k += 256) {
        uint4 hv = f[k];
        const uint32_t* hu = &hv.x;
        float v[8];
        #pragma unroll
        for (int q = 0; q < 4; q++) {
            float2 t = __half22float2(*(const __half2*)&hu[q]);
            v[2*q] = t.x; v[2*q+1] = t.y;
        }
        #pragma unroll
        for (int j = 0; j < 4; j++) {
            const float4* wj = (const float4*)(w + (size_t)j*FDIM) + 2*k;
            float4 a = wj[0], b2 = wj[1];
            s[j] += v[0]*a.x + v[1]*a.y + v[2]*a.z + v[3]*a.w
                  + v[4]*b2.x + v[5]*b2.y + v[6]*b2.z + v[7]*b2.w;
        }
    }
    #pragma unroll
    for (int o = 16; o > 0; o >>= 1) {
        #pragma unroll
        for (int j = 0; j < 4; j++)
            s[j] += __shfl_down_sync(0xffffffffu, s[j], o);
    }
    __shared__ float red[4][8];
    int lane = tid & 31, warp = tid >> 5;
    if (lane == 0) { red[0][warp]=s[0]; red[1][warp]=s[1]; red[2][warp]=s[2]; red[3][warp]=s[3]; }
    __syncthreads();
    if (tid == 0) {
        float d[4];
        #pragma unroll
        for (int j = 0; j < 4; j++) {
            float t = 0.f;
            #pragma unroll
            for (int ww = 0; ww < 8; ww++) t += red[j][ww];
            d[j] = 1.0f + 0.5f / (1.0f + expf(-(t + bias[j])));
        }
        const float* r = rois + roi*5;
        float cx = (r[1] + r[3]) * 0.5f + d[0];
        float cy = (r[2] + r[4]) * 0.5f + d[1];
        float nw = (r[3] - r[1]) * d[2];
        float nh = (r[4] - r[2]) * d[3];
        float* nr = g_nrois + roi*5;
        nr[0] = r[0];
        nr[1] = cx - 0.5f*nw;  nr[2] = cy - 0.5f*nh;
        nr[3] = cx + 0.5f*nw;  nr[4] = cy + 0.5f*nh;
    }
}

// ------------ fp16 tensor-core NT GEMM, 128x128x32, 3-stage cp.async --------
__device__ __forceinline__ void mma_f16(float* c, uint32_t a0, uint32_t a1,
                                        uint32_t a2, uint32_t a3,
                                        uint32_t b0, uint32_t b1) {
    asm volatile(
        "mma.sync.aligned.m16n8k16.row.col.f32.f16.f16.f32 "
        "{%0,%1,%2,%3}, {%4,%5,%6,%7}, {%8,%9}, {%0,%1,%2,%3};"
        : "+f"(c[0]), "+f"(c[1]), "+f"(c[2]), "+f"(c[3])
        : "r"(a0), "r"(a1), "r"(a2), "r"(a3), "r"(b0), "r"(b1));
}
__device__ __forceinline__ uint32_t s2u(const void* p) {
    return (uint32_t)__cvta_generic_to_shared(p);
}
__device__ __forceinline__ void cp16(uint32_t dst, const void* src) {
    asm volatile("cp.async.cg.shared.global [%0], [%1], 16;" :: "r"(dst), "l"(src));
}

__global__ void __launch_bounds__(256, 2)
gemm_h(const __half* __restrict__ A, const __half* __restrict__ B,
       float* __restrict__ P, int N, int K) {
    const int BM = 128, BN = 128;
    __shared__ __align__(16) uint32_t As[3][BM*16];
    __shared__ __align__(16) uint32_t Bs[3][BN*16];

    int tid  = threadIdx.x;
    int lane = tid & 31, w = tid >> 5;
    int g = lane >> 2, tig = lane & 3;
    int wm = w >> 2, wn = w & 3;               // 2 x 4 warp grid
    int bm = blockIdx.y * BM, bn = blockIdx.x * BN;
    int S  = gridDim.z, kz = blockIdx.z;
    int Ks = K / S;
    int M  = gridDim.y * BM;
    int nst = Ks >> 5;

    int lm = tid >> 2, lq = tid & 3;
    const __half* Ap0 = A + (size_t)(bm + lm)*K + (size_t)kz*Ks + lq*8;
    const __half* Ap1 = Ap0 + (size_t)64*K;
    const __half* Bp0 = B + (size_t)(bn + lm)*K + (size_t)kz*Ks + lq*8;
    const __half* Bp1 = Bp0 + (size_t)64*K;
    int sc = lq ^ ((lm >> 1) & 3);
    int sw0 = lm*16 + sc*4;
    int sw1 = (lm + 64)*16 + sc*4;
    uint32_t sa0[3], sa1[3], sb0[3], sb1[3];
    #pragma unroll
    for (int b3 = 0; b3 < 3; b3++) {
        sa0[b3] = s2u(&As[b3][sw0]);  sa1[b3] = s2u(&As[b3][sw1]);
        sb0[b3] = s2u(&Bs[b3][sw0]);  sb1[b3] = s2u(&Bs[b3][sw1]);
    }

    float acc[4][4][4];
    #pragma unroll
    for (int i = 0; i < 4; i++)
        #pragma unroll
        for (int j = 0; j < 4; j++)
            #pragma unroll
            for (int q = 0; q < 4; q++) acc[i][j][q] = 0.0f;

    int mrow[4], mj[4];
    #pragma unroll
    for (int ii = 0; ii < 4; ii++) {
        mrow[ii] = wm*64 + ii*16 + g;
        mj[ii] = ((mrow[ii] >> 1) & 3) << 2;
    }
    int nrow[4], nj[4];
    #pragma unroll
    for (int jj = 0; jj < 4; jj++) {
        nrow[jj] = wn*32 + jj*8 + g;
        nj[jj] = ((nrow[jj] >> 1) & 3) << 2;
    }

    // prologue: stages 0 and 1
    cp16(sa0[0], Ap0);  cp16(sa1[0], Ap1);
    cp16(sb0[0], Bp0);  cp16(sb1[0], Bp1);
    asm volatile("cp.async.commit_group;");
    if (nst > 1) {
        cp16(sa0[1], Ap0 + 32);  cp16(sa1[1], Ap1 + 32);
        cp16(sb0[1], Bp0 + 32);  cp16(sb1[1], Bp1 + 32);
        asm volatile("cp.async.commit_group;");
    }

    int buf = 0;
    for (int s = 0; s < nst; s++) {
        if (s < nst - 1) asm volatile("cp.async.wait_group 1;");
        else             asm volatile("cp.async.wait_group 0;");
        __syncthreads();                       // stage s visible; compute(s-1) done

        const uint32_t* as = As[buf];
        const uint32_t* bs = Bs[buf];
        #pragma unroll
        for (int kb = 0; kb < 2; kb++) {
            int kw0 = kb*8 + tig, kw1 = kw0 + 4;
            uint32_t af[4][4], bf[4][2];
            #pragma unroll
            for (int jj = 0; jj < 4; jj++) {
                int rn = nrow[jj]*16, x = nj[jj];
                bf[jj][0] = bs[rn + (kw0 ^ x)];
                bf[jj][1] = bs[rn + (kw1 ^ x)];
            }
            #pragma unroll
            for (int ii = 0; ii < 4; ii++) {
                int r0 = mrow[ii]*16, r1 = (mrow[ii]+8)*16, x = mj[ii];
                af[ii][0] = as[r0 + (kw0 ^ x)];
                af[ii][1] = as[r1 + (kw0 ^ x)];
                af[ii][2] = as[r0 + (kw1 ^ x)];
                af[ii][3] = as[r1 + (kw1 ^ x)];
            }
            #pragma unroll
            for (int ii = 0; ii < 4; ii++)
                #pragma unroll
                for (int jj = 0; jj < 4; jj++)
                    mma_f16(acc[ii][jj], af[ii][0], af[ii][1], af[ii][2], af[ii][3],
                            bf[jj][0], bf[jj][1]);
        }

        if (s + 2 < nst) {
            int nb = buf;                       // (s+2)%3 == (s-1)%3 == old buf after rotation
            nb = (buf + 2) % 3;
            size_t o = (size_t)(s+2)*32;
            cp16(sa0[nb], Ap0 + o);  cp16(sa1[nb], Ap1 + o);
            cp16(sb0[nb], Bp0 + o);  cp16(sb1[nb], Bp1 + o);
            asm volatile("cp.async.commit_group;");
        }
        buf = (buf + 1) % 3;
    }

    float* Pp = P + (size_t)kz * M * N;
    #pragma unroll
    for (int ii = 0; ii < 4; ii++) {
        #pragma unroll
        for (int jj = 0; jj < 4; jj++) {
            int r0 = bm + wm*64 + ii*16 + g;
            int c0 = bn + wn*32 + jj*8 + tig*2;
            Pp[(size_t)r0*N + c0]       = acc[ii][jj][0];
            Pp[(size_t)r0*N + c0 + 1]   = acc[ii][jj][1];
            Pp[(size_t)(r0+8)*N + c0]   = acc[ii][jj][2];
            Pp[(size_t)(r0+8)*N + c0+1] = acc[ii][jj][3];
        }
    }
}

// -------- split-K combine (float4, half out): for N multiple of 4 -----------
__global__ void combine4h(const float* __restrict__ P, const float* __restrict__ bias,
                          __half* __restrict__ outh, int M, int N, int S) {
    int i = blockIdx.x * 256 + threadIdx.x;   // over M*N/4
    if (i >= M*N/4) return;
    int base = i*4;
    int m = base / N, n = base - m*N;
    float4 bv = *(const float4*)(bias + n);
    float4 v = bv;
    for (int s = 0; s < S; s++) {
        float4 p = *(const float4*)(P + ((size_t)s*M + m)*N + n);
        v.x += p.x; v.y += p.y; v.z += p.z; v.w += p.w;
    }
    v.x = fmaxf(v.x, 0.f); v.y = fmaxf(v.y, 0.f);
    v.z = fmaxf(v.z, 0.f); v.w = fmaxf(v.w, 0.f);
    uint2 o;
    o.x = h2u(__floats2half2_rn(v.x, v.y));
    o.y = h2u(__floats2half2_rn(v.z, v.w));
    *(uint2*)(outh + base) = o;
}

// -------- scalar combine (float out, ragged N) for the final layer ----------
__global__ void combine_f(const float* __restrict__ P, const float* __restrict__ bias,
                          float* __restrict__ outf, int M, int Ntot, int Nlog, int S) {
    int i = blockIdx.x * 256 + threadIdx.x;
    if (i >= M*Nlog) return;
    int m = i / Nlog, n = i - m*Nlog;
    float v = bias[n];
    for (int s = 0; s < S; s++)
        v += P[((size_t)s*M + m)*Ntot + n];
    outf[i] = v;
}

// ---------------- launch -----------------------------------------------------
extern "C" void kernel_launch(void* const* d_in, const int* in_sizes, int n_in,
                              void* d_out, int out_size) {
    const float* input     = (const float*)d_in[0];
    const float* rois      = (const float*)d_in[1];
    const float* rescale_w = (const float*)d_in[2];
    const float* rescale_b = (const float*)d_in[3];
    const float* off_w1    = (const float*)d_in[4];
    const float* off_b1    = (const float*)d_in[5];
    const float* off_w2    = (const float*)d_in[6];
    const float* off_b2    = (const float*)d_in[7];
    const float* off_w3    = (const float*)d_in[8];
    const float* off_b3    = (const float*)d_in[9];

    float* xcls = (float*)d_out;
    float* xreg = xcls + (size_t)NROIS * FDIM;

    __half *a1p, *w1p, *w2p, *w3p, *h1p, *h2p;
    float *offp, *nroisp, *partp;
    cudaGetSymbolAddress((void**)&a1p,    g_a1h);
    cudaGetSymbolAddress((void**)&w1p,    g_w1h);
    cudaGetSymbolAddress((void**)&w2p,    g_w2h);
    cudaGetSymbolAddress((void**)&w3p,    g_w3h);
    cudaGetSymbolAddress((void**)&h1p,    g_h1h);
    cudaGetSymbolAddress((void**)&h2p,    g_h2h);
    cudaGetSymbolAddress((void**)&offp,   g_off);
    cudaGetSymbolAddress((void**)&nroisp, g_nrois);
    cudaGetSymbolAddress((void**)&partp,  g_part);

    const int smem_pool = FDIM * sizeof(float);
    cudaFuncSetAttribute((const void*)roi_pool<false,true>,
                         cudaFuncAttributeMaxDynamicSharedMemorySize, smem_pool);
    cudaFuncSetAttribute((const void*)roi_pool<true,false>,
                         cudaFuncAttributeMaxDynamicSharedMemorySize, smem_pool);

    // 1) transpose to NHWC fp16 + fused weight half-conversion
    nchw2nhwc_h<<<dim3(HW/32, CH/64, BATCH), dim3(32, 8)>>>(input);
    cvt_weights<<<(W1_8 + W2_8 + W3_8 + 255)/256, 256>>>(off_w1, off_w2, off_w3);
    // 2) x_cls pool -> d_out (fp32) + g_a1h (half)
    roi_pool<false,true><<<NROIS, 256, smem_pool>>>(rois, nullptr, xcls, a1p);
    // 3) rescale head (fp16 flat, fp32 weights) + new_rois
    rescale_newrois<<<NROIS, 256>>>(a1p, rois, rescale_w, rescale_b);
    // 4) offset MLP: fp16 tensor cores (3-stage cp.async), split-K + combine
    gemm_h<<<dim3(DFC/128, NROIS/128, 8), 256>>>(a1p, w1p, partp, DFC, FDIM);
    combine4h<<<(NROIS*DFC/4 + 255)/256, 256>>>(partp, off_b1, h1p, NROIS, DFC, 8);
    gemm_h<<<dim3(DFC/128, NROIS/128, 8), 256>>>(h1p, w2p, partp, DFC, DFC);
    combine4h<<<(NROIS*DFC/4 + 255)/256, 256>>>(partp, off_b2, h2p, NROIS, DFC, 8);
    gemm_h<<<dim3(1, NROIS/128, 8), 256>>>(h2p, w3p, partp, NOFFP, DFC);
    combine_f<<<(NROIS*NOFF + 255)/256, 256>>>(partp, off_b3, offp, NROIS, NOFFP, NOFF, 8);
    // 5) x_reg pool (new rois + offsets) -> second half of d_out
    roi_pool<true,false><<<NROIS, 256, smem_pool>>>(nroisp, offp, xreg, nullptr);
}

// round 12
// speedup vs baseline: 6.7873x; 1.0569x over previous
#include <cuda_runtime.h>
#include <cuda_fp16.h>
#include <math.h>
#include <stdint.h>

#define BATCH 4
#define CH    256
#define FH    100
#define FW    152
#define HW    (FH*FW)          // 15200
#define NROIS 512
#define OH    7
#define OW    7
#define NBIN  49
#define FDIM  (CH*NBIN)        // 12544
#define DFC   1024
#define NOFF  98               // 2*49
#define NOFFP 128              // padded for GEMM3
#define SCALE 0.0625f
#define GAMMA 0.1f
#define SKMAX 8

// ---------------- scratch (device globals; no allocation allowed) -----------
__device__ __half g_feath[(size_t)BATCH*HW*CH];  // NHWC fp16 features, 31 MB
__device__ __half g_a1h[(size_t)NROIS*FDIM];     // half(xcls) 12.8 MB
__device__ __half g_w1h[(size_t)DFC*FDIM];       // half(w1) 25.7 MB
__device__ __half g_w2h[(size_t)DFC*DFC];        // half(w2) 2 MB
__device__ __half g_w3h[(size_t)NOFFP*DFC];      // half(w3), zero-padded rows
__device__ __half g_h1h[NROIS*DFC];
__device__ __half g_h2h[NROIS*DFC];
__device__ float  g_off[NROIS*NOFF];
__device__ float  g_nrois[NROIS*5];
__device__ float  g_part[(size_t)SKMAX*NROIS*DFC]; // split-K partials (16 MB)

// ---------------- NCHW -> NHWC fp16 transpose -------------------------------
__global__ void nchw2nhwc_h(const float* __restrict__ in) {
    __shared__ float tile[64][33];
    int b   = blockIdx.z;
    int hw0 = blockIdx.x * 32;
    int c0  = blockIdx.y * 64;
    #pragma unroll
    for (int r = 0; r < 8; r++) {
        int c  = c0 + threadIdx.y + r*8;
        int hw = hw0 + threadIdx.x;
        tile[threadIdx.y + r*8][threadIdx.x] = in[((size_t)b*CH + c)*HW + hw];
    }
    __syncthreads();
    __half2* out2 = (__half2*)g_feath;
    #pragma unroll
    for (int r = 0; r < 4; r++) {
        int hwl = threadIdx.y + r*8;
        int hw  = hw0 + hwl;
        int c2  = threadIdx.x;
        float lo = tile[2*c2][hwl];
        float hi = tile[2*c2+1][hwl];
        out2[((size_t)b*HW + hw)*(CH/2) + c0/2 + c2] = __floats2half2_rn(lo, hi);
    }
}

// ---------------- fused fp32 -> fp16 weight conversion ----------------------
__device__ __forceinline__ uint32_t h2u(__half2 h) { return *reinterpret_cast<uint32_t*>(&h); }
__device__ __forceinline__ uint4 f8toh8(const float4* s) {
    float4 a = s[0], b = s[1];
    uint4 o;
    o.x = h2u(__floats2half2_rn(a.x, a.y));
    o.y = h2u(__floats2half2_rn(a.z, a.w));
    o.z = h2u(__floats2half2_rn(b.x, b.y));
    o.w = h2u(__floats2half2_rn(b.z, b.w));
    return o;
}

#define W1_8 (DFC*FDIM/8)
#define W2_8 (DFC*DFC/8)
#define W3_8 (NOFFP*DFC/8)

__global__ void cvt_weights(const float* __restrict__ w1,
                            const float* __restrict__ w2,
                            const float* __restrict__ w3) {
    int i = blockIdx.x * 256 + threadIdx.x;
    if (i < W1_8) {
        ((uint4*)g_w1h)[i] = f8toh8((const float4*)(w1 + (size_t)i*8));
    } else if (i < W1_8 + W2_8) {
        int j = i - W1_8;
        ((uint4*)g_w2h)[j] = f8toh8((const float4*)(w2 + (size_t)j*8));
    } else if (i < W1_8 + W2_8 + W3_8) {
        int j = i - W1_8 - W2_8;
        int r = (j*8) >> 10;
        uint4 o;
        if (r < NOFF) o = f8toh8((const float4*)(w3 + (size_t)j*8));
        else          o.x = o.y = o.z = o.w = 0u;
        ((uint4*)g_w3h)[j] = o;
    }
}

// ------- deformable RoI pool: 2 CTAs per ROI (128 channels each) ------------
// grid (NROIS, 2); 256 threads = (16 bins in flight) x (16 groups of 8 ch).
#define POOL_CH   128
#define POOL_HALF (POOL_CH*NBIN)     // 6272 floats per half
template<bool HAS_OFF, bool EMIT_HALF>
__global__ void roi_pool(const float* __restrict__ rois,
                         const float* __restrict__ off,
                         float* __restrict__ out,
                         __half* __restrict__ out_h) {
    __shared__ float sout[POOL_HALF];         // 25 KB
    int roi = blockIdx.x;
    int cb  = blockIdx.y;                      // channel half: 0 or 1
    int tid = threadIdx.x;
    int bq = tid >> 4, cg = tid & 15;          // bin slot, 8-ch group (within half)
    const float* r = rois + roi*5;
    int   b  = (int)r[0];
    float x1 = r[1]*SCALE - 0.5f;
    float y1 = r[2]*SCALE - 0.5f;
    float x2 = r[3]*SCALE - 0.5f;
    float y2 = r[4]*SCALE - 0.5f;
    float rw = x2 - x1, rh = y2 - y1;
    float bw = rw * (1.0f/OW), bh = rh * (1.0f/OH);
    const uint4* fb = (const uint4*)(g_feath + (size_t)b*HW*CH);
    const int C8 = CH/8;                       // 32 uint4 per pixel
    int cgl = cb*16 + cg;                      // global 8-ch group index

    for (int b0 = 0; b0 < NBIN; b0 += 16) {
        int bin = b0 + bq;
        if (bin < NBIN) {
            int ph = bin / OW, pw = bin - ph*OW;
            float sw_ = x1, sh_ = y1;
            if (HAS_OFF) {
                sw_ += GAMMA * rw * off[roi*NOFF + bin];
                sh_ += GAMMA * rh * off[roi*NOFF + NBIN + bin];
            }
            float acc[8] = {};
            #pragma unroll
            for (int iy = 0; iy < 2; iy++) {
                float y = sh_ + ((float)ph + ((float)iy + 0.5f)*0.5f) * bh;
                #pragma unroll
                for (int ix = 0; ix < 2; ix++) {
                    float x = sw_ + ((float)pw + ((float)ix + 0.5f)*0.5f) * bw;
                    if (y > -1.0f && y < (float)FH && x > -1.0f && x < (float)FW) {
                        float yc = fminf(fmaxf(y, 0.0f), (float)(FH-1));
                        float xc = fminf(fmaxf(x, 0.0f), (float)(FW-1));
                        int y0 = min((int)floorf(yc), FH-2);
                        int x0 = min((int)floorf(xc), FW-2);
                        float ly = yc - (float)y0, lx = xc - (float)x0;
                        float hy = 1.0f - ly,     hx = 1.0f - lx;
                        float w00 = hy*hx, w01 = hy*lx, w10 = ly*hx, w11 = ly*lx;
                        const uint4* p = fb + ((size_t)y0*FW + x0)*C8 + cgl;
                        uint4 v00 = p[0];
                        uint4 v01 = p[C8];
                        uint4 v10 = p[FW*C8];
                        uint4 v11 = p[FW*C8 + C8];
                        const uint32_t* u00 = &v00.x;
                        const uint32_t* u01 = &v01.x;
                        const uint32_t* u10 = &v10.x;
                        const uint32_t* u11 = &v11.x;
                        #pragma unroll
                        for (int q = 0; q < 4; q++) {
                            float2 f00 = __half22float2(*(const __half2*)&u00[q]);
                            float2 f01 = __half22float2(*(const __half2*)&u01[q]);
                            float2 f10 = __half22float2(*(const __half2*)&u10[q]);
                            float2 f11 = __half22float2(*(const __half2*)&u11[q]);
                            acc[2*q]   += w00*f00.x + w01*f01.x + w10*f10.x + w11*f11.x;
                            acc[2*q+1] += w00*f00.y + w01*f01.y + w10*f10.y + w11*f11.y;
                        }
                    }
                }
            }
            int c = cg*8;                      // local channel within this half
            #pragma unroll
            for (int j = 0; j < 8; j++)
                sout[(c+j)*NBIN + bin] = acc[j] * 0.25f;
        }
    }
    __syncthreads();
    size_t base = (size_t)roi * FDIM + (size_t)cb * POOL_HALF;
    float* o = out + base;
    if (EMIT_HALF) {
        __half* oh = out_h + base;
        for (int i = tid; i < POOL_HALF; i += 256) {
            float v = sout[i];
            o[i] = v;
            oh[i] = __float2half_rn(v);
        }
    } else {
        for (int i = tid; i < POOL_HALF; i += 256) o[i] = sout[i];
    }
}

// ---------------- rescale head (fp32 flat, float4) + new_rois ---------------
#define FDIM4 (FDIM/4)   // 3136
__global__ void rescale_newrois(const float* __restrict__ flat,
                                const float* __restrict__ rois,
                                const float* __restrict__ w,
                                const float* __restrict__ bias) {
    int roi = blockIdx.x;
    int tid = threadIdx.x;       // 256
    const float4* f  = (const float4*)(flat + (size_t)roi * FDIM);
    const float4* w0 = (const float4*)w;
    const float4* w1 = w0 + FDIM4;
    const float4* w2 = w1 + FDIM4;
    const float4* w3 = w2 + FDIM4;
    float s0 = 0.f, s1 = 0.f, s2 = 0.f, s3 = 0.f;
    for (int k = tid; k < FDIM4; k += 256) {
        float4 v = f[k];
        float4 a = w0[k], b = w1[k], c = w2[k], d = w3[k];
        s0 += v.x*a.x + v.y*a.y + v.z*a.z + v.w*a.w;
        s1 += v.x*b.x + v.y*b.y + v.z*b.z + v.w*b.w;
        s2 += v.x*c.x + v.y*c.y + v.z*c.z + v.w*c.w;
        s3 += v.x*d.x + v.y*d.y + v.z*d.z + v.w*d.w;
    }
    #pragma unroll
    for (int o = 16; o > 0; o >>= 1) {
        s0 += __shfl_down_sync(0xffffffffu, s0, o);
        s1 += __shfl_down_sync(0xffffffffu, s1, o);
        s2 += __shfl_down_sync(0xffffffffu, s2, o);
        s3 += __shfl_down_sync(0xffffffffu, s3, o);
    }
    __shared__ float red[4][8];
    int lane = tid & 31, warp = tid >> 5;
    if (lane == 0) { red[0][warp]=s0; red[1][warp]=s1; red[2][warp]=s2; red[3][warp]=s3; }
    __syncthreads();
    if (tid == 0) {
        float d[4];
        #pragma unroll
        for (int j = 0; j < 4; j++) {
            float t = 0.f;
            #pragma unroll
            for (int ww = 0; ww < 8; ww++) t += red[j][ww];
            d[j] = 1.0f + 0.5f / (1.0f + expf(-(t + bias[j])));
        }
        const float* r = rois + roi*5;
        float cx = (r[1] + r[3]) * 0.5f + d[0];
        float cy = (r[2] + r[4]) * 0.5f + d[1];
        float nw = (r[3] - r[1]) * d[2];
        float nh = (r[4] - r[2]) * d[3];
        float* nr = g_nrois + roi*5;
        nr[0] = r[0];
        nr[1] = cx - 0.5f*nw;  nr[2] = cy - 0.5f*nh;
        nr[3] = cx + 0.5f*nw;  nr[4] = cy + 0.5f*nh;
    }
}

// ------------ fp16 tensor-core NT GEMM, 128x128x32, 3-stage cp.async --------
__device__ __forceinline__ void mma_f16(float* c, uint32_t a0, uint32_t a1,
                                        uint32_t a2, uint32_t a3,
                                        uint32_t b0, uint32_t b1) {
    asm volatile(
        "mma.sync.aligned.m16n8k16.row.col.f32.f16.f16.f32 "
        "{%0,%1,%2,%3}, {%4,%5,%6,%7}, {%8,%9}, {%0,%1,%2,%3};"
        : "+f"(c[0]), "+f"(c[1]), "+f"(c[2]), "+f"(c[3])
        : "r"(a0), "r"(a1), "r"(a2), "r"(a3), "r"(b0), "r"(b1));
}
__device__ __forceinline__ uint32_t s2u(const void* p) {
    return (uint32_t)__cvta_generic_to_shared(p);
}
__device__ __forceinline__ void cp16(uint32_t dst, const void* src) {
    asm volatile("cp.async.cg.shared.global [%0], [%1], 16;" :: "r"(dst), "l"(src));
}

__global__ void __launch_bounds__(256, 2)
gemm_h(const __half* __restrict__ A, const __half* __restrict__ B,
       float* __restrict__ P, int N, int K) {
    const int BM = 128, BN = 128;
    __shared__ __align__(16) uint32_t As[3][BM*16];
    __shared__ __align__(16) uint32_t Bs[3][BN*16];

    int tid  = threadIdx.x;
    int lane = tid & 31, w = tid >> 5;
    int g = lane >> 2, tig = lane & 3;
    int wm = w >> 2, wn = w & 3;               // 2 x 4 warp grid
    int bm = blockIdx.y * BM, bn = blockIdx.x * BN;
    int S  = gridDim.z, kz = blockIdx.z;
    int Ks = K / S;
    int M  = gridDim.y * BM;
    int nst = Ks >> 5;

    int lm = tid >> 2, lq = tid & 3;
    const __half* Ap0 = A + (size_t)(bm + lm)*K + (size_t)kz*Ks + lq*8;
    const __half* Ap1 = Ap0 + (size_t)64*K;
    const __half* Bp0 = B + (size_t)(bn + lm)*K + (size_t)kz*Ks + lq*8;
    const __half* Bp1 = Bp0 + (size_t)64*K;
    int sc = lq ^ ((lm >> 1) & 3);
    int sw0 = lm*16 + sc*4;
    int sw1 = (lm + 64)*16 + sc*4;
    uint32_t sa0[3], sa1[3], sb0[3], sb1[3];
    #pragma unroll
    for (int b3 = 0; b3 < 3; b3++) {
        sa0[b3] = s2u(&As[b3][sw0]);  sa1[b3] = s2u(&As[b3][sw1]);
        sb0[b3] = s2u(&Bs[b3][sw0]);  sb1[b3] = s2u(&Bs[b3][sw1]);
    }

    float acc[4][4][4];
    #pragma unroll
    for (int i = 0; i < 4; i++)
        #pragma unroll
        for (int j = 0; j < 4; j++)
            #pragma unroll
            for (int q = 0; q < 4; q++) acc[i][j][q] = 0.0f;

    int mrow[4], mj[4];
    #pragma unroll
    for (int ii = 0; ii < 4; ii++) {
        mrow[ii] = wm*64 + ii*16 + g;
        mj[ii] = ((mrow[ii] >> 1) & 3) << 2;
    }
    int nrow[4], nj[4];
    #pragma unroll
    for (int jj = 0; jj < 4; jj++) {
        nrow[jj] = wn*32 + jj*8 + g;
        nj[jj] = ((nrow[jj] >> 1) & 3) << 2;
    }

    cp16(sa0[0], Ap0);  cp16(sa1[0], Ap1);
    cp16(sb0[0], Bp0);  cp16(sb1[0], Bp1);
    asm volatile("cp.async.commit_group;");
    if (nst > 1) {
        cp16(sa0[1], Ap0 + 32);  cp16(sa1[1], Ap1 + 32);
        cp16(sb0[1], Bp0 + 32);  cp16(sb1[1], Bp1 + 32);
        asm volatile("cp.async.commit_group;");
    }

    int buf = 0;
    for (int s = 0; s < nst; s++) {
        if (s < nst - 1) asm volatile("cp.async.wait_group 1;");
        else             asm volatile("cp.async.wait_group 0;");
        __syncthreads();

        const uint32_t* as = As[buf];
        const uint32_t* bs = Bs[buf];
        #pragma unroll
        for (int kb = 0; kb < 2; kb++) {
            int kw0 = kb*8 + tig, kw1 = kw0 + 4;
            uint32_t af[4][4], bf[4][2];
            #pragma unroll
            for (int jj = 0; jj < 4; jj++) {
                int rn = nrow[jj]*16, x = nj[jj];
                bf[jj][0] = bs[rn + (kw0 ^ x)];
                bf[jj][1] = bs[rn + (kw1 ^ x)];
            }
            #pragma unroll
            for (int ii = 0; ii < 4; ii++) {
                int r0 = mrow[ii]*16, r1 = (mrow[ii]+8)*16, x = mj[ii];
                af[ii][0] = as[r0 + (kw0 ^ x)];
                af[ii][1] = as[r1 + (kw0 ^ x)];
                af[ii][2] = as[r0 + (kw1 ^ x)];
                af[ii][3] = as[r1 + (kw1 ^ x)];
            }
            #pragma unroll
            for (int ii = 0; ii < 4; ii++)
                #pragma unroll
                for (int jj = 0; jj < 4; jj++)
                    mma_f16(acc[ii][jj], af[ii][0], af[ii][1], af[ii][2], af[ii][3],
                            bf[jj][0], bf[jj][1]);
        }

        if (s + 2 < nst) {
            int nb = (buf + 2) % 3;
            size_t o = (size_t)(s+2)*32;
            cp16(sa0[nb], Ap0 + o);  cp16(sa1[nb], Ap1 + o);
            cp16(sb0[nb], Bp0 + o);  cp16(sb1[nb], Bp1 + o);
            asm volatile("cp.async.commit_group;");
        }
        buf = (buf + 1) % 3;
    }

    float* Pp = P + (size_t)kz * M * N;
    #pragma unroll
    for (int ii = 0; ii < 4; ii++) {
        #pragma unroll
        for (int jj = 0; jj < 4; jj++) {
            int r0 = bm + wm*64 + ii*16 + g;
            int c0 = bn + wn*32 + jj*8 + tig*2;
            Pp[(size_t)r0*N + c0]       = acc[ii][jj][0];
            Pp[(size_t)r0*N + c0 + 1]   = acc[ii][jj][1];
            Pp[(size_t)(r0+8)*N + c0]   = acc[ii][jj][2];
            Pp[(size_t)(r0+8)*N + c0+1] = acc[ii][jj][3];
        }
    }
}

// -------- split-K combine (float4, half out): for N multiple of 4 -----------
__global__ void combine4h(const float* __restrict__ P, const float* __restrict__ bias,
                          __half* __restrict__ outh, int M, int N, int S) {
    int i = blockIdx.x * 256 + threadIdx.x;   // over M*N/4
    if (i >= M*N/4) return;
    int base = i*4;
    int m = base / N, n = base - m*N;
    float4 v = *(const float4*)(bias + n);
    for (int s = 0; s < S; s++) {
        float4 p = *(const float4*)(P + ((size_t)s*M + m)*N + n);
        v.x += p.x; v.y += p.y; v.z += p.z; v.w += p.w;
    }
    v.x = fmaxf(v.x, 0.f); v.y = fmaxf(v.y, 0.f);
    v.z = fmaxf(v.z, 0.f); v.w = fmaxf(v.w, 0.f);
    uint2 o;
    o.x = h2u(__floats2half2_rn(v.x, v.y));
    o.y = h2u(__floats2half2_rn(v.z, v.w));
    *(uint2*)(outh + base) = o;
}

// -------- scalar combine (float out, ragged N) for the final layer ----------
__global__ void combine_f(const float* __restrict__ P, const float* __restrict__ bias,
                          float* __restrict__ outf, int M, int Ntot, int Nlog, int S) {
    int i = blockIdx.x * 256 + threadIdx.x;
    if (i >= M*Nlog) return;
    int m = i / Nlog, n = i - m*Nlog;
    float v = bias[n];
    for (int s = 0; s < S; s++)
        v += P[((size_t)s*M + m)*Ntot + n];
    outf[i] = v;
}

// ---------------- launch -----------------------------------------------------
extern "C" void kernel_launch(void* const* d_in, const int* in_sizes, int n_in,
                              void* d_out, int out_size) {
    const float* input     = (const float*)d_in[0];
    const float* rois      = (const float*)d_in[1];
    const float* rescale_w = (const float*)d_in[2];
    const float* rescale_b = (const float*)d_in[3];
    const float* off_w1    = (const float*)d_in[4];
    const float* off_b1    = (const float*)d_in[5];
    const float* off_w2    = (const float*)d_in[6];
    const float* off_b2    = (const float*)d_in[7];
    const float* off_w3    = (const float*)d_in[8];
    const float* off_b3    = (const float*)d_in[9];

    float* xcls = (float*)d_out;
    float* xreg = xcls + (size_t)NROIS * FDIM;

    __half *a1p, *w1p, *w2p, *w3p, *h1p, *h2p;
    float *offp, *nroisp, *partp;
    cudaGetSymbolAddress((void**)&a1p,    g_a1h);
    cudaGetSymbolAddress((void**)&w1p,    g_w1h);
    cudaGetSymbolAddress((void**)&w2p,    g_w2h);
    cudaGetSymbolAddress((void**)&w3p,    g_w3h);
    cudaGetSymbolAddress((void**)&h1p,    g_h1h);
    cudaGetSymbolAddress((void**)&h2p,    g_h2h);
    cudaGetSymbolAddress((void**)&offp,   g_off);
    cudaGetSymbolAddress((void**)&nroisp, g_nrois);
    cudaGetSymbolAddress((void**)&partp,  g_part);

    // 1) transpose to NHWC fp16 + fused weight half-conversion
    nchw2nhwc_h<<<dim3(HW/32, CH/64, BATCH), dim3(32, 8)>>>(input);
    cvt_weights<<<(W1_8 + W2_8 + W3_8 + 255)/256, 256>>>(off_w1, off_w2, off_w3);
    // 2) x_cls pool (2 CTAs/ROI) -> d_out (fp32) + g_a1h (half)
    roi_pool<false,true><<<dim3(NROIS, 2), 256>>>(rois, nullptr, xcls, a1p);
    // 3) rescale head (fp32 flat, float4) + new_rois
    rescale_newrois<<<NROIS, 256>>>(xcls, rois, rescale_w, rescale_b);
    // 4) offset MLP: fp16 tensor cores (3-stage cp.async), split-K + combine
    gemm_h<<<dim3(DFC/128, NROIS/128, 8), 256>>>(a1p, w1p, partp, DFC, FDIM);
    combine4h<<<(NROIS*DFC/4 + 255)/256, 256>>>(partp, off_b1, h1p, NROIS, DFC, 8);
    gemm_h<<<dim3(DFC/128, NROIS/128, 8), 256>>>(h1p, w2p, partp, DFC, DFC);
    combine4h<<<(NROIS*DFC/4 + 255)/256, 256>>>(partp, off_b2, h2p, NROIS, DFC, 8);
    gemm_h<<<dim3(1, NROIS/128, 8), 256>>>(h2p, w3p, partp, NOFFP, DFC);
    combine_f<<<(NROIS*NOFF + 255)/256, 256>>>(partp, off_b3, offp, NROIS, NOFFP, NOFF, 8);
    // 5) x_reg pool (2 CTAs/ROI) -> second half of d_out
    roi_pool<true,false><<<dim3(NROIS, 2), 256>>>(nroisp, offp, xreg, nullptr);
}

// round 14
// speedup vs baseline: 6.8694x; 1.0121x over previous
#include <cuda_runtime.h>
#include <cuda_fp16.h>
#include <math.h>
#include <stdint.h>

#define BATCH 4
#define CH    256
#define FH    100
#define FW    152
#define HW    (FH*FW)          // 15200
#define NROIS 512
#define OH    7
#define OW    7
#define NBIN  49
#define FDIM  (CH*NBIN)        // 12544
#define DFC   1024
#define NOFF  98               // 2*49
#define NOFFP 128              // padded for GEMM3
#define SCALE 0.0625f
#define GAMMA 0.1f
#define SKMAX 8

// ---------------- scratch (device globals; no allocation allowed) -----------
__device__ __half g_feath[(size_t)BATCH*HW*CH];  // NHWC fp16 features, 31 MB
__device__ __half g_a1h[(size_t)NROIS*FDIM];     // half(xcls) 12.8 MB
__device__ __half g_w1h[(size_t)DFC*FDIM];       // half(w1) 25.7 MB
__device__ __half g_w2h[(size_t)DFC*DFC];        // half(w2) 2 MB
__device__ __half g_w3h[(size_t)NOFFP*DFC];      // half(w3), zero-padded rows
__device__ __half g_h1h[NROIS*DFC];
__device__ __half g_h2h[NROIS*DFC];
__device__ float  g_off[NROIS*NOFF];
__device__ float  g_nrois[NROIS*5];
__device__ float  g_dots[NROIS*8];               // rescale partial dots [roi][cb][4]
__device__ float  g_part[(size_t)SKMAX*NROIS*DFC]; // split-K partials (16 MB)

// ---------------- NCHW -> NHWC fp16 transpose -------------------------------
__global__ void nchw2nhwc_h(const float* __restrict__ in) {
    __shared__ float tile[64][33];
    int b   = blockIdx.z;
    int hw0 = blockIdx.x * 32;
    int c0  = blockIdx.y * 64;
    #pragma unroll
    for (int r = 0; r < 8; r++) {
        int c  = c0 + threadIdx.y + r*8;
        int hw = hw0 + threadIdx.x;
        tile[threadIdx.y + r*8][threadIdx.x] = in[((size_t)b*CH + c)*HW + hw];
    }
    __syncthreads();
    __half2* out2 = (__half2*)g_feath;
    #pragma unroll
    for (int r = 0; r < 4; r++) {
        int hwl = threadIdx.y + r*8;
        int hw  = hw0 + hwl;
        int c2  = threadIdx.x;
        float lo = tile[2*c2][hwl];
        float hi = tile[2*c2+1][hwl];
        out2[((size_t)b*HW + hw)*(CH/2) + c0/2 + c2] = __floats2half2_rn(lo, hi);
    }
}

// ---------------- fused fp32 -> fp16 weight conversion ----------------------
__device__ __forceinline__ uint32_t h2u(__half2 h) { return *reinterpret_cast<uint32_t*>(&h); }
__device__ __forceinline__ uint4 f8toh8(const float4* s) {
    float4 a = s[0], b = s[1];
    uint4 o;
    o.x = h2u(__floats2half2_rn(a.x, a.y));
    o.y = h2u(__floats2half2_rn(a.z, a.w));
    o.z = h2u(__floats2half2_rn(b.x, b.y));
    o.w = h2u(__floats2half2_rn(b.z, b.w));
    return o;
}

#define W1_8 (DFC*FDIM/8)
#define W2_8 (DFC*DFC/8)
#define W3_8 (NOFFP*DFC/8)

__global__ void cvt_weights(const float* __restrict__ w1,
                            const float* __restrict__ w2,
                            const float* __restrict__ w3) {
    int i = blockIdx.x * 256 + threadIdx.x;
    if (i < W1_8) {
        ((uint4*)g_w1h)[i] = f8toh8((const float4*)(w1 + (size_t)i*8));
    } else if (i < W1_8 + W2_8) {
        int j = i - W1_8;
        ((uint4*)g_w2h)[j] = f8toh8((const float4*)(w2 + (size_t)j*8));
    } else if (i < W1_8 + W2_8 + W3_8) {
        int j = i - W1_8 - W2_8;
        int r = (j*8) >> 10;
        uint4 o;
        if (r < NOFF) o = f8toh8((const float4*)(w3 + (size_t)j*8));
        else          o.x = o.y = o.z = o.w = 0u;
        ((uint4*)g_w3h)[j] = o;
    }
}

// ------- deformable RoI pool: 2 CTAs per ROI (128 channels each) ------------
// grid (NROIS, 2); 256 threads = (16 bins in flight) x (16 groups of 8 ch).
// RESCALE: epilogue also computes 4 partial dots vs rescale_w -> g_dots.
#define POOL_CH   128
#define POOL_HALF (POOL_CH*NBIN)     // 6272 floats per half
#define PH4       (POOL_HALF/4)      // 1568
template<bool HAS_OFF, bool EMIT_HALF, bool RESCALE>
__global__ void roi_pool(const float* __restrict__ rois,
                         const float* __restrict__ off,
                         float* __restrict__ out,
                         __half* __restrict__ out_h,
                         const float4* __restrict__ rw4) {
    __shared__ float sout[POOL_HALF];         // 25 KB
    int roi = blockIdx.x;
    int cb  = blockIdx.y;                      // channel half: 0 or 1
    int tid = threadIdx.x;
    int bq = tid >> 4, cg = tid & 15;          // bin slot, 8-ch group (within half)
    const float* r = rois + roi*5;
    int   b  = (int)r[0];
    float x1 = r[1]*SCALE - 0.5f;
    float y1 = r[2]*SCALE - 0.5f;
    float x2 = r[3]*SCALE - 0.5f;
    float y2 = r[4]*SCALE - 0.5f;
    float rw = x2 - x1, rh = y2 - y1;
    float bw = rw * (1.0f/OW), bh = rh * (1.0f/OH);
    const uint4* fb = (const uint4*)(g_feath + (size_t)b*HW*CH);
    const int C8 = CH/8;                       // 32 uint4 per pixel
    int cgl = cb*16 + cg;                      // global 8-ch group index

    for (int b0 = 0; b0 < NBIN; b0 += 16) {
        int bin = b0 + bq;
        if (bin < NBIN) {
            int ph = bin / OW, pw = bin - ph*OW;
            float sw_ = x1, sh_ = y1;
            if (HAS_OFF) {
                sw_ += GAMMA * rw * off[roi*NOFF + bin];
                sh_ += GAMMA * rh * off[roi*NOFF + NBIN + bin];
            }
            float acc[8] = {};
            #pragma unroll
            for (int iy = 0; iy < 2; iy++) {
                float y = sh_ + ((float)ph + ((float)iy + 0.5f)*0.5f) * bh;
                #pragma unroll
                for (int ix = 0; ix < 2; ix++) {
                    float x = sw_ + ((float)pw + ((float)ix + 0.5f)*0.5f) * bw;
                    if (y > -1.0f && y < (float)FH && x > -1.0f && x < (float)FW) {
                        float yc = fminf(fmaxf(y, 0.0f), (float)(FH-1));
                        float xc = fminf(fmaxf(x, 0.0f), (float)(FW-1));
                        int y0 = min((int)floorf(yc), FH-2);
                        int x0 = min((int)floorf(xc), FW-2);
                        float ly = yc - (float)y0, lx = xc - (float)x0;
                        float hy = 1.0f - ly,     hx = 1.0f - lx;
                        float w00 = hy*hx, w01 = hy*lx, w10 = ly*hx, w11 = ly*lx;
                        const uint4* p = fb + ((size_t)y0*FW + x0)*C8 + cgl;
                        uint4 v00 = p[0];
                        uint4 v01 = p[C8];
                        uint4 v10 = p[FW*C8];
                        uint4 v11 = p[FW*C8 + C8];
                        const uint32_t* u00 = &v00.x;
                        const uint32_t* u01 = &v01.x;
                        const uint32_t* u10 = &v10.x;
                        const uint32_t* u11 = &v11.x;
                        #pragma unroll
                        for (int q = 0; q < 4; q++) {
                            float2 f00 = __half22float2(*(const __half2*)&u00[q]);
                            float2 f01 = __half22float2(*(const __half2*)&u01[q]);
                            float2 f10 = __half22float2(*(const __half2*)&u10[q]);
                            float2 f11 = __half22float2(*(const __half2*)&u11[q]);
                            acc[2*q]   += w00*f00.x + w01*f01.x + w10*f10.x + w11*f11.x;
                            acc[2*q+1] += w00*f00.y + w01*f01.y + w10*f10.y + w11*f11.y;
                        }
                    }
                }
            }
            int c = cg*8;                      // local channel within this half
            #pragma unroll
            for (int j = 0; j < 8; j++)
                sout[(c+j)*NBIN + bin] = acc[j] * 0.25f;
        }
    }
    __syncthreads();
    size_t base = (size_t)roi * FDIM + (size_t)cb * POOL_HALF;
    float* o = out + base;
    if (EMIT_HALF) {
        __half* oh = out_h + base;
        for (int i = tid; i < POOL_HALF; i += 256) {
            float v = sout[i];
            o[i] = v;
            oh[i] = __float2half_rn(v);
        }
    } else {
        for (int i = tid; i < POOL_HALF; i += 256) o[i] = sout[i];
    }

    if (RESCALE) {
        // partial dots of this half of flat vs rescale_w rows 0..3
        const float4* s4 = (const float4*)sout;
        int wo = cb * PH4;                    // float4 offset into each w row
        float s[4] = {0.f, 0.f, 0.f, 0.f};
        for (int k = tid; k < PH4; k += 256) {
            float4 v = s4[k];
            #pragma unroll
            for (int j = 0; j < 4; j++) {
                float4 a = rw4[(size_t)j*(FDIM/4) + wo + k];
                s[j] += v.x*a.x + v.y*a.y + v.z*a.z + v.w*a.w;
            }
        }
        #pragma unroll
        for (int o2 = 16; o2 > 0; o2 >>= 1)
            #pragma unroll
            for (int j = 0; j < 4; j++)
                s[j] += __shfl_down_sync(0xffffffffu, s[j], o2);
        __shared__ float red[4][8];
        int lane = tid & 31, warp = tid >> 5;
        if (lane == 0) { red[0][warp]=s[0]; red[1][warp]=s[1]; red[2][warp]=s[2]; red[3][warp]=s[3]; }
        __syncthreads();
        if (tid < 4) {
            float t = 0.f;
            #pragma unroll
            for (int ww = 0; ww < 8; ww++) t += red[tid][ww];
            g_dots[roi*8 + cb*4 + tid] = t;
        }
    }
}

// ---------- finalize: dots -> sigmoid rescale -> new rois (512 threads) -----
__global__ void finalize_newrois(const float* __restrict__ rois,
                                 const float* __restrict__ bias) {
    int roi = blockIdx.x * 256 + threadIdx.x;
    if (roi >= NROIS) return;
    float d[4];
    #pragma unroll
    for (int j = 0; j < 4; j++) {
        float t = g_dots[roi*8 + j] + g_dots[roi*8 + 4 + j] + bias[j];
        d[j] = 1.0f + 0.5f / (1.0f + expf(-t));
    }
    const float* r = rois + roi*5;
    float cx = (r[1] + r[3]) * 0.5f + d[0];
    float cy = (r[2] + r[4]) * 0.5f + d[1];
    float nw = (r[3] - r[1]) * d[2];
    float nh = (r[4] - r[2]) * d[3];
    float* nr = g_nrois + roi*5;
    nr[0] = r[0];
    nr[1] = cx - 0.5f*nw;  nr[2] = cy - 0.5f*nh;
    nr[3] = cx + 0.5f*nw;  nr[4] = cy + 0.5f*nh;
}

// ------------ fp16 tensor-core NT GEMM, 128x128x32, 3-stage cp.async --------
__device__ __forceinline__ void mma_f16(float* c, uint32_t a0, uint32_t a1,
                                        uint32_t a2, uint32_t a3,
                                        uint32_t b0, uint32_t b1) {
    asm volatile(
        "mma.sync.aligned.m16n8k16.row.col.f32.f16.f16.f32 "
        "{%0,%1,%2,%3}, {%4,%5,%6,%7}, {%8,%9}, {%0,%1,%2,%3};"
        : "+f"(c[0]), "+f"(c[1]), "+f"(c[2]), "+f"(c[3])
        : "r"(a0), "r"(a1), "r"(a2), "r"(a3), "r"(b0), "r"(b1));
}
__device__ __forceinline__ uint32_t s2u(const void* p) {
    return (uint32_t)__cvta_generic_to_shared(p);
}
__device__ __forceinline__ void cp16(uint32_t dst, const void* src) {
    asm volatile("cp.async.cg.shared.global [%0], [%1], 16;" :: "r"(dst), "l"(src));
}

__global__ void __launch_bounds__(256, 2)
gemm_h(const __half* __restrict__ A, const __half* __restrict__ B,
       float* __restrict__ P, int N, int K) {
    const int BM = 128, BN = 128;
    __shared__ __align__(16) uint32_t As[3][BM*16];
    __shared__ __align__(16) uint32_t Bs[3][BN*16];

    int tid  = threadIdx.x;
    int lane = tid & 31, w = tid >> 5;
    int g = lane >> 2, tig = lane & 3;
    int wm = w >> 2, wn = w & 3;               // 2 x 4 warp grid
    int bm = blockIdx.y * BM, bn = blockIdx.x * BN;
    int S  = gridDim.z, kz = blockIdx.z;
    int Ks = K / S;
    int M  = gridDim.y * BM;
    int nst = Ks >> 5;

    int lm = tid >> 2, lq = tid & 3;
    const __half* Ap0 = A + (size_t)(bm + lm)*K + (size_t)kz*Ks + lq*8;
    const __half* Ap1 = Ap0 + (size_t)64*K;
    const __half* Bp0 = B + (size_t)(bn + lm)*K + (size_t)kz*Ks + lq*8;
    const __half* Bp1 = Bp0 + (size_t)64*K;
    int sc = lq ^ ((lm >> 1) & 3);
    int sw0 = lm*16 + sc*4;
    int sw1 = (lm + 64)*16 + sc*4;
    uint32_t sa0[3], sa1[3], sb0[3], sb1[3];
    #pragma unroll
    for (int b3 = 0; b3 < 3; b3++) {
        sa0[b3] = s2u(&As[b3][sw0]);  sa1[b3] = s2u(&As[b3][sw1]);
        sb0[b3] = s2u(&Bs[b3][sw0]);  sb1[b3] = s2u(&Bs[b3][sw1]);
    }

    float acc[4][4][4];
    #pragma unroll
    for (int i = 0; i < 4; i++)
        #pragma unroll
        for (int j = 0; j < 4; j++)
            #pragma unroll
            for (int q = 0; q < 4; q++) acc[i][j][q] = 0.0f;

    int mrow[4], mj[4];
    #pragma unroll
    for (int ii = 0; ii < 4; ii++) {
        mrow[ii] = wm*64 + ii*16 + g;
        mj[ii] = ((mrow[ii] >> 1) & 3) << 2;
    }
    int nrow[4], nj[4];
    #pragma unroll
    for (int jj = 0; jj < 4; jj++) {
        nrow[jj] = wn*32 + jj*8 + g;
        nj[jj] = ((nrow[jj] >> 1) & 3) << 2;
    }

    cp16(sa0[0], Ap0);  cp16(sa1[0], Ap1);
    cp16(sb0[0], Bp0);  cp16(sb1[0], Bp1);
    asm volatile("cp.async.commit_group;");
    if (nst > 1) {
        cp16(sa0[1], Ap0 + 32);  cp16(sa1[1], Ap1 + 32);
        cp16(sb0[1], Bp0 + 32);  cp16(sb1[1], Bp1 + 32);
        asm volatile("cp.async.commit_group;");
    }

    int buf = 0;
    for (int s = 0; s < nst; s++) {
        if (s < nst - 1) asm volatile("cp.async.wait_group 1;");
        else             asm volatile("cp.async.wait_group 0;");
        __syncthreads();

        const uint32_t* as = As[buf];
        const uint32_t* bs = Bs[buf];
        #pragma unroll
        for (int kb = 0; kb < 2; kb++) {
            int kw0 = kb*8 + tig, kw1 = kw0 + 4;
            uint32_t af[4][4], bf[4][2];
            #pragma unroll
            for (int jj = 0; jj < 4; jj++) {
                int rn = nrow[jj]*16, x = nj[jj];
                bf[jj][0] = bs[rn + (kw0 ^ x)];
                bf[jj][1] = bs[rn + (kw1 ^ x)];
            }
            #pragma unroll
            for (int ii = 0; ii < 4; ii++) {
                int r0 = mrow[ii]*16, r1 = (mrow[ii]+8)*16, x = mj[ii];
                af[ii][0] = as[r0 + (kw0 ^ x)];
                af[ii][1] = as[r1 + (kw0 ^ x)];
                af[ii][2] = as[r0 + (kw1 ^ x)];
                af[ii][3] = as[r1 + (kw1 ^ x)];
            }
            #pragma unroll
            for (int ii = 0; ii < 4; ii++)
                #pragma unroll
                for (int jj = 0; jj < 4; jj++)
                    mma_f16(acc[ii][jj], af[ii][0], af[ii][1], af[ii][2], af[ii][3],
                            bf[jj][0], bf[jj][1]);
        }

        if (s + 2 < nst) {
            int nb = (buf + 2) % 3;
            size_t o = (size_t)(s+2)*32;
            cp16(sa0[nb], Ap0 + o);  cp16(sa1[nb], Ap1 + o);
            cp16(sb0[nb], Bp0 + o);  cp16(sb1[nb], Bp1 + o);
            asm volatile("cp.async.commit_group;");
        }
        buf = (buf + 1) % 3;
    }

    float* Pp = P + (size_t)kz * M * N;
    #pragma unroll
    for (int ii = 0; ii < 4; ii++) {
        #pragma unroll
        for (int jj = 0; jj < 4; jj++) {
            int r0 = bm + wm*64 + ii*16 + g;
            int c0 = bn + wn*32 + jj*8 + tig*2;
            Pp[(size_t)r0*N + c0]       = acc[ii][jj][0];
            Pp[(size_t)r0*N + c0 + 1]   = acc[ii][jj][1];
            Pp[(size_t)(r0+8)*N + c0]   = acc[ii][jj][2];
            Pp[(size_t)(r0+8)*N + c0+1] = acc[ii][jj][3];
        }
    }
}

// -------- split-K combine (float4, half out): for N multiple of 4 -----------
__global__ void combine4h(const float* __restrict__ P, const float* __restrict__ bias,
                          __half* __restrict__ outh, int M, int N, int S) {
    int i = blockIdx.x * 256 + threadIdx.x;   // over M*N/4
    if (i >= M*N/4) return;
    int base = i*4;
    int m = base / N, n = base - m*N;
    float4 v = *(const float4*)(bias + n);
    for (int s = 0; s < S; s++) {
        float4 p = *(const float4*)(P + ((size_t)s*M + m)*N + n);
        v.x += p.x; v.y += p.y; v.z += p.z; v.w += p.w;
    }
    v.x = fmaxf(v.x, 0.f); v.y = fmaxf(v.y, 0.f);
    v.z = fmaxf(v.z, 0.f); v.w = fmaxf(v.w, 0.f);
    uint2 o;
    o.x = h2u(__floats2half2_rn(v.x, v.y));
    o.y = h2u(__floats2half2_rn(v.z, v.w));
    *(uint2*)(outh + base) = o;
}

// -------- scalar combine (float out, ragged N) for the final layer ----------
__global__ void combine_f(const float* __restrict__ P, const float* __restrict__ bias,
                          float* __restrict__ outf, int M, int Ntot, int Nlog, int S) {
    int i = blockIdx.x * 256 + threadIdx.x;
    if (i >= M*Nlog) return;
    int m = i / Nlog, n = i - m*Nlog;
    float v = bias[n];
    for (int s = 0; s < S; s++)
        v += P[((size_t)s*M + m)*Ntot + n];
    outf[i] = v;
}

// ---------------- launch -----------------------------------------------------
extern "C" void kernel_launch(void* const* d_in, const int* in_sizes, int n_in,
                              void* d_out, int out_size) {
    const float* input     = (const float*)d_in[0];
    const float* rois      = (const float*)d_in[1];
    const float* rescale_w = (const float*)d_in[2];
    const float* rescale_b = (const float*)d_in[3];
    const float* off_w1    = (const float*)d_in[4];
    const float* off_b1    = (const float*)d_in[5];
    const float* off_w2    = (const float*)d_in[6];
    const float* off_b2    = (const float*)d_in[7];
    const float* off_w3    = (const float*)d_in[8];
    const float* off_b3    = (const float*)d_in[9];

    float* xcls = (float*)d_out;
    float* xreg = xcls + (size_t)NROIS * FDIM;

    __half *a1p, *w1p, *w2p, *w3p, *h1p, *h2p;
    float *offp, *nroisp, *partp;
    cudaGetSymbolAddress((void**)&a1p,    g_a1h);
    cudaGetSymbolAddress((void**)&w1p,    g_w1h);
    cudaGetSymbolAddress((void**)&w2p,    g_w2h);
    cudaGetSymbolAddress((void**)&w3p,    g_w3h);
    cudaGetSymbolAddress((void**)&h1p,    g_h1h);
    cudaGetSymbolAddress((void**)&h2p,    g_h2h);
    cudaGetSymbolAddress((void**)&offp,   g_off);
    cudaGetSymbolAddress((void**)&nroisp, g_nrois);
    cudaGetSymbolAddress((void**)&partp,  g_part);

    // 1) transpose to NHWC fp16 + fused weight half-conversion
    nchw2nhwc_h<<<dim3(HW/32, CH/64, BATCH), dim3(32, 8)>>>(input);
    cvt_weights<<<(W1_8 + W2_8 + W3_8 + 255)/256, 256>>>(off_w1, off_w2, off_w3);
    // 2) x_cls pool (2 CTAs/ROI) -> d_out (fp32) + g_a1h (half) + rescale dots
    roi_pool<false,true,true><<<dim3(NROIS, 2), 256>>>(
        rois, nullptr, xcls, a1p, (const float4*)rescale_w);
    // 3) finalize rescale -> new_rois (tiny)
    finalize_newrois<<<2, 256>>>(rois, rescale_b);
    // 4) offset MLP: fp16 tensor cores (3-stage cp.async), split-K + combine
    gemm_h<<<dim3(DFC/128, NROIS/128, 8), 256>>>(a1p, w1p, partp, DFC, FDIM);
    combine4h<<<(NROIS*DFC/4 + 255)/256, 256>>>(partp, off_b1, h1p, NROIS, DFC, 8);
    gemm_h<<<dim3(DFC/128, NROIS/128, 8), 256>>>(h1p, w2p, partp, DFC, DFC);
    combine4h<<<(NROIS*DFC/4 + 255)/256, 256>>>(partp, off_b2, h2p, NROIS, DFC, 8);
    gemm_h<<<dim3(1, NROIS/128, 8), 256>>>(h2p, w3p, partp, NOFFP, DFC);
    combine_f<<<(NROIS*NOFF + 255)/256, 256>>>(partp, off_b3, offp, NROIS, NOFFP, NOFF, 8);
    // 5) x_reg pool (2 CTAs/ROI) -> second half of d_out
    roi_pool<true,false,false><<<dim3(NROIS, 2), 256>>>(
        nroisp, offp, xreg, nullptr, nullptr);
}

// round 15
// speedup vs baseline: 7.2246x; 1.0517x over previous
#include <cuda_runtime.h>
#include <cuda_fp16.h>
#include <math.h>
#include <stdint.h>

#define BATCH 4
#define CH    256
#define FH    100
#define FW    152
#define HW    (FH*FW)          // 15200
#define NROIS 512
#define OH    7
#define OW    7
#define NBIN  49
#define FDIM  (CH*NBIN)        // 12544
#define DFC   1024
#define NOFF  98               // 2*49
#define NOFFP 128              // padded for GEMM3
#define SCALE 0.0625f
#define GAMMA 0.1f
#define SKMAX 8

// ---------------- scratch (device globals; no allocation allowed) -----------
__device__ __half g_feath[(size_t)BATCH*HW*CH];  // NHWC fp16 features, 31 MB
__device__ __half g_a1h[(size_t)NROIS*FDIM];     // half(xcls) 12.8 MB
__device__ __half g_w1h[(size_t)DFC*FDIM];       // half(w1) 25.7 MB
__device__ __half g_w2h[(size_t)DFC*DFC];        // half(w2) 2 MB
__device__ __half g_w3h[(size_t)NOFFP*DFC];      // half(w3), zero-padded rows
__device__ __half g_h1h[NROIS*DFC];
__device__ __half g_h2h[NROIS*DFC];
__device__ float  g_off[NROIS*NOFF];
__device__ float  g_nrois[NROIS*5];
__device__ float  g_dots[NROIS*8];               // rescale partial dots [roi][cb][4]
__device__ float  g_part[(size_t)SKMAX*NROIS*DFC]; // split-K partials (16 MB)

// ---------------- NCHW -> NHWC fp16 transpose -------------------------------
__global__ void nchw2nhwc_h(const float* __restrict__ in) {
    __shared__ float tile[64][33];
    int b   = blockIdx.z;
    int hw0 = blockIdx.x * 32;
    int c0  = blockIdx.y * 64;
    #pragma unroll
    for (int r = 0; r < 8; r++) {
        int c  = c0 + threadIdx.y + r*8;
        int hw = hw0 + threadIdx.x;
        tile[threadIdx.y + r*8][threadIdx.x] = in[((size_t)b*CH + c)*HW + hw];
    }
    __syncthreads();
    __half2* out2 = (__half2*)g_feath;
    #pragma unroll
    for (int r = 0; r < 4; r++) {
        int hwl = threadIdx.y + r*8;
        int hw  = hw0 + hwl;
        int c2  = threadIdx.x;
        float lo = tile[2*c2][hwl];
        float hi = tile[2*c2+1][hwl];
        out2[((size_t)b*HW + hw)*(CH/2) + c0/2 + c2] = __floats2half2_rn(lo, hi);
    }
}

// ---------------- fp32 -> fp16 weight conversion helpers --------------------
__device__ __forceinline__ uint32_t h2u(__half2 h) { return *reinterpret_cast<uint32_t*>(&h); }
__device__ __forceinline__ uint4 f8toh8(const float4* s) {
    float4 a = s[0], b = s[1];
    uint4 o;
    o.x = h2u(__floats2half2_rn(a.x, a.y));
    o.y = h2u(__floats2half2_rn(a.z, a.w));
    o.z = h2u(__floats2half2_rn(b.x, b.y));
    o.w = h2u(__floats2half2_rn(b.z, b.w));
    return o;
}

#define W1_8 (DFC*FDIM/8)
#define W2_8 (DFC*DFC/8)
#define W3_8 (NOFFP*DFC/8)
#define WTOT8 (W1_8 + W2_8 + W3_8)

__device__ __forceinline__ void cvt_one(int i, const float* w1, const float* w2,
                                        const float* w3) {
    if (i < W1_8) {
        ((uint4*)g_w1h)[i] = f8toh8((const float4*)(w1 + (size_t)i*8));
    } else if (i < W1_8 + W2_8) {
        int j = i - W1_8;
        ((uint4*)g_w2h)[j] = f8toh8((const float4*)(w2 + (size_t)j*8));
    } else {
        int j = i - W1_8 - W2_8;
        int r = (j*8) >> 10;
        uint4 o;
        if (r < NOFF) o = f8toh8((const float4*)(w3 + (size_t)j*8));
        else          o.x = o.y = o.z = o.w = 0u;
        ((uint4*)g_w3h)[j] = o;
    }
}

// ------- deformable RoI pool: 2 CTAs per ROI (128 channels each) ------------
// grid (NROIS, 2 [+1 when DO_CVT]); 256 threads.
// RESCALE: epilogue also computes 4 partial dots vs rescale_w -> g_dots.
// DO_CVT: blockIdx.y==2 blocks instead run grid-stride weight conversion.
#define POOL_CH   128
#define POOL_HALF (POOL_CH*NBIN)     // 6272 floats per half
#define PH4       (POOL_HALF/4)      // 1568
template<bool HAS_OFF, bool EMIT_HALF, bool RESCALE, bool DO_CVT>
__global__ void roi_pool(const float* __restrict__ rois,
                         const float* __restrict__ off,
                         float* __restrict__ out,
                         __half* __restrict__ out_h,
                         const float4* __restrict__ rw4,
                         const float* __restrict__ w1,
                         const float* __restrict__ w2,
                         const float* __restrict__ w3) {
    __shared__ float sout[POOL_HALF];         // 25 KB
    int tid = threadIdx.x;
    if (DO_CVT && blockIdx.y == 2) {
        const int stride = NROIS * 256;
        for (int i = blockIdx.x*256 + tid; i < WTOT8; i += stride)
            cvt_one(i, w1, w2, w3);
        return;
    }
    int roi = blockIdx.x;
    int cb  = blockIdx.y;                      // channel half: 0 or 1
    int bq = tid >> 4, cg = tid & 15;          // bin slot, 8-ch group (within half)
    const float* r = rois + roi*5;
    int   b  = (int)r[0];
    float x1 = r[1]*SCALE - 0.5f;
    float y1 = r[2]*SCALE - 0.5f;
    float x2 = r[3]*SCALE - 0.5f;
    float y2 = r[4]*SCALE - 0.5f;
    float rw = x2 - x1, rh = y2 - y1;
    float bw = rw * (1.0f/OW), bh = rh * (1.0f/OH);
    const uint4* fb = (const uint4*)(g_feath + (size_t)b*HW*CH);
    const int C8 = CH/8;                       // 32 uint4 per pixel
    int cgl = cb*16 + cg;                      // global 8-ch group index

    for (int b0 = 0; b0 < NBIN; b0 += 16) {
        int bin = b0 + bq;
        if (bin < NBIN) {
            int ph = bin / OW, pw = bin - ph*OW;
            float sw_ = x1, sh_ = y1;
            if (HAS_OFF) {
                sw_ += GAMMA * rw * off[roi*NOFF + bin];
                sh_ += GAMMA * rh * off[roi*NOFF + NBIN + bin];
            }
            float acc[8] = {};
            #pragma unroll
            for (int iy = 0; iy < 2; iy++) {
                float y = sh_ + ((float)ph + ((float)iy + 0.5f)*0.5f) * bh;
                #pragma unroll
                for (int ix = 0; ix < 2; ix++) {
                    float x = sw_ + ((float)pw + ((float)ix + 0.5f)*0.5f) * bw;
                    if (y > -1.0f && y < (float)FH && x > -1.0f && x < (float)FW) {
                        float yc = fminf(fmaxf(y, 0.0f), (float)(FH-1));
                        float xc = fminf(fmaxf(x, 0.0f), (float)(FW-1));
                        int y0 = min((int)floorf(yc), FH-2);
                        int x0 = min((int)floorf(xc), FW-2);
                        float ly = yc - (float)y0, lx = xc - (float)x0;
                        float hy = 1.0f - ly,     hx = 1.0f - lx;
                        float w00 = hy*hx, w01 = hy*lx, w10 = ly*hx, w11 = ly*lx;
                        const uint4* p = fb + ((size_t)y0*FW + x0)*C8 + cgl;
                        uint4 v00 = p[0];
                        uint4 v01 = p[C8];
                        uint4 v10 = p[FW*C8];
                        uint4 v11 = p[FW*C8 + C8];
                        const uint32_t* u00 = &v00.x;
                        const uint32_t* u01 = &v01.x;
                        const uint32_t* u10 = &v10.x;
                        const uint32_t* u11 = &v11.x;
                        #pragma unroll
                        for (int q = 0; q < 4; q++) {
                            float2 f00 = __half22float2(*(const __half2*)&u00[q]);
                            float2 f01 = __half22float2(*(const __half2*)&u01[q]);
                            float2 f10 = __half22float2(*(const __half2*)&u10[q]);
                            float2 f11 = __half22float2(*(const __half2*)&u11[q]);
                            acc[2*q]   += w00*f00.x + w01*f01.x + w10*f10.x + w11*f11.x;
                            acc[2*q+1] += w00*f00.y + w01*f01.y + w10*f10.y + w11*f11.y;
                        }
                    }
                }
            }
            int c = cg*8;                      // local channel within this half
            #pragma unroll
            for (int j = 0; j < 8; j++)
                sout[(c+j)*NBIN + bin] = acc[j] * 0.25f;
        }
    }
    __syncthreads();
    size_t base = (size_t)roi * FDIM + (size_t)cb * POOL_HALF;
    float* o = out + base;
    if (EMIT_HALF) {
        __half* oh = out_h + base;
        for (int i = tid; i < POOL_HALF; i += 256) {
            float v = sout[i];
            o[i] = v;
            oh[i] = __float2half_rn(v);
        }
    } else {
        for (int i = tid; i < POOL_HALF; i += 256) o[i] = sout[i];
    }

    if (RESCALE) {
        const float4* s4 = (const float4*)sout;
        int wo = cb * PH4;                    // float4 offset into each w row
        float s[4] = {0.f, 0.f, 0.f, 0.f};
        for (int k = tid; k < PH4; k += 256) {
            float4 v = s4[k];
            #pragma unroll
            for (int j = 0; j < 4; j++) {
                float4 a = rw4[(size_t)j*(FDIM/4) + wo + k];
                s[j] += v.x*a.x + v.y*a.y + v.z*a.z + v.w*a.w;
            }
        }
        #pragma unroll
        for (int o2 = 16; o2 > 0; o2 >>= 1)
            #pragma unroll
            for (int j = 0; j < 4; j++)
                s[j] += __shfl_down_sync(0xffffffffu, s[j], o2);
        __shared__ float red[4][8];
        int lane = tid & 31, warp = tid >> 5;
        if (lane == 0) { red[0][warp]=s[0]; red[1][warp]=s[1]; red[2][warp]=s[2]; red[3][warp]=s[3]; }
        __syncthreads();
        if (tid < 4) {
            float t = 0.f;
            #pragma unroll
            for (int ww = 0; ww < 8; ww++) t += red[tid][ww];
            g_dots[roi*8 + cb*4 + tid] = t;
        }
    }
}

// ------------ fp16 tensor-core NT GEMM, 128x128x32, 3-stage cp.async --------
__device__ __forceinline__ void mma_f16(float* c, uint32_t a0, uint32_t a1,
                                        uint32_t a2, uint32_t a3,
                                        uint32_t b0, uint32_t b1) {
    asm volatile(
        "mma.sync.aligned.m16n8k16.row.col.f32.f16.f16.f32 "
        "{%0,%1,%2,%3}, {%4,%5,%6,%7}, {%8,%9}, {%0,%1,%2,%3};"
        : "+f"(c[0]), "+f"(c[1]), "+f"(c[2]), "+f"(c[3])
        : "r"(a0), "r"(a1), "r"(a2), "r"(a3), "r"(b0), "r"(b1));
}
__device__ __forceinline__ uint32_t s2u(const void* p) {
    return (uint32_t)__cvta_generic_to_shared(p);
}
__device__ __forceinline__ void cp16(uint32_t dst, const void* src) {
    asm volatile("cp.async.cg.shared.global [%0], [%1], 16;" :: "r"(dst), "l"(src));
}

__global__ void __launch_bounds__(256, 2)
gemm_h(const __half* __restrict__ A, const __half* __restrict__ B,
       float* __restrict__ P, int N, int K) {
    const int BM = 128, BN = 128;
    __shared__ __align__(16) uint32_t As[3][BM*16];
    __shared__ __align__(16) uint32_t Bs[3][BN*16];

    int tid  = threadIdx.x;
    int lane = tid & 31, w = tid >> 5;
    int g = lane >> 2, tig = lane & 3;
    int wm = w >> 2, wn = w & 3;               // 2 x 4 warp grid
    int bm = blockIdx.y * BM, bn = blockIdx.x * BN;
    int S  = gridDim.z, kz = blockIdx.z;
    int Ks = K / S;
    int M  = gridDim.y * BM;
    int nst = Ks >> 5;

    int lm = tid >> 2, lq = tid & 3;
    const __half* Ap0 = A + (size_t)(bm + lm)*K + (size_t)kz*Ks + lq*8;
    const __half* Ap1 = Ap0 + (size_t)64*K;
    const __half* Bp0 = B + (size_t)(bn + lm)*K + (size_t)kz*Ks + lq*8;
    const __half* Bp1 = Bp0 + (size_t)64*K;
    int sc = lq ^ ((lm >> 1) & 3);
    int sw0 = lm*16 + sc*4;
    int sw1 = (lm + 64)*16 + sc*4;
    uint32_t sa0[3], sa1[3], sb0[3], sb1[3];
    #pragma unroll
    for (int b3 = 0; b3 < 3; b3++) {
        sa0[b3] = s2u(&As[b3][sw0]);  sa1[b3] = s2u(&As[b3][sw1]);
        sb0[b3] = s2u(&Bs[b3][sw0]);  sb1[b3] = s2u(&Bs[b3][sw1]);
    }

    float acc[4][4][4];
    #pragma unroll
    for (int i = 0; i < 4; i++)
        #pragma unroll
        for (int j = 0; j < 4; j++)
            #pragma unroll
            for (int q = 0; q < 4; q++) acc[i][j][q] = 0.0f;

    int mrow[4], mj[4];
    #pragma unroll
    for (int ii = 0; ii < 4; ii++) {
        mrow[ii] = wm*64 + ii*16 + g;
        mj[ii] = ((mrow[ii] >> 1) & 3) << 2;
    }
    int nrow[4], nj[4];
    #pragma unroll
    for (int jj = 0; jj < 4; jj++) {
        nrow[jj] = wn*32 + jj*8 + g;
        nj[jj] = ((nrow[jj] >> 1) & 3) << 2;
    }

    cp16(sa0[0], Ap0);  cp16(sa1[0], Ap1);
    cp16(sb0[0], Bp0);  cp16(sb1[0], Bp1);
    asm volatile("cp.async.commit_group;");
    if (nst > 1) {
        cp16(sa0[1], Ap0 + 32);  cp16(sa1[1], Ap1 + 32);
        cp16(sb0[1], Bp0 + 32);  cp16(sb1[1], Bp1 + 32);
        asm volatile("cp.async.commit_group;");
    }

    int buf = 0;
    for (int s = 0; s < nst; s++) {
        if (s < nst - 1) asm volatile("cp.async.wait_group 1;");
        else             asm volatile("cp.async.wait_group 0;");
        __syncthreads();

        const uint32_t* as = As[buf];
        const uint32_t* bs = Bs[buf];
        #pragma unroll
        for (int kb = 0; kb < 2; kb++) {
            int kw0 = kb*8 + tig, kw1 = kw0 + 4;
            uint32_t af[4][4], bf[4][2];
            #pragma unroll
            for (int jj = 0; jj < 4; jj++) {
                int rn = nrow[jj]*16, x = nj[jj];
                bf[jj][0] = bs[rn + (kw0 ^ x)];
                bf[jj][1] = bs[rn + (kw1 ^ x)];
            }
            #pragma unroll
            for (int ii = 0; ii < 4; ii++) {
                int r0 = mrow[ii]*16, r1 = (mrow[ii]+8)*16, x = mj[ii];
                af[ii][0] = as[r0 + (kw0 ^ x)];
                af[ii][1] = as[r1 + (kw0 ^ x)];
                af[ii][2] = as[r0 + (kw1 ^ x)];
                af[ii][3] = as[r1 + (kw1 ^ x)];
            }
            #pragma unroll
            for (int ii = 0; ii < 4; ii++)
                #pragma unroll
                for (int jj = 0; jj < 4; jj++)
                    mma_f16(acc[ii][jj], af[ii][0], af[ii][1], af[ii][2], af[ii][3],
                            bf[jj][0], bf[jj][1]);
        }

        if (s + 2 < nst) {
            int nb = (buf + 2) % 3;
            size_t o = (size_t)(s+2)*32;
            cp16(sa0[nb], Ap0 + o);  cp16(sa1[nb], Ap1 + o);
            cp16(sb0[nb], Bp0 + o);  cp16(sb1[nb], Bp1 + o);
            asm volatile("cp.async.commit_group;");
        }
        buf = (buf + 1) % 3;
    }

    float* Pp = P + (size_t)kz * M * N;
    #pragma unroll
    for (int ii = 0; ii < 4; ii++) {
        #pragma unroll
        for (int jj = 0; jj < 4; jj++) {
            int r0 = bm + wm*64 + ii*16 + g;
            int c0 = bn + wn*32 + jj*8 + tig*2;
            Pp[(size_t)r0*N + c0]       = acc[ii][jj][0];
            Pp[(size_t)r0*N + c0 + 1]   = acc[ii][jj][1];
            Pp[(size_t)(r0+8)*N + c0]   = acc[ii][jj][2];
            Pp[(size_t)(r0+8)*N + c0+1] = acc[ii][jj][3];
        }
    }
}

// -------- split-K combine (float4, half out): for N multiple of 4 -----------
__global__ void combine4h(const float* __restrict__ P, const float* __restrict__ bias,
                          __half* __restrict__ outh, int M, int N, int S) {
    int i = blockIdx.x * 256 + threadIdx.x;   // over M*N/4
    if (i >= M*N/4) return;
    int base = i*4;
    int m = base / N, n = base - m*N;
    float4 v = *(const float4*)(bias + n);
    for (int s = 0; s < S; s++) {
        float4 p = *(const float4*)(P + ((size_t)s*M + m)*N + n);
        v.x += p.x; v.y += p.y; v.z += p.z; v.w += p.w;
    }
    v.x = fmaxf(v.x, 0.f); v.y = fmaxf(v.y, 0.f);
    v.z = fmaxf(v.z, 0.f); v.w = fmaxf(v.w, 0.f);
    uint2 o;
    o.x = h2u(__floats2half2_rn(v.x, v.y));
    o.y = h2u(__floats2half2_rn(v.z, v.w));
    *(uint2*)(outh + base) = o;
}

// -------- final combine (float out, ragged N) + fused new-roi finalize ------
#define CF_BLOCKS ((NROIS*NOFF + 255)/256)    // 196
__global__ void combine_f_fin(const float* __restrict__ P, const float* __restrict__ bias,
                              float* __restrict__ outf, int M, int Ntot, int Nlog, int S,
                              const float* __restrict__ rois,
                              const float* __restrict__ rbias) {
    if (blockIdx.x >= CF_BLOCKS) {
        // finalize new rois: 2 blocks x 256 threads cover 512 ROIs
        int roi = (blockIdx.x - CF_BLOCKS) * 256 + threadIdx.x;
        if (roi >= NROIS) return;
        float d[4];
        #pragma unroll
        for (int j = 0; j < 4; j++) {
            float t = g_dots[roi*8 + j] + g_dots[roi*8 + 4 + j] + rbias[j];
            d[j] = 1.0f + 0.5f / (1.0f + expf(-t));
        }
        const float* r = rois + roi*5;
        float cx = (r[1] + r[3]) * 0.5f + d[0];
        float cy = (r[2] + r[4]) * 0.5f + d[1];
        float nw = (r[3] - r[1]) * d[2];
        float nh = (r[4] - r[2]) * d[3];
        float* nr = g_nrois + roi*5;
        nr[0] = r[0];
        nr[1] = cx - 0.5f*nw;  nr[2] = cy - 0.5f*nh;
        nr[3] = cx + 0.5f*nw;  nr[4] = cy + 0.5f*nh;
        return;
    }
    int i = blockIdx.x * 256 + threadIdx.x;
    if (i >= M*Nlog) return;
    int m = i / Nlog, n = i - m*Nlog;
    float v = bias[n];
    for (int s = 0; s < S; s++)
        v += P[((size_t)s*M + m)*Ntot + n];
    outf[i] = v;
}

// ---------------- launch -----------------------------------------------------
extern "C" void kernel_launch(void* const* d_in, const int* in_sizes, int n_in,
                              void* d_out, int out_size) {
    const float* input     = (const float*)d_in[0];
    const float* rois      = (const float*)d_in[1];
    const float* rescale_w = (const float*)d_in[2];
    const float* rescale_b = (const float*)d_in[3];
    const float* off_w1    = (const float*)d_in[4];
    const float* off_b1    = (const float*)d_in[5];
    const float* off_w2    = (const float*)d_in[6];
    const float* off_b2    = (const float*)d_in[7];
    const float* off_w3    = (const float*)d_in[8];
    const float* off_b3    = (const float*)d_in[9];

    float* xcls = (float*)d_out;
    float* xreg = xcls + (size_t)NROIS * FDIM;

    __half *a1p, *w1p, *w2p, *w3p, *h1p, *h2p;
    float *offp, *nroisp, *partp;
    cudaGetSymbolAddress((void**)&a1p,    g_a1h);
    cudaGetSymbolAddress((void**)&w1p,    g_w1h);
    cudaGetSymbolAddress((void**)&w2p,    g_w2h);
    cudaGetSymbolAddress((void**)&w3p,    g_w3h);
    cudaGetSymbolAddress((void**)&h1p,    g_h1h);
    cudaGetSymbolAddress((void**)&h2p,    g_h2h);
    cudaGetSymbolAddress((void**)&offp,   g_off);
    cudaGetSymbolAddress((void**)&nroisp, g_nrois);
    cudaGetSymbolAddress((void**)&partp,  g_part);

    // 1) transpose to NHWC fp16
    nchw2nhwc_h<<<dim3(HW/32, CH/64, BATCH), dim3(32, 8)>>>(input);
    // 2) x_cls pool (2 CTAs/ROI) + rescale dots + fused weight conversion
    roi_pool<false,true,true,true><<<dim3(NROIS, 3), 256>>>(
        rois, nullptr, xcls, a1p, (const float4*)rescale_w,
        off_w1, off_w2, off_w3);
    // 3) offset MLP: fp16 tensor cores (3-stage cp.async), split-K + combine
    gemm_h<<<dim3(DFC/128, NROIS/128, 8), 256>>>(a1p, w1p, partp, DFC, FDIM);
    combine4h<<<(NROIS*DFC/4 + 255)/256, 256>>>(partp, off_b1, h1p, NROIS, DFC, 8);
    gemm_h<<<dim3(DFC/128, NROIS/128, 8), 256>>>(h1p, w2p, partp, DFC, DFC);
    combine4h<<<(NROIS*DFC/4 + 255)/256, 256>>>(partp, off_b2, h2p, NROIS, DFC, 8);
    gemm_h<<<dim3(1, NROIS/128, 8), 256>>>(h2p, w3p, partp, NOFFP, DFC);
    // 4) final combine + fused new-roi finalize
    combine_f_fin<<<CF_BLOCKS + 2, 256>>>(partp, off_b3, offp, NROIS, NOFFP, NOFF, 8,
                                          rois, rescale_b);
    // 5) x_reg pool (2 CTAs/ROI) -> second half of d_out
    roi_pool<true,false,false,false><<<dim3(NROIS, 2), 256>>>(
        nroisp, offp, xreg, nullptr, nullptr, nullptr, nullptr, nullptr);
}